// round 9
// baseline (speedup 1.0000x reference)
#include <cuda_runtime.h>
#include <math.h>

// ---------------- problem constants ----------------
#define Dm   1024
#define Hh   16
#define DH   64
#define DFF  4096
#define DC   768
#define Tt   2048
#define Bb   2
#define Cc   77
#define MX   4096          // Bb*Tt rows of x

// ---------------- scratch (static device arrays; no allocs) ----------------
__device__ float g_ln   [(size_t)MX * Dm];
__device__ float g_qkv  [(size_t)MX * 3 * Dm];
__device__ float g_attn [(size_t)MX * Dm];
__device__ float g_x1   [(size_t)MX * Dm];
__device__ float g_x2   [(size_t)MX * Dm];
__device__ float g_qca  [(size_t)MX * Dm];
__device__ float g_kvca [(size_t)Bb * Cc * 2 * Dm];
__device__ float g_ff   [(size_t)MX * DFF];
__device__ float g_w    [(size_t)16400000];          // tf32-rounded weights + cond

// weight-scratch offsets (floats) - contiguous, in rounding order
#define SZ_QKV  (Dm*3*Dm)
#define SZ_PSA  (Dm*Dm)
#define SZ_QCA  (Dm*Dm)
#define SZ_KVCA (DC*2*Dm)
#define SZ_PCA  (Dm*Dm)
#define SZ_FF1  (Dm*DFF)
#define SZ_FF2  (DFF*Dm)
#define SZ_COND (Bb*Cc*DC)
#define OW_QKV   0
#define OW_PSA   (OW_QKV + SZ_QKV)
#define OW_QCA   (OW_PSA + SZ_PSA)
#define OW_KVCA  (OW_QCA + SZ_QCA)
#define OW_PCA   (OW_KVCA + SZ_KVCA)
#define OW_FF1   (OW_PCA + SZ_PCA)
#define OW_FF2   (OW_FF1 + SZ_FF1)
#define OW_COND  (OW_FF2 + SZ_FF2)
#define OW_TOT   (OW_COND + SZ_COND)

// ---------------- tf32 helpers ----------------
__device__ __forceinline__ unsigned totf(float f) {
    unsigned u;
    asm("cvt.rna.tf32.f32 %0, %1;" : "=r"(u) : "f"(f));
    return u;
}
__device__ __forceinline__ float totf_f(float f) { return __uint_as_float(totf(f)); }

__device__ __forceinline__ void mma_tf32(float c[4],
    unsigned a0, unsigned a1, unsigned a2, unsigned a3,
    unsigned b0, unsigned b1)
{
    asm volatile(
        "mma.sync.aligned.m16n8k8.row.col.f32.tf32.tf32.f32 "
        "{%0,%1,%2,%3}, {%4,%5,%6,%7}, {%8,%9}, {%0,%1,%2,%3};\n"
        : "+f"(c[0]), "+f"(c[1]), "+f"(c[2]), "+f"(c[3])
        : "r"(a0), "r"(a1), "r"(a2), "r"(a3), "r"(b0), "r"(b1));
}

__device__ __forceinline__ void cpa16(unsigned dst, const float* src, bool pred) {
    int sz = pred ? 16 : 0;
    asm volatile("cp.async.cg.shared.global [%0], [%1], 16, %2;\n"
                 :: "r"(dst), "l"(src), "r"(sz));
}
__device__ __forceinline__ void cpa16u(unsigned dst, const float* src) {
    asm volatile("cp.async.cg.shared.global [%0], [%1], 16;\n"
                 :: "r"(dst), "l"(src));
}
__device__ __forceinline__ void cpa_commit() {
    asm volatile("cp.async.commit_group;\n");
}
template<int N>
__device__ __forceinline__ void cpa_wait() {
    asm volatile("cp.async.wait_group %0;\n" :: "n"(N));
}

// ---------------- merged weight rounding prep (one launch) ----------------
__global__ __launch_bounds__(256) void round_all_kernel(
    const float* __restrict__ s0, const float* __restrict__ s1,
    const float* __restrict__ s2, const float* __restrict__ s3,
    const float* __restrict__ s4, const float* __restrict__ s5,
    const float* __restrict__ s6, const float* __restrict__ s7,
    float* __restrict__ dst)
{
    int n4 = OW_TOT / 4;
    for (int i = blockIdx.x * 256 + threadIdx.x; i < n4; i += gridDim.x * 256) {
        int idx = i * 4;
        const float* src;
        if      (idx < OW_PSA)  src = s0 + (idx - OW_QKV);
        else if (idx < OW_QCA)  src = s1 + (idx - OW_PSA);
        else if (idx < OW_KVCA) src = s2 + (idx - OW_QCA);
        else if (idx < OW_PCA)  src = s3 + (idx - OW_KVCA);
        else if (idx < OW_FF1)  src = s4 + (idx - OW_PCA);
        else if (idx < OW_FF2)  src = s5 + (idx - OW_FF1);
        else if (idx < OW_COND) src = s6 + (idx - OW_FF2);
        else                    src = s7 + (idx - OW_COND);
        float4 v = *(const float4*)src;
        v.x = totf_f(v.x); v.y = totf_f(v.y);
        v.z = totf_f(v.z); v.w = totf_f(v.w);
        *(float4*)(dst + idx) = v;
    }
}

// ---------------- reductions ----------------
__device__ __forceinline__ float block_sum(float v, float* sh) {
    #pragma unroll
    for (int o = 16; o > 0; o >>= 1) v += __shfl_xor_sync(0xffffffffu, v, o);
    int w = threadIdx.x >> 5;
    if ((threadIdx.x & 31) == 0) sh[w] = v;
    __syncthreads();
    if (threadIdx.x < 32) {
        float t = (threadIdx.x < 8) ? sh[threadIdx.x] : 0.f;
        #pragma unroll
        for (int o = 4; o > 0; o >>= 1) t += __shfl_xor_sync(0xffffffffu, t, o);
        if (threadIdx.x == 0) sh[0] = t;
    }
    __syncthreads();
    float r = sh[0];
    __syncthreads();
    return r;
}

// ---------------- LayerNorm (tf32-rounded output) ----------------
__global__ __launch_bounds__(256) void ln_kernel(
    const float* __restrict__ x, const float* __restrict__ g,
    const float* __restrict__ b, float* __restrict__ out)
{
    __shared__ float sh[8];
    long row = blockIdx.x;
    const float4* xr = (const float4*)(x + row * Dm);
    int tid = threadIdx.x;
    float4 v = xr[tid];
    float s = v.x + v.y + v.z + v.w;
    s = block_sum(s, sh);
    float mean = s * (1.0f / Dm);
    float dx = v.x - mean, dy = v.y - mean, dz = v.z - mean, dw = v.w - mean;
    float s2 = dx*dx + dy*dy + dz*dz + dw*dw;
    s2 = block_sum(s2, sh);
    float rstd = rsqrtf(s2 * (1.0f / Dm) + 1e-5f);
    float4 gg = ((const float4*)g)[tid];
    float4 bbv = ((const float4*)b)[tid];
    float4 o;
    o.x = totf_f(dx * rstd * gg.x + bbv.x);
    o.y = totf_f(dy * rstd * gg.y + bbv.y);
    o.z = totf_f(dz * rstd * gg.z + bbv.z);
    o.w = totf_f(dw * rstd * gg.w + bbv.w);
    ((float4*)(out + row * Dm))[tid] = o;
}

// ================= fused flash attention (tf32, pre-rounded inputs) =================
// R5 proven version: sync K/V loads, 2 CTAs/SM interleave.
#define FBQ 128
#define FBK 64
#define FSQ 68
#define FSV 72
#define FSMEM ((FBQ*FSQ + FBK*FSQ + FBK*FSV) * 4)

__global__ __launch_bounds__(256, 2) void flash_kernel(
    const float* __restrict__ Qp, const float* __restrict__ Kp,
    const float* __restrict__ Vp, float* __restrict__ Op,
    int Tq, int Tk, int ldq, int ldk, int ldo,
    long sQb, long sQh, long sKb, long sKh, long sOb, long sOh,
    int Hn, float scale, int causal)
{
    extern __shared__ unsigned fsm[];
    unsigned* Qs = fsm;
    unsigned* Ks = fsm + FBQ * FSQ;
    unsigned* Vs = Ks + FBK * FSQ;

    int z = blockIdx.z, zb = z / Hn, zh = z - zb * Hn;
    Qp += zb * sQb + zh * sQh;
    Kp += zb * sKb + zh * sKh;
    Vp += zb * sKb + zh * sKh;
    Op += zb * sOb + zh * sOh;

    int tid = threadIdx.x, lane = tid & 31, warp = tid >> 5;
    int gid = lane >> 2, tg = lane & 3;
    int row0 = blockIdx.y * FBQ;

    #pragma unroll
    for (int it = 0; it < 8; it++) {
        int idx = it * 256 + tid;
        int r = idx >> 4, c4 = (idx & 15) * 4;
        int gr = row0 + r;
        float4 v = make_float4(0.f, 0.f, 0.f, 0.f);
        if (gr < Tq) v = *(const float4*)(Qp + (long)gr * ldq + c4);
        unsigned* q = &Qs[r * FSQ + c4];
        q[0] = __float_as_uint(v.x * scale); q[1] = __float_as_uint(v.y * scale);
        q[2] = __float_as_uint(v.z * scale); q[3] = __float_as_uint(v.w * scale);
    }

    int r_0 = row0 + warp * 16 + gid;
    int r_1 = r_0 + 8;

    float m0 = -1e30f, m1 = -1e30f, l0 = 0.f, l1 = 0.f;
    float o[8][4];
    #pragma unroll
    for (int i = 0; i < 8; i++)
        #pragma unroll
        for (int j = 0; j < 4; j++) o[i][j] = 0.f;

    int ntile = causal ? (row0 + FBQ) / FBK : (Tk + FBK - 1) / FBK;

    for (int t = 0; t < ntile; t++) {
        int kvb = t * FBK;
        __syncthreads();
        #pragma unroll
        for (int it = 0; it < 4; it++) {
            int idx = it * 256 + tid;
            int r = idx >> 4, c4 = (idx & 15) * 4;
            int gr = kvb + r;
            float4 kv = make_float4(0.f,0.f,0.f,0.f), vv = make_float4(0.f,0.f,0.f,0.f);
            if (gr < Tk) {
                kv = *(const float4*)(Kp + (long)gr * ldk + c4);
                vv = *(const float4*)(Vp + (long)gr * ldk + c4);
            }
            unsigned* k = &Ks[r * FSQ + c4];
            k[0] = __float_as_uint(kv.x); k[1] = __float_as_uint(kv.y);
            k[2] = __float_as_uint(kv.z); k[3] = __float_as_uint(kv.w);
            unsigned* v = &Vs[r * FSV + c4];
            v[0] = __float_as_uint(vv.x); v[1] = __float_as_uint(vv.y);
            v[2] = __float_as_uint(vv.z); v[3] = __float_as_uint(vv.w);
        }
        __syncthreads();

        float sacc[8][4];
        #pragma unroll
        for (int i = 0; i < 8; i++)
            #pragma unroll
            for (int j = 0; j < 4; j++) sacc[i][j] = 0.f;

        #pragma unroll
        for (int ks = 0; ks < 8; ks++) {
            int qb = (warp * 16 + gid) * FSQ + ks * 8 + tg;
            unsigned qa0 = Qs[qb];
            unsigned qa1 = Qs[qb + 8 * FSQ];
            unsigned qa2 = Qs[qb + 4];
            unsigned qa3 = Qs[qb + 8 * FSQ + 4];
            #pragma unroll
            for (int ni = 0; ni < 8; ni++) {
                int kb = (ni * 8 + gid) * FSQ + ks * 8 + tg;
                mma_tf32(sacc[ni], qa0, qa1, qa2, qa3, Ks[kb], Ks[kb + 4]);
            }
        }

        bool domask = (causal && (kvb + FBK - 1 > row0)) || (kvb + FBK > Tk);
        if (domask) {
            #pragma unroll
            for (int ni = 0; ni < 8; ni++) {
                #pragma unroll
                for (int s = 0; s < 4; s++) {
                    int col = kvb + ni * 8 + tg * 2 + (s & 1);
                    int r = (s < 2) ? r_0 : r_1;
                    bool ok = (col < Tk) && (!causal || col <= r);
                    if (!ok) sacc[ni][s] = -1e30f;
                }
            }
        }

        float tm0 = -1e30f, tm1 = -1e30f;
        #pragma unroll
        for (int ni = 0; ni < 8; ni++) {
            tm0 = fmaxf(tm0, fmaxf(sacc[ni][0], sacc[ni][1]));
            tm1 = fmaxf(tm1, fmaxf(sacc[ni][2], sacc[ni][3]));
        }
        tm0 = fmaxf(tm0, __shfl_xor_sync(0xffffffffu, tm0, 1));
        tm0 = fmaxf(tm0, __shfl_xor_sync(0xffffffffu, tm0, 2));
        tm1 = fmaxf(tm1, __shfl_xor_sync(0xffffffffu, tm1, 1));
        tm1 = fmaxf(tm1, __shfl_xor_sync(0xffffffffu, tm1, 2));

        float nm0 = fmaxf(m0, tm0), nm1 = fmaxf(m1, tm1);
        float sc0 = __expf(m0 - nm0), sc1 = __expf(m1 - nm1);
        m0 = nm0; m1 = nm1;

        float rs0 = 0.f, rs1 = 0.f;
        #pragma unroll
        for (int ni = 0; ni < 8; ni++) {
            sacc[ni][0] = __expf(sacc[ni][0] - nm0); rs0 += sacc[ni][0];
            sacc[ni][1] = __expf(sacc[ni][1] - nm0); rs0 += sacc[ni][1];
            sacc[ni][2] = __expf(sacc[ni][2] - nm1); rs1 += sacc[ni][2];
            sacc[ni][3] = __expf(sacc[ni][3] - nm1); rs1 += sacc[ni][3];
        }
        rs0 += __shfl_xor_sync(0xffffffffu, rs0, 1);
        rs0 += __shfl_xor_sync(0xffffffffu, rs0, 2);
        rs1 += __shfl_xor_sync(0xffffffffu, rs1, 1);
        rs1 += __shfl_xor_sync(0xffffffffu, rs1, 2);
        l0 = l0 * sc0 + rs0;
        l1 = l1 * sc1 + rs1;

        #pragma unroll
        for (int ni = 0; ni < 8; ni++) {
            o[ni][0] *= sc0; o[ni][1] *= sc0;
            o[ni][2] *= sc1; o[ni][3] *= sc1;
        }

        int bl = lane & ~3;
        int s0 = bl + (tg >> 1);
        int s1 = bl + 2 + (tg >> 1);
        bool hi = (tg & 1);
        #pragma unroll
        for (int ks = 0; ks < 8; ks++) {
            float p0 = sacc[ks][0], p1 = sacc[ks][1];
            float p2 = sacc[ks][2], p3 = sacc[ks][3];
            float v00 = __shfl_sync(0xffffffffu, p0, s0);
            float v01 = __shfl_sync(0xffffffffu, p1, s0);
            float v10 = __shfl_sync(0xffffffffu, p2, s0);
            float v11 = __shfl_sync(0xffffffffu, p3, s0);
            float w00 = __shfl_sync(0xffffffffu, p0, s1);
            float w01 = __shfl_sync(0xffffffffu, p1, s1);
            float w10 = __shfl_sync(0xffffffffu, p2, s1);
            float w11 = __shfl_sync(0xffffffffu, p3, s1);
            unsigned a0 = totf(hi ? v01 : v00);
            unsigned a1 = totf(hi ? v11 : v10);
            unsigned a2 = totf(hi ? w01 : w00);
            unsigned a3 = totf(hi ? w11 : w10);
            #pragma unroll
            for (int nj = 0; nj < 8; nj++) {
                int vb = (ks * 8 + tg) * FSV + nj * 8 + gid;
                mma_tf32(o[nj], a0, a1, a2, a3, Vs[vb], Vs[vb + 4 * FSV]);
            }
        }
    }

    float inv0 = 1.0f / l0, inv1 = 1.0f / l1;
    #pragma unroll
    for (int nj = 0; nj < 8; nj++) {
        int c = nj * 8 + tg * 2;
        if (r_0 < Tq) {
            float2 w = make_float2(totf_f(o[nj][0] * inv0), totf_f(o[nj][1] * inv0));
            *(float2*)(Op + (long)r_0 * ldo + c) = w;
        }
        if (r_1 < Tq) {
            float2 w = make_float2(totf_f(o[nj][2] * inv1), totf_f(o[nj][3] * inv1));
            *(float2*)(Op + (long)r_1 * ldo + c) = w;
        }
    }
}

// ================= cp.async 4-stage tf32 GEMM, 128x256 block (wide-N) ================
#define BM 128
#define BN 256
#define BK 16
#define NSTG 4
#define SAS 20
#define SBS 264
#define AW (BM * SAS)
#define BW (BK * SBS)
#define STG (AW + BW)
#define GSMEM (STG * NSTG * 4)

template<int EPI>
__global__ __launch_bounds__(256, 1) void tgemm(
    const float* __restrict__ A, const float* __restrict__ Bm,
    const float* __restrict__ bias, const float* __restrict__ Res,
    float* __restrict__ C,
    int M, int N, int K, int lda, int ldb)
{
    extern __shared__ unsigned dsm[];
    unsigned sbase = (unsigned)__cvta_generic_to_shared(dsm);

    int row0 = blockIdx.y * BM, col0 = blockIdx.x * BN;
    int tid  = threadIdx.x;
    int lane = tid & 31, warp = tid >> 5;
    int wm = (warp & 1) * 64;
    int wn = (warp >> 1) * 64;
    int gid = lane >> 2, tg = lane & 3;

    int ar = tid >> 1;
    int ak = (tid & 1) * 8;
    int bk = tid >> 6;
    int bn = (tid & 63) * 4;

    auto load_stage = [&](int s, int k0) {
        unsigned abase = sbase + (s * STG) * 4;
        unsigned bbase = sbase + (s * STG + AW) * 4;
        const float* asrc = A + (long)(row0 + ar) * lda + k0 + ak;
        bool av = (row0 + ar) < M;
        unsigned adst = abase + (ar * SAS + ak) * 4;
        cpa16(adst, asrc, av);
        cpa16(adst + 16, asrc + 4, av);
        const float* bsrc = Bm + (long)(k0 + bk) * ldb + col0 + bn;
        unsigned bdst = bbase + (bk * SBS + bn) * 4;
        #pragma unroll
        for (int i = 0; i < 4; i++)
            cpa16u(bdst + i * (SBS * 4 * 4), bsrc + (long)(4 * i) * ldb);
    };

    float acc[4][8][4];
    #pragma unroll
    for (int i = 0; i < 4; i++)
        #pragma unroll
        for (int j = 0; j < 8; j++)
            #pragma unroll
            for (int r = 0; r < 4; r++) acc[i][j][r] = 0.f;

    int ntiles = K / BK;

    #pragma unroll
    for (int s = 0; s < NSTG - 1; s++) {
        if (s < ntiles) load_stage(s, s * BK);
        cpa_commit();
    }

    for (int t = 0; t < ntiles; t++) {
        cpa_wait<NSTG - 2>();
        __syncthreads();

        int tn = t + NSTG - 1;
        if (tn < ntiles) load_stage(tn % NSTG, tn * BK);
        cpa_commit();

        int buf = t % NSTG;
        const unsigned* As = dsm + buf * STG;
        const unsigned* Bs = dsm + buf * STG + AW;

        #pragma unroll
        for (int ks = 0; ks < 2; ks++) {
            int k0s = ks * 8;
            unsigned a[4][4], b[8][2];
            #pragma unroll
            for (int mi = 0; mi < 4; mi++) {
                int r = wm + mi * 16 + gid;
                a[mi][0] = As[r * SAS + k0s + tg];
                a[mi][1] = As[(r + 8) * SAS + k0s + tg];
                a[mi][2] = As[r * SAS + k0s + tg + 4];
                a[mi][3] = As[(r + 8) * SAS + k0s + tg + 4];
            }
            #pragma unroll
            for (int ni = 0; ni < 8; ni++) {
                int n = wn + ni * 8 + gid;
                b[ni][0] = Bs[(k0s + tg) * SBS + n];
                b[ni][1] = Bs[(k0s + tg + 4) * SBS + n];
            }
            #pragma unroll
            for (int mi = 0; mi < 4; mi++)
                #pragma unroll
                for (int ni = 0; ni < 8; ni++)
                    mma_tf32(acc[mi][ni], a[mi][0], a[mi][1], a[mi][2], a[mi][3],
                             b[ni][0], b[ni][1]);
        }
    }

    #pragma unroll
    for (int mi = 0; mi < 4; mi++) {
        #pragma unroll
        for (int rr = 0; rr < 2; rr++) {
            int r = row0 + wm + mi * 16 + gid + rr * 8;
            if (r >= M) continue;
            #pragma unroll
            for (int ni = 0; ni < 8; ni++) {
                int c = col0 + wn + ni * 8 + tg * 2;
                float v0 = acc[mi][ni][rr * 2 + 0];
                float v1 = acc[mi][ni][rr * 2 + 1];
                if (EPI & 1) { v0 += bias[c]; v1 += bias[c + 1]; }
                if (EPI & 4) {
                    v0 = 0.5f * v0 * (1.0f + erff(v0 * 0.70710678118654752f));
                    v1 = 0.5f * v1 * (1.0f + erff(v1 * 0.70710678118654752f));
                }
                if (EPI & 2) {
                    float2 rv = *(const float2*)(Res + (long)r * N + c);
                    v0 += rv.x; v1 += rv.y;
                }
                if (EPI & 8) { v0 = totf_f(v0); v1 = totf_f(v1); }
                *(float2*)(C + (long)r * N + c) = make_float2(v0, v1);
            }
        }
    }
}

// ============== 4-warp 128x128 tf32 GEMM (3 CTAs/SM, latency-hiding) ================
#define QBM 128
#define QBN 128
#define QSBS 136
#define QAW (QBM * SAS)            // 2560
#define QBW (BK * QSBS)            // 2176
#define QSTG (QAW + QBW)           // 4736 words
#define QSMEM (QSTG * NSTG * 4)    // 75776 bytes

template<int EPI>
__global__ __launch_bounds__(128, 3) void tgemm4w(
    const float* __restrict__ A, const float* __restrict__ Bm,
    const float* __restrict__ bias, const float* __restrict__ Res,
    float* __restrict__ C,
    int M, int N, int K, int lda, int ldb)
{
    extern __shared__ unsigned dsm[];
    unsigned sbase = (unsigned)__cvta_generic_to_shared(dsm);

    int row0 = blockIdx.y * QBM, col0 = blockIdx.x * QBN;
    int tid  = threadIdx.x;
    int lane = tid & 31, warp = tid >> 5;      // 4 warps
    int wm = (warp & 1) * 64;
    int wn = (warp >> 1) * 64;
    int gid = lane >> 2, tg = lane & 3;

    // loaders: 128 threads
    int bk = tid >> 5;                 // 0..3
    int bn = (tid & 31) * 4;

    auto load_stage = [&](int s, int k0) {
        unsigned abase = sbase + (s * QSTG) * 4;
        unsigned bbase = sbase + (s * QSTG + QAW) * 4;
        // A: 128 rows x 16; thread = row, 4 chunks
        const float* asrc = A + (long)(row0 + tid) * lda + k0;
        bool av = (row0 + tid) < M;
        unsigned adst = abase + (tid * SAS) * 4;
        #pragma unroll
        for (int i = 0; i < 4; i++)
            cpa16(adst + i * 16, asrc + i * 4, av);
        // B: 16 rows x 128; thread: rows bk+4i, cols bn..bn+3
        const float* bsrc = Bm + (long)(k0 + bk) * ldb + col0 + bn;
        unsigned bdst = bbase + (bk * QSBS + bn) * 4;
        #pragma unroll
        for (int i = 0; i < 4; i++)
            cpa16u(bdst + i * (QSBS * 4 * 4), bsrc + (long)(4 * i) * ldb);
    };

    float acc[4][8][4];
    #pragma unroll
    for (int i = 0; i < 4; i++)
        #pragma unroll
        for (int j = 0; j < 8; j++)
            #pragma unroll
            for (int r = 0; r < 4; r++) acc[i][j][r] = 0.f;

    int ntiles = K / BK;

    #pragma unroll
    for (int s = 0; s < NSTG - 1; s++) {
        if (s < ntiles) load_stage(s, s * BK);
        cpa_commit();
    }

    for (int t = 0; t < ntiles; t++) {
        cpa_wait<NSTG - 2>();
        __syncthreads();

        int tn = t + NSTG - 1;
        if (tn < ntiles) load_stage(tn % NSTG, tn * BK);
        cpa_commit();

        int buf = t % NSTG;
        const unsigned* As = dsm + buf * QSTG;
        const unsigned* Bs = dsm + buf * QSTG + QAW;

        #pragma unroll
        for (int ks = 0; ks < 2; ks++) {
            int k0s = ks * 8;
            unsigned a[4][4], b[8][2];
            #pragma unroll
            for (int mi = 0; mi < 4; mi++) {
                int r = wm + mi * 16 + gid;
                a[mi][0] = As[r * SAS + k0s + tg];
                a[mi][1] = As[(r + 8) * SAS + k0s + tg];
                a[mi][2] = As[r * SAS + k0s + tg + 4];
                a[mi][3] = As[(r + 8) * SAS + k0s + tg + 4];
            }
            #pragma unroll
            for (int ni = 0; ni < 8; ni++) {
                int n = wn + ni * 8 + gid;
                b[ni][0] = Bs[(k0s + tg) * QSBS + n];
                b[ni][1] = Bs[(k0s + tg + 4) * QSBS + n];
            }
            #pragma unroll
            for (int mi = 0; mi < 4; mi++)
                #pragma unroll
                for (int ni = 0; ni < 8; ni++)
                    mma_tf32(acc[mi][ni], a[mi][0], a[mi][1], a[mi][2], a[mi][3],
                             b[ni][0], b[ni][1]);
        }
    }

    #pragma unroll
    for (int mi = 0; mi < 4; mi++) {
        #pragma unroll
        for (int rr = 0; rr < 2; rr++) {
            int r = row0 + wm + mi * 16 + gid + rr * 8;
            if (r >= M) continue;
            #pragma unroll
            for (int ni = 0; ni < 8; ni++) {
                int c = col0 + wn + ni * 8 + tg * 2;
                float v0 = acc[mi][ni][rr * 2 + 0];
                float v1 = acc[mi][ni][rr * 2 + 1];
                if (EPI & 1) { v0 += bias[c]; v1 += bias[c + 1]; }
                if (EPI & 4) {
                    v0 = 0.5f * v0 * (1.0f + erff(v0 * 0.70710678118654752f));
                    v1 = 0.5f * v1 * (1.0f + erff(v1 * 0.70710678118654752f));
                }
                if (EPI & 2) {
                    float2 rv = *(const float2*)(Res + (long)r * N + c);
                    v0 += rv.x; v1 += rv.y;
                }
                if (EPI & 8) { v0 = totf_f(v0); v1 = totf_f(v1); }
                *(float2*)(C + (long)r * N + c) = make_float2(v0, v1);
            }
        }
    }
}

// ---------------- host side ----------------
static inline dim3 ggrid(int M, int N) {
    return dim3((unsigned)((N + BN - 1) / BN), (unsigned)((M + BM - 1) / BM), 1);
}
static inline dim3 qgrid(int M, int N) {
    return dim3((unsigned)((N + QBN - 1) / QBN), (unsigned)((M + QBM - 1) / QBM), 1);
}

extern "C" void kernel_launch(void* const* d_in, const int* in_sizes, int n_in,
                              void* d_out, int out_size)
{
    const float* x        = (const float*)d_in[0];
    const float* cond     = (const float*)d_in[1];
    const float* Wqkv     = (const float*)d_in[2];
    const float* Wproj_sa = (const float*)d_in[3];
    const float* bproj_sa = (const float*)d_in[4];
    const float* g1       = (const float*)d_in[5];
    const float* b1       = (const float*)d_in[6];
    const float* Wq_ca    = (const float*)d_in[7];
    const float* Wkv_ca   = (const float*)d_in[8];
    const float* Wproj_ca = (const float*)d_in[9];
    const float* bproj_ca = (const float*)d_in[10];
    const float* g2       = (const float*)d_in[11];
    const float* b2       = (const float*)d_in[12];
    const float* Wff1     = (const float*)d_in[13];
    const float* bff1     = (const float*)d_in[14];
    const float* Wff2     = (const float*)d_in[15];
    const float* bff2     = (const float*)d_in[16];
    const float* g3       = (const float*)d_in[17];
    const float* b3       = (const float*)d_in[18];
    float* out            = (float*)d_out;

    float *p_ln, *p_qkv, *p_attn, *p_x1, *p_x2, *p_qca, *p_kvca, *p_ff, *p_w;
    cudaGetSymbolAddress((void**)&p_ln,   g_ln);
    cudaGetSymbolAddress((void**)&p_qkv,  g_qkv);
    cudaGetSymbolAddress((void**)&p_attn, g_attn);
    cudaGetSymbolAddress((void**)&p_x1,   g_x1);
    cudaGetSymbolAddress((void**)&p_x2,   g_x2);
    cudaGetSymbolAddress((void**)&p_qca,  g_qca);
    cudaGetSymbolAddress((void**)&p_kvca, g_kvca);
    cudaGetSymbolAddress((void**)&p_ff,   g_ff);
    cudaGetSymbolAddress((void**)&p_w,    g_w);

    static int smem_set = 0;
    if (!smem_set) {
        cudaFuncSetAttribute(flash_kernel, cudaFuncAttributeMaxDynamicSharedMemorySize, FSMEM);
        cudaFuncSetAttribute(tgemm<8>,    cudaFuncAttributeMaxDynamicSharedMemorySize, GSMEM);
        cudaFuncSetAttribute(tgemm<13>,   cudaFuncAttributeMaxDynamicSharedMemorySize, GSMEM);
        cudaFuncSetAttribute(tgemm4w<3>,  cudaFuncAttributeMaxDynamicSharedMemorySize, QSMEM);
        cudaFuncSetAttribute(tgemm4w<8>,  cudaFuncAttributeMaxDynamicSharedMemorySize, QSMEM);
        smem_set = 1;
    }

    const long T3D = (long)Tt * 3 * Dm;
    const long TD  = (long)Tt * Dm;
    const long KVb = (long)Cc * 2 * Dm;
    const float iscale = 0.125f;

    // 0) tf32-round all weights + cond into scratch (single launch)
    round_all_kernel<<<2048, 256>>>(Wqkv, Wproj_sa, Wq_ca, Wkv_ca,
                                    Wproj_ca, Wff1, Wff2, cond, p_w);

    // 1) ln1 = LN(x)
    ln_kernel<<<MX, 256>>>(x, g1, b1, p_ln);

    // 2) qkv = ln1 @ Wqkv   (wide-N kernel)
    tgemm<8><<<ggrid(MX, 3*Dm), 256, GSMEM>>>(
        p_ln, p_w + OW_QKV, nullptr, nullptr, p_qkv, MX, 3*Dm, Dm, Dm, 3*Dm);

    // 3) fused causal self-attention -> g_attn
    flash_kernel<<<dim3(1, Tt/FBQ, Bb*Hh), 256, FSMEM>>>(
        p_qkv, p_qkv + Dm, p_qkv + 2*Dm, p_attn,
        Tt, Tt, 3*Dm, 3*Dm, Dm,
        T3D, DH, T3D, DH, TD, DH, Hh, iscale, 1);

    // 4) x1 = x + attn @ Wproj_sa + b     (4-warp kernel)
    tgemm4w<3><<<qgrid(MX, Dm), 128, QSMEM>>>(
        p_attn, p_w + OW_PSA, bproj_sa, x, p_x1, MX, Dm, Dm, Dm, Dm);

    // 5) ln2 = LN(x1)
    ln_kernel<<<MX, 256>>>(p_x1, g2, b2, p_ln);

    // 6) q_ca = ln2 @ Wq_ca  (4-warp)
    tgemm4w<8><<<qgrid(MX, Dm), 128, QSMEM>>>(
        p_ln, p_w + OW_QCA, nullptr, nullptr, p_qca, MX, Dm, Dm, Dm, Dm);

    // 7) kv_ca = cond_r @ Wkv_ca (4-warp; N=2048)
    tgemm4w<8><<<qgrid(Bb*Cc, 2*Dm), 128, QSMEM>>>(
        p_w + OW_COND, p_w + OW_KVCA, nullptr, nullptr, p_kvca,
        Bb*Cc, 2*Dm, DC, DC, 2*Dm);

    // 8) fused cross-attention -> g_attn
    flash_kernel<<<dim3(1, Tt/FBQ, Bb*Hh), 256, FSMEM>>>(
        p_qca, p_kvca, p_kvca + Dm, p_attn,
        Tt, Cc, Dm, 2*Dm, Dm,
        TD, DH, KVb, DH, TD, DH, Hh, iscale, 0);

    // 9) x2 = x1 + ca_out @ Wproj_ca + b  (4-warp)
    tgemm4w<3><<<qgrid(MX, Dm), 128, QSMEM>>>(
        p_attn, p_w + OW_PCA, bproj_ca, p_x1, p_x2, MX, Dm, Dm, Dm, Dm);

    // 10) ln3 = LN(x2)
    ln_kernel<<<MX, 256>>>(p_x2, g3, b3, p_ln);

    // 11) ffh = gelu(ln3 @ Wff1 + bff1), rounded (wide-N kernel)
    tgemm<13><<<ggrid(MX, DFF), 256, GSMEM>>>(
        p_ln, p_w + OW_FF1, bff1, nullptr, p_ff, MX, DFF, Dm, Dm, DFF);

    // 12) out = x2 + ffh @ Wff2 + bff2    (4-warp; K=4096)
    tgemm4w<3><<<qgrid(MX, Dm), 128, QSMEM>>>(
        p_ff, p_w + OW_FF2, bff2, p_x2, out, MX, Dm, DFF, DFF, Dm);
}

// round 11
// speedup vs baseline: 1.0807x; 1.0807x over previous
#include <cuda_runtime.h>
#include <math.h>

// ---------------- problem constants ----------------
#define Dm   1024
#define Hh   16
#define DH   64
#define DFF  4096
#define DC   768
#define Tt   2048
#define Bb   2
#define Cc   77
#define MX   4096          // Bb*Tt rows of x

// ---------------- scratch (static device arrays; no allocs) ----------------
__device__ float g_ln   [(size_t)MX * Dm];
__device__ float g_qkv  [(size_t)MX * 3 * Dm];
__device__ float g_attn [(size_t)MX * Dm];
__device__ float g_x1   [(size_t)MX * Dm];
__device__ float g_x2   [(size_t)MX * Dm];
__device__ float g_qca  [(size_t)MX * Dm];
__device__ float g_kvca [(size_t)Bb * Cc * 2 * Dm];
__device__ float g_ff   [(size_t)MX * DFF];
__device__ float g_w    [(size_t)16400000];          // tf32-rounded weights + cond

// weight-scratch offsets (floats) - contiguous, in rounding order
#define SZ_QKV  (Dm*3*Dm)
#define SZ_PSA  (Dm*Dm)
#define SZ_QCA  (Dm*Dm)
#define SZ_KVCA (DC*2*Dm)
#define SZ_PCA  (Dm*Dm)
#define SZ_FF1  (Dm*DFF)
#define SZ_FF2  (DFF*Dm)
#define SZ_COND (Bb*Cc*DC)
#define OW_QKV   0
#define OW_PSA   (OW_QKV + SZ_QKV)
#define OW_QCA   (OW_PSA + SZ_PSA)
#define OW_KVCA  (OW_QCA + SZ_QCA)
#define OW_PCA   (OW_KVCA + SZ_KVCA)
#define OW_FF1   (OW_PCA + SZ_PCA)
#define OW_FF2   (OW_FF1 + SZ_FF1)
#define OW_COND  (OW_FF2 + SZ_FF2)
#define OW_TOT   (OW_COND + SZ_COND)

// ---------------- tf32 helpers ----------------
__device__ __forceinline__ unsigned totf(float f) {
    unsigned u;
    asm("cvt.rna.tf32.f32 %0, %1;" : "=r"(u) : "f"(f));
    return u;
}
__device__ __forceinline__ float totf_f(float f) { return __uint_as_float(totf(f)); }

__device__ __forceinline__ void mma_tf32(float c[4],
    unsigned a0, unsigned a1, unsigned a2, unsigned a3,
    unsigned b0, unsigned b1)
{
    asm volatile(
        "mma.sync.aligned.m16n8k8.row.col.f32.tf32.tf32.f32 "
        "{%0,%1,%2,%3}, {%4,%5,%6,%7}, {%8,%9}, {%0,%1,%2,%3};\n"
        : "+f"(c[0]), "+f"(c[1]), "+f"(c[2]), "+f"(c[3])
        : "r"(a0), "r"(a1), "r"(a2), "r"(a3), "r"(b0), "r"(b1));
}

__device__ __forceinline__ void cpa16(unsigned dst, const float* src, bool pred) {
    int sz = pred ? 16 : 0;
    asm volatile("cp.async.cg.shared.global [%0], [%1], 16, %2;\n"
                 :: "r"(dst), "l"(src), "r"(sz));
}
__device__ __forceinline__ void cpa16u(unsigned dst, const float* src) {
    asm volatile("cp.async.cg.shared.global [%0], [%1], 16;\n"
                 :: "r"(dst), "l"(src));
}
__device__ __forceinline__ void cpa_commit() {
    asm volatile("cp.async.commit_group;\n");
}
template<int N>
__device__ __forceinline__ void cpa_wait() {
    asm volatile("cp.async.wait_group %0;\n" :: "n"(N));
}

// ---------------- merged weight rounding prep (one launch) ----------------
__global__ __launch_bounds__(256) void round_all_kernel(
    const float* __restrict__ s0, const float* __restrict__ s1,
    const float* __restrict__ s2, const float* __restrict__ s3,
    const float* __restrict__ s4, const float* __restrict__ s5,
    const float* __restrict__ s6, const float* __restrict__ s7,
    float* __restrict__ dst)
{
    int n4 = OW_TOT / 4;
    for (int i = blockIdx.x * 256 + threadIdx.x; i < n4; i += gridDim.x * 256) {
        int idx = i * 4;
        const float* src;
        if      (idx < OW_PSA)  src = s0 + (idx - OW_QKV);
        else if (idx < OW_QCA)  src = s1 + (idx - OW_PSA);
        else if (idx < OW_KVCA) src = s2 + (idx - OW_QCA);
        else if (idx < OW_PCA)  src = s3 + (idx - OW_KVCA);
        else if (idx < OW_FF1)  src = s4 + (idx - OW_PCA);
        else if (idx < OW_FF2)  src = s5 + (idx - OW_FF1);
        else if (idx < OW_COND) src = s6 + (idx - OW_FF2);
        else                    src = s7 + (idx - OW_COND);
        float4 v = *(const float4*)src;
        v.x = totf_f(v.x); v.y = totf_f(v.y);
        v.z = totf_f(v.z); v.w = totf_f(v.w);
        *(float4*)(dst + idx) = v;
    }
}

// ---------------- reductions ----------------
__device__ __forceinline__ float block_sum(float v, float* sh) {
    #pragma unroll
    for (int o = 16; o > 0; o >>= 1) v += __shfl_xor_sync(0xffffffffu, v, o);
    int w = threadIdx.x >> 5;
    if ((threadIdx.x & 31) == 0) sh[w] = v;
    __syncthreads();
    if (threadIdx.x < 32) {
        float t = (threadIdx.x < 8) ? sh[threadIdx.x] : 0.f;
        #pragma unroll
        for (int o = 4; o > 0; o >>= 1) t += __shfl_xor_sync(0xffffffffu, t, o);
        if (threadIdx.x == 0) sh[0] = t;
    }
    __syncthreads();
    float r = sh[0];
    __syncthreads();
    return r;
}

// ---------------- LayerNorm (tf32-rounded output) ----------------
__global__ __launch_bounds__(256) void ln_kernel(
    const float* __restrict__ x, const float* __restrict__ g,
    const float* __restrict__ b, float* __restrict__ out)
{
    __shared__ float sh[8];
    long row = blockIdx.x;
    const float4* xr = (const float4*)(x + row * Dm);
    int tid = threadIdx.x;
    float4 v = xr[tid];
    float s = v.x + v.y + v.z + v.w;
    s = block_sum(s, sh);
    float mean = s * (1.0f / Dm);
    float dx = v.x - mean, dy = v.y - mean, dz = v.z - mean, dw = v.w - mean;
    float s2 = dx*dx + dy*dy + dz*dz + dw*dw;
    s2 = block_sum(s2, sh);
    float rstd = rsqrtf(s2 * (1.0f / Dm) + 1e-5f);
    float4 gg = ((const float4*)g)[tid];
    float4 bbv = ((const float4*)b)[tid];
    float4 o;
    o.x = totf_f(dx * rstd * gg.x + bbv.x);
    o.y = totf_f(dy * rstd * gg.y + bbv.y);
    o.z = totf_f(dz * rstd * gg.z + bbv.z);
    o.w = totf_f(dw * rstd * gg.w + bbv.w);
    ((float4*)(out + row * Dm))[tid] = o;
}

// ================= fused flash attention (tf32, LDS.64 permuted Q/K) ================
// Q/K smem store k-permuted within 8-groups: pos8(w) = (w&3)*2 + (w>>2), so the
// fragment pair (k, k+4) is contiguous -> LDS.64. FSQ=72 makes 64-bit frag reads
// bank-conflict-free (bank = 8*gid + 2*tg per 16-lane phase). V stays scalar.
#define FBQ 128
#define FBK 64
#define FSQ 72
#define FSV 72
#define FSMEM ((FBQ*FSQ + FBK*FSQ + FBK*FSV) * 4)

__global__ __launch_bounds__(256, 2) void flash_kernel(
    const float* __restrict__ Qp, const float* __restrict__ Kp,
    const float* __restrict__ Vp, float* __restrict__ Op,
    int Tq, int Tk, int ldq, int ldk, int ldo,
    long sQb, long sQh, long sKb, long sKh, long sOb, long sOh,
    int Hn, float scale, int causal)
{
    extern __shared__ unsigned fsm[];
    unsigned* Qs = fsm;
    unsigned* Ks = fsm + FBQ * FSQ;
    unsigned* Vs = Ks + FBK * FSQ;

    int z = blockIdx.z, zb = z / Hn, zh = z - zb * Hn;
    Qp += zb * sQb + zh * sQh;
    Kp += zb * sKb + zh * sKh;
    Vp += zb * sKb + zh * sKh;
    Op += zb * sOb + zh * sOh;

    int tid = threadIdx.x, lane = tid & 31, warp = tid >> 5;
    int gid = lane >> 2, tg = lane & 3;
    // longest-first for causal (highest row blocks first)
    int yb = causal ? ((int)gridDim.y - 1 - (int)blockIdx.y) : (int)blockIdx.y;
    int row0 = yb * FBQ;

    // ---- Q tile: permuted store; exact pow2 scale folded ----
    #pragma unroll
    for (int it = 0; it < 8; it++) {
        int idx = it * 256 + tid;
        int r = idx >> 4, c4 = (idx & 15) * 4;        // c4 multiple of 4
        int gr = row0 + r;
        float4 v = make_float4(0.f, 0.f, 0.f, 0.f);
        if (gr < Tq) v = *(const float4*)(Qp + (long)gr * ldq + c4);
        int pbase = r * FSQ + (c4 & ~7) + ((c4 & 4) ? 1 : 0);
        Qs[pbase + 0] = __float_as_uint(v.x * scale);
        Qs[pbase + 2] = __float_as_uint(v.y * scale);
        Qs[pbase + 4] = __float_as_uint(v.z * scale);
        Qs[pbase + 6] = __float_as_uint(v.w * scale);
    }

    int r_0 = row0 + warp * 16 + gid;
    int r_1 = r_0 + 8;

    float m0 = -1e30f, m1 = -1e30f, l0 = 0.f, l1 = 0.f;
    float o[8][4];
    #pragma unroll
    for (int i = 0; i < 8; i++)
        #pragma unroll
        for (int j = 0; j < 4; j++) o[i][j] = 0.f;

    int ntile = causal ? (row0 + FBQ) / FBK : (Tk + FBK - 1) / FBK;

    for (int t = 0; t < ntile; t++) {
        int kvb = t * FBK;
        __syncthreads();
        // ---- load K (permuted), V (linear) ----
        #pragma unroll
        for (int it = 0; it < 4; it++) {
            int idx = it * 256 + tid;
            int r = idx >> 4, c4 = (idx & 15) * 4;
            int gr = kvb + r;
            float4 kv = make_float4(0.f,0.f,0.f,0.f), vv = make_float4(0.f,0.f,0.f,0.f);
            if (gr < Tk) {
                kv = *(const float4*)(Kp + (long)gr * ldk + c4);
                vv = *(const float4*)(Vp + (long)gr * ldk + c4);
            }
            int pbase = r * FSQ + (c4 & ~7) + ((c4 & 4) ? 1 : 0);
            Ks[pbase + 0] = __float_as_uint(kv.x);
            Ks[pbase + 2] = __float_as_uint(kv.y);
            Ks[pbase + 4] = __float_as_uint(kv.z);
            Ks[pbase + 6] = __float_as_uint(kv.w);
            unsigned* v = &Vs[r * FSV + c4];
            v[0] = __float_as_uint(vv.x); v[1] = __float_as_uint(vv.y);
            v[2] = __float_as_uint(vv.z); v[3] = __float_as_uint(vv.w);
        }
        __syncthreads();

        // ---- S = Q @ K^T  (LDS.64 frags) ----
        float sacc[8][4];
        #pragma unroll
        for (int i = 0; i < 8; i++)
            #pragma unroll
            for (int j = 0; j < 4; j++) sacc[i][j] = 0.f;

        #pragma unroll
        for (int ks = 0; ks < 8; ks++) {
            int qb = (warp * 16 + gid) * FSQ + ks * 8 + tg * 2;
            uint2 qlo = *(const uint2*)&Qs[qb];              // (a0, a2): row r
            uint2 qhi = *(const uint2*)&Qs[qb + 8 * FSQ];    // (a1, a3): row r+8
            #pragma unroll
            for (int ni = 0; ni < 8; ni++) {
                int kb = (ni * 8 + gid) * FSQ + ks * 8 + tg * 2;
                uint2 kk = *(const uint2*)&Ks[kb];           // (b0, b1)
                mma_tf32(sacc[ni], qlo.x, qhi.x, qlo.y, qhi.y, kk.x, kk.y);
            }
        }

        bool domask = (causal && (kvb + FBK - 1 > row0)) || (kvb + FBK > Tk);
        if (domask) {
            #pragma unroll
            for (int ni = 0; ni < 8; ni++) {
                #pragma unroll
                for (int s = 0; s < 4; s++) {
                    int col = kvb + ni * 8 + tg * 2 + (s & 1);
                    int r = (s < 2) ? r_0 : r_1;
                    bool ok = (col < Tk) && (!causal || col <= r);
                    if (!ok) sacc[ni][s] = -1e30f;
                }
            }
        }

        // ---- online softmax ----
        float tm0 = -1e30f, tm1 = -1e30f;
        #pragma unroll
        for (int ni = 0; ni < 8; ni++) {
            tm0 = fmaxf(tm0, fmaxf(sacc[ni][0], sacc[ni][1]));
            tm1 = fmaxf(tm1, fmaxf(sacc[ni][2], sacc[ni][3]));
        }
        tm0 = fmaxf(tm0, __shfl_xor_sync(0xffffffffu, tm0, 1));
        tm0 = fmaxf(tm0, __shfl_xor_sync(0xffffffffu, tm0, 2));
        tm1 = fmaxf(tm1, __shfl_xor_sync(0xffffffffu, tm1, 1));
        tm1 = fmaxf(tm1, __shfl_xor_sync(0xffffffffu, tm1, 2));

        float nm0 = fmaxf(m0, tm0), nm1 = fmaxf(m1, tm1);
        float sc0 = __expf(m0 - nm0), sc1 = __expf(m1 - nm1);
        m0 = nm0; m1 = nm1;

        float rs0 = 0.f, rs1 = 0.f;
        #pragma unroll
        for (int ni = 0; ni < 8; ni++) {
            sacc[ni][0] = __expf(sacc[ni][0] - nm0); rs0 += sacc[ni][0];
            sacc[ni][1] = __expf(sacc[ni][1] - nm0); rs0 += sacc[ni][1];
            sacc[ni][2] = __expf(sacc[ni][2] - nm1); rs1 += sacc[ni][2];
            sacc[ni][3] = __expf(sacc[ni][3] - nm1); rs1 += sacc[ni][3];
        }
        rs0 += __shfl_xor_sync(0xffffffffu, rs0, 1);
        rs0 += __shfl_xor_sync(0xffffffffu, rs0, 2);
        rs1 += __shfl_xor_sync(0xffffffffu, rs1, 1);
        rs1 += __shfl_xor_sync(0xffffffffu, rs1, 2);
        l0 = l0 * sc0 + rs0;
        l1 = l1 * sc1 + rs1;

        #pragma unroll
        for (int ni = 0; ni < 8; ni++) {
            o[ni][0] *= sc0; o[ni][1] *= sc0;
            o[ni][2] *= sc1; o[ni][3] *= sc1;
        }

        // ---- O += P @ V ----
        int bl = lane & ~3;
        int s0 = bl + (tg >> 1);
        int s1 = bl + 2 + (tg >> 1);
        bool hi = (tg & 1);
        #pragma unroll
        for (int ks = 0; ks < 8; ks++) {
            float p0 = sacc[ks][0], p1 = sacc[ks][1];
            float p2 = sacc[ks][2], p3 = sacc[ks][3];
            float v00 = __shfl_sync(0xffffffffu, p0, s0);
            float v01 = __shfl_sync(0xffffffffu, p1, s0);
            float v10 = __shfl_sync(0xffffffffu, p2, s0);
            float v11 = __shfl_sync(0xffffffffu, p3, s0);
            float w00 = __shfl_sync(0xffffffffu, p0, s1);
            float w01 = __shfl_sync(0xffffffffu, p1, s1);
            float w10 = __shfl_sync(0xffffffffu, p2, s1);
            float w11 = __shfl_sync(0xffffffffu, p3, s1);
            unsigned a0 = totf(hi ? v01 : v00);
            unsigned a1 = totf(hi ? v11 : v10);
            unsigned a2 = totf(hi ? w01 : w00);
            unsigned a3 = totf(hi ? w11 : w10);
            #pragma unroll
            for (int nj = 0; nj < 8; nj++) {
                int vb = (ks * 8 + tg) * FSV + nj * 8 + gid;
                mma_tf32(o[nj], a0, a1, a2, a3, Vs[vb], Vs[vb + 4 * FSV]);
            }
        }
    }

    float inv0 = 1.0f / l0, inv1 = 1.0f / l1;
    #pragma unroll
    for (int nj = 0; nj < 8; nj++) {
        int c = nj * 8 + tg * 2;
        if (r_0 < Tq) {
            float2 w = make_float2(totf_f(o[nj][0] * inv0), totf_f(o[nj][1] * inv0));
            *(float2*)(Op + (long)r_0 * ldo + c) = w;
        }
        if (r_1 < Tq) {
            float2 w = make_float2(totf_f(o[nj][2] * inv1), totf_f(o[nj][3] * inv1));
            *(float2*)(Op + (long)r_1 * ldo + c) = w;
        }
    }
}

// ================= cp.async 4-stage tf32 GEMM, 128x256 block, 64x64 warp tile ========
#define BM 128
#define BN 256
#define BK 16
#define NSTG 4
#define SAS 20
#define SBS 264
#define AW (BM * SAS)
#define BW (BK * SBS)
#define STG (AW + BW)
#define GSMEM (STG * NSTG * 4)

template<int EPI>
__global__ __launch_bounds__(256, 1) void tgemm(
    const float* __restrict__ A, const float* __restrict__ Bm,
    const float* __restrict__ bias, const float* __restrict__ Res,
    float* __restrict__ C,
    int M, int N, int K, int lda, int ldb)
{
    extern __shared__ unsigned dsm[];
    unsigned sbase = (unsigned)__cvta_generic_to_shared(dsm);

    int row0 = blockIdx.y * BM, col0 = blockIdx.x * BN;
    int tid  = threadIdx.x;
    int lane = tid & 31, warp = tid >> 5;
    int wm = (warp & 1) * 64;
    int wn = (warp >> 1) * 64;
    int gid = lane >> 2, tg = lane & 3;

    int ar = tid >> 1;
    int ak = (tid & 1) * 8;
    int bk = tid >> 6;
    int bn = (tid & 63) * 4;

    auto load_stage = [&](int s, int k0) {
        unsigned abase = sbase + (s * STG) * 4;
        unsigned bbase = sbase + (s * STG + AW) * 4;
        const float* asrc = A + (long)(row0 + ar) * lda + k0 + ak;
        bool av = (row0 + ar) < M;
        unsigned adst = abase + (ar * SAS + ak) * 4;
        cpa16(adst, asrc, av);
        cpa16(adst + 16, asrc + 4, av);
        const float* bsrc = Bm + (long)(k0 + bk) * ldb + col0 + bn;
        unsigned bdst = bbase + (bk * SBS + bn) * 4;
        #pragma unroll
        for (int i = 0; i < 4; i++)
            cpa16u(bdst + i * (SBS * 4 * 4), bsrc + (long)(4 * i) * ldb);
    };

    float acc[4][8][4];
    #pragma unroll
    for (int i = 0; i < 4; i++)
        #pragma unroll
        for (int j = 0; j < 8; j++)
            #pragma unroll
            for (int r = 0; r < 4; r++) acc[i][j][r] = 0.f;

    int ntiles = K / BK;

    #pragma unroll
    for (int s = 0; s < NSTG - 1; s++) {
        if (s < ntiles) load_stage(s, s * BK);
        cpa_commit();
    }

    for (int t = 0; t < ntiles; t++) {
        cpa_wait<NSTG - 2>();
        __syncthreads();

        int tn = t + NSTG - 1;
        if (tn < ntiles) load_stage(tn % NSTG, tn * BK);
        cpa_commit();

        int buf = t % NSTG;
        const unsigned* As = dsm + buf * STG;
        const unsigned* Bs = dsm + buf * STG + AW;

        #pragma unroll
        for (int ks = 0; ks < 2; ks++) {
            int k0s = ks * 8;
            unsigned a[4][4], b[8][2];
            #pragma unroll
            for (int mi = 0; mi < 4; mi++) {
                int r = wm + mi * 16 + gid;
                a[mi][0] = As[r * SAS + k0s + tg];
                a[mi][1] = As[(r + 8) * SAS + k0s + tg];
                a[mi][2] = As[r * SAS + k0s + tg + 4];
                a[mi][3] = As[(r + 8) * SAS + k0s + tg + 4];
            }
            #pragma unroll
            for (int ni = 0; ni < 8; ni++) {
                int n = wn + ni * 8 + gid;
                b[ni][0] = Bs[(k0s + tg) * SBS + n];
                b[ni][1] = Bs[(k0s + tg + 4) * SBS + n];
            }
            #pragma unroll
            for (int mi = 0; mi < 4; mi++)
                #pragma unroll
                for (int ni = 0; ni < 8; ni++)
                    mma_tf32(acc[mi][ni], a[mi][0], a[mi][1], a[mi][2], a[mi][3],
                             b[ni][0], b[ni][1]);
        }
    }

    #pragma unroll
    for (int mi = 0; mi < 4; mi++) {
        #pragma unroll
        for (int rr = 0; rr < 2; rr++) {
            int r = row0 + wm + mi * 16 + gid + rr * 8;
            if (r >= M) continue;
            #pragma unroll
            for (int ni = 0; ni < 8; ni++) {
                int c = col0 + wn + ni * 8 + tg * 2;
                float v0 = acc[mi][ni][rr * 2 + 0];
                float v1 = acc[mi][ni][rr * 2 + 1];
                if (EPI & 1) { v0 += bias[c]; v1 += bias[c + 1]; }
                if (EPI & 4) {
                    v0 = 0.5f * v0 * (1.0f + erff(v0 * 0.70710678118654752f));
                    v1 = 0.5f * v1 * (1.0f + erff(v1 * 0.70710678118654752f));
                }
                if (EPI & 2) {
                    float2 rv = *(const float2*)(Res + (long)r * N + c);
                    v0 += rv.x; v1 += rv.y;
                }
                if (EPI & 8) { v0 = totf_f(v0); v1 = totf_f(v1); }
                *(float2*)(C + (long)r * N + c) = make_float2(v0, v1);
            }
        }
    }
}

// ---------------- host side ----------------
static inline dim3 ggrid(int M, int N) {
    return dim3((unsigned)((N + BN - 1) / BN), (unsigned)((M + BM - 1) / BM), 1);
}

extern "C" void kernel_launch(void* const* d_in, const int* in_sizes, int n_in,
                              void* d_out, int out_size)
{
    const float* x        = (const float*)d_in[0];
    const float* cond     = (const float*)d_in[1];
    const float* Wqkv     = (const float*)d_in[2];
    const float* Wproj_sa = (const float*)d_in[3];
    const float* bproj_sa = (const float*)d_in[4];
    const float* g1       = (const float*)d_in[5];
    const float* b1       = (const float*)d_in[6];
    const float* Wq_ca    = (const float*)d_in[7];
    const float* Wkv_ca   = (const float*)d_in[8];
    const float* Wproj_ca = (const float*)d_in[9];
    const float* bproj_ca = (const float*)d_in[10];
    const float* g2       = (const float*)d_in[11];
    const float* b2       = (const float*)d_in[12];
    const float* Wff1     = (const float*)d_in[13];
    const float* bff1     = (const float*)d_in[14];
    const float* Wff2     = (const float*)d_in[15];
    const float* bff2     = (const float*)d_in[16];
    const float* g3       = (const float*)d_in[17];
    const float* b3       = (const float*)d_in[18];
    float* out            = (float*)d_out;

    float *p_ln, *p_qkv, *p_attn, *p_x1, *p_x2, *p_qca, *p_kvca, *p_ff, *p_w;
    cudaGetSymbolAddress((void**)&p_ln,   g_ln);
    cudaGetSymbolAddress((void**)&p_qkv,  g_qkv);
    cudaGetSymbolAddress((void**)&p_attn, g_attn);
    cudaGetSymbolAddress((void**)&p_x1,   g_x1);
    cudaGetSymbolAddress((void**)&p_x2,   g_x2);
    cudaGetSymbolAddress((void**)&p_qca,  g_qca);
    cudaGetSymbolAddress((void**)&p_kvca, g_kvca);
    cudaGetSymbolAddress((void**)&p_ff,   g_ff);
    cudaGetSymbolAddress((void**)&p_w,    g_w);

    static int smem_set = 0;
    if (!smem_set) {
        cudaFuncSetAttribute(flash_kernel, cudaFuncAttributeMaxDynamicSharedMemorySize, FSMEM);
        cudaFuncSetAttribute(tgemm<8>,  cudaFuncAttributeMaxDynamicSharedMemorySize, GSMEM);
        cudaFuncSetAttribute(tgemm<3>,  cudaFuncAttributeMaxDynamicSharedMemorySize, GSMEM);
        cudaFuncSetAttribute(tgemm<13>, cudaFuncAttributeMaxDynamicSharedMemorySize, GSMEM);
        smem_set = 1;
    }

    const long T3D = (long)Tt * 3 * Dm;
    const long TD  = (long)Tt * Dm;
    const long KVb = (long)Cc * 2 * Dm;
    const float iscale = 0.125f;

    // 0) tf32-round all weights + cond into scratch (single launch)
    round_all_kernel<<<2048, 256>>>(Wqkv, Wproj_sa, Wq_ca, Wkv_ca,
                                    Wproj_ca, Wff1, Wff2, cond, p_w);

    // 1) ln1 = LN(x)
    ln_kernel<<<MX, 256>>>(x, g1, b1, p_ln);

    // 2) qkv = ln1 @ Wqkv   (rounded output -> flash inputs)
    tgemm<8><<<ggrid(MX, 3*Dm), 256, GSMEM>>>(
        p_ln, p_w + OW_QKV, nullptr, nullptr, p_qkv, MX, 3*Dm, Dm, Dm, 3*Dm);

    // 3) fused causal self-attention -> g_attn
    flash_kernel<<<dim3(1, Tt/FBQ, Bb*Hh), 256, FSMEM>>>(
        p_qkv, p_qkv + Dm, p_qkv + 2*Dm, p_attn,
        Tt, Tt, 3*Dm, 3*Dm, Dm,
        T3D, DH, T3D, DH, TD, DH, Hh, iscale, 1);

    // 4) x1 = x + attn @ Wproj_sa + b
    tgemm<3><<<ggrid(MX, Dm), 256, GSMEM>>>(
        p_attn, p_w + OW_PSA, bproj_sa, x, p_x1, MX, Dm, Dm, Dm, Dm);

    // 5) ln2 = LN(x1)
    ln_kernel<<<MX, 256>>>(p_x1, g2, b2, p_ln);

    // 6) q_ca = ln2 @ Wq_ca  (rounded -> flash)
    tgemm<8><<<ggrid(MX, Dm), 256, GSMEM>>>(
        p_ln, p_w + OW_QCA, nullptr, nullptr, p_qca, MX, Dm, Dm, Dm, Dm);

    // 7) kv_ca = cond_r @ Wkv_ca (rounded -> flash)
    tgemm<8><<<ggrid(Bb*Cc, 2*Dm), 256, GSMEM>>>(
        p_w + OW_COND, p_w + OW_KVCA, nullptr, nullptr, p_kvca,
        Bb*Cc, 2*Dm, DC, DC, 2*Dm);

    // 8) fused cross-attention -> g_attn
    flash_kernel<<<dim3(1, Tt/FBQ, Bb*Hh), 256, FSMEM>>>(
        p_qca, p_kvca, p_kvca + Dm, p_attn,
        Tt, Cc, Dm, 2*Dm, Dm,
        TD, DH, KVb, DH, TD, DH, Hh, iscale, 0);

    // 9) x2 = x1 + ca_out @ Wproj_ca + b
    tgemm<3><<<ggrid(MX, Dm), 256, GSMEM>>>(
        p_attn, p_w + OW_PCA, bproj_ca, p_x1, p_x2, MX, Dm, Dm, Dm, Dm);

    // 10) ln3 = LN(x2)
    ln_kernel<<<MX, 256>>>(p_x2, g3, b3, p_ln);

    // 11) ffh = gelu(ln3 @ Wff1 + bff1), rounded
    tgemm<13><<<ggrid(MX, DFF), 256, GSMEM>>>(
        p_ln, p_w + OW_FF1, bff1, nullptr, p_ff, MX, DFF, Dm, Dm, DFF);

    // 12) out = x2 + ffh @ Wff2 + bff2
    tgemm<3><<<ggrid(MX, Dm), 256, GSMEM>>>(
        p_ff, p_w + OW_FF2, bff2, p_x2, out, MX, Dm, DFF, DFF, Dm);
}

// round 12
// speedup vs baseline: 1.6147x; 1.4941x over previous
#include <cuda_runtime.h>
#include <cuda_fp16.h>
#include <math.h>

// ---------------- problem constants ----------------
#define Dm   1024
#define Hh   16
#define DH   64
#define DFF  4096
#define DC   768
#define Tt   2048
#define Bb   2
#define Cc   77
#define MX   4096          // Bb*Tt rows of x

// ---------------- scratch (static device arrays; no allocs) ----------------
__device__ __half g_lnH  [(size_t)MX * Dm];
__device__ __half g_qkvH [(size_t)MX * 3 * Dm];
__device__ __half g_attnH[(size_t)MX * Dm];
__device__ __half g_qcaH [(size_t)MX * Dm];
__device__ __half g_kvcaH[(size_t)Bb * Cc * 2 * Dm];
__device__ __half g_ffH  [(size_t)MX * DFF];
__device__ float  g_x1   [(size_t)MX * Dm];
__device__ float  g_x2   [(size_t)MX * Dm];
__device__ __half g_wh   [(size_t)16400000];   // transposed half weights + cond

// weight-scratch offsets (elements)
#define SZ_QKV  (Dm*3*Dm)
#define SZ_PSA  (Dm*Dm)
#define SZ_QCA  (Dm*Dm)
#define SZ_KVCA (DC*2*Dm)
#define SZ_PCA  (Dm*Dm)
#define SZ_FF1  (Dm*DFF)
#define SZ_FF2  (DFF*Dm)
#define SZ_COND (Bb*Cc*DC)
#define OW_QKV   0
#define OW_PSA   (OW_QKV + SZ_QKV)
#define OW_QCA   (OW_PSA + SZ_PSA)
#define OW_KVCA  (OW_QCA + SZ_QCA)
#define OW_PCA   (OW_KVCA + SZ_KVCA)
#define OW_FF1   (OW_PCA + SZ_PCA)
#define OW_FF2   (OW_FF1 + SZ_FF1)
#define OW_COND  (OW_FF2 + SZ_FF2)

// ---------------- helpers ----------------
__device__ __forceinline__ unsigned hpack(float a, float b) {
    __half2 h = __floats2half2_rn(a, b);
    return *(unsigned*)&h;
}

__device__ __forceinline__ void mma_f16(float c[4],
    unsigned a0, unsigned a1, unsigned a2, unsigned a3,
    unsigned b0, unsigned b1)
{
    asm volatile(
        "mma.sync.aligned.m16n8k16.row.col.f32.f16.f16.f32 "
        "{%0,%1,%2,%3}, {%4,%5,%6,%7}, {%8,%9}, {%0,%1,%2,%3};\n"
        : "+f"(c[0]), "+f"(c[1]), "+f"(c[2]), "+f"(c[3])
        : "r"(a0), "r"(a1), "r"(a2), "r"(a3), "r"(b0), "r"(b1));
}

#define LDM_X4(r0,r1,r2,r3,addr) \
    asm volatile("ldmatrix.sync.aligned.m8n8.x4.shared.b16 {%0,%1,%2,%3}, [%4];" \
        : "=r"(r0),"=r"(r1),"=r"(r2),"=r"(r3) : "r"(addr))
#define LDM_X4T(r0,r1,r2,r3,addr) \
    asm volatile("ldmatrix.sync.aligned.m8n8.x4.trans.shared.b16 {%0,%1,%2,%3}, [%4];" \
        : "=r"(r0),"=r"(r1),"=r"(r2),"=r"(r3) : "r"(addr))

__device__ __forceinline__ void cpa16(unsigned dst, const void* src, bool pred) {
    int sz = pred ? 16 : 0;
    asm volatile("cp.async.cg.shared.global [%0], [%1], 16, %2;\n"
                 :: "r"(dst), "l"(src), "r"(sz));
}
__device__ __forceinline__ void cpa16u(unsigned dst, const void* src) {
    asm volatile("cp.async.cg.shared.global [%0], [%1], 16;\n"
                 :: "r"(dst), "l"(src));
}
__device__ __forceinline__ void cpa_commit() {
    asm volatile("cp.async.commit_group;\n");
}
template<int N>
__device__ __forceinline__ void cpa_wait() {
    asm volatile("cp.async.wait_group %0;\n" :: "n"(N));
}

// ---------------- prep: transpose+convert weights to half [N][K] ----------------
__global__ __launch_bounds__(256) void transpose_h(
    const float* __restrict__ src, __half* __restrict__ dst, int K, int N)
{
    __shared__ float t[32][33];
    int bx = blockIdx.x * 32, by = blockIdx.y * 32;
    int tx = threadIdx.x & 31, ty = threadIdx.x >> 5;   // 32 x 8
    #pragma unroll
    for (int j = 0; j < 32; j += 8)
        t[ty + j][tx] = src[(long)(by + ty + j) * N + bx + tx];
    __syncthreads();
    #pragma unroll
    for (int j = 0; j < 32; j += 8)
        dst[(long)(bx + ty + j) * K + by + tx] = __float2half(t[tx][ty + j]);
}

__global__ __launch_bounds__(256) void conv_h(
    const float* __restrict__ src, __half* __restrict__ dst, int n)
{
    int i = blockIdx.x * 256 + threadIdx.x;
    if (i < n) dst[i] = __float2half(src[i]);
}

// ---------------- reductions ----------------
__device__ __forceinline__ float block_sum(float v, float* sh) {
    #pragma unroll
    for (int o = 16; o > 0; o >>= 1) v += __shfl_xor_sync(0xffffffffu, v, o);
    int w = threadIdx.x >> 5;
    if ((threadIdx.x & 31) == 0) sh[w] = v;
    __syncthreads();
    if (threadIdx.x < 32) {
        float t = (threadIdx.x < 8) ? sh[threadIdx.x] : 0.f;
        #pragma unroll
        for (int o = 4; o > 0; o >>= 1) t += __shfl_xor_sync(0xffffffffu, t, o);
        if (threadIdx.x == 0) sh[0] = t;
    }
    __syncthreads();
    float r = sh[0];
    __syncthreads();
    return r;
}

// ---------------- LayerNorm (half output) ----------------
__global__ __launch_bounds__(256) void ln_kernel(
    const float* __restrict__ x, const float* __restrict__ g,
    const float* __restrict__ b, __half* __restrict__ out)
{
    __shared__ float sh[8];
    long row = blockIdx.x;
    const float4* xr = (const float4*)(x + row * Dm);
    int tid = threadIdx.x;
    float4 v = xr[tid];
    float s = v.x + v.y + v.z + v.w;
    s = block_sum(s, sh);
    float mean = s * (1.0f / Dm);
    float dx = v.x - mean, dy = v.y - mean, dz = v.z - mean, dw = v.w - mean;
    float s2 = dx*dx + dy*dy + dz*dz + dw*dw;
    s2 = block_sum(s2, sh);
    float rstd = rsqrtf(s2 * (1.0f / Dm) + 1e-5f);
    float4 gg = ((const float4*)g)[tid];
    float4 bbv = ((const float4*)b)[tid];
    uint2 u;
    u.x = hpack(dx * rstd * gg.x + bbv.x, dy * rstd * gg.y + bbv.y);
    u.y = hpack(dz * rstd * gg.z + bbv.z, dw * rstd * gg.w + bbv.w);
    ((uint2*)(out + row * Dm))[tid] = u;
}

// ================= fused flash attention (fp16 operands, fp32 softmax) =============
// Q/K/V tiles stored [row][64 halves], row stride 36 words (144 B).
// Frags via ldmatrix: Q/K non-trans, V trans (P@V B-operand).
// P A-frags come straight from the S accumulator (layout match, no shuffles).
#define FBQ 128
#define FBK 64
#define FST 36                                    // words per row
#define FSMEM ((FBQ + FBK + FBK) * FST * 4)       // 36864 B

__global__ __launch_bounds__(256, 2) void flash_kernel(
    const __half* __restrict__ Qp, const __half* __restrict__ Kp,
    const __half* __restrict__ Vp, __half* __restrict__ Op,
    int Tq, int Tk, int ldq, int ldk, int ldo,
    long sQb, long sQh, long sKb, long sKh, long sOb, long sOh,
    int Hn, int causal)
{
    extern __shared__ unsigned fsm[];
    unsigned* Qs = fsm;
    unsigned* Ks = fsm + FBQ * FST;
    unsigned* Vs = Ks + FBK * FST;
    unsigned sbase = (unsigned)__cvta_generic_to_shared(fsm);

    int z = blockIdx.z, zb = z / Hn, zh = z - zb * Hn;
    Qp += zb * sQb + zh * sQh;
    Kp += zb * sKb + zh * sKh;
    Vp += zb * sKb + zh * sKh;
    Op += zb * sOb + zh * sOh;

    int tid = threadIdx.x, lane = tid & 31, warp = tid >> 5;
    int gid = lane >> 2, tg = lane & 3;
    int sel = lane & 7, grp = lane >> 3;
    int yb = causal ? ((int)gridDim.y - 1 - (int)blockIdx.y) : (int)blockIdx.y;
    int row0 = yb * FBQ;

    const __half2 scale2 = __half2half2(__float2half(0.125f));

    // ---- Q tile: uint4 copies, *0.125 in half2 ----
    #pragma unroll
    for (int it = 0; it < 4; it++) {
        int idx = it * 256 + tid;                 // 1024 x 16B
        int r = idx >> 3, c8 = (idx & 7) * 8;
        int gr = row0 + r;
        uint4 v = make_uint4(0u, 0u, 0u, 0u);
        if (gr < Tq) v = *(const uint4*)(Qp + (long)gr * ldq + c8);
        __half2* h = (__half2*)&v;
        h[0] = __hmul2(h[0], scale2); h[1] = __hmul2(h[1], scale2);
        h[2] = __hmul2(h[2], scale2); h[3] = __hmul2(h[3], scale2);
        *(uint4*)&Qs[r * FST + c8 / 2] = v;
    }

    // ldmatrix per-thread base addresses
    unsigned qAddr = sbase + (unsigned)((warp * 16 + sel + ((grp & 1) << 3)) * 144
                                        + ((grp >> 1) << 4));
    unsigned kBase = sbase + FBQ * 144;
    unsigned vBase = kBase + FBK * 144;
    unsigned kRow = (unsigned)((sel + ((grp >> 1) << 3)) * 144 + ((grp & 1) << 4));
    unsigned vRow = (unsigned)((sel + ((grp & 1) << 3)) * 144 + ((grp >> 1) << 4));

    int r_0 = row0 + warp * 16 + gid;
    int r_1 = r_0 + 8;

    float m0 = -1e30f, m1 = -1e30f, l0 = 0.f, l1 = 0.f;
    float o[8][4];
    #pragma unroll
    for (int i = 0; i < 8; i++)
        #pragma unroll
        for (int j = 0; j < 4; j++) o[i][j] = 0.f;

    int ntile = causal ? (row0 + FBQ) / FBK : (Tk + FBK - 1) / FBK;

    for (int t = 0; t < ntile; t++) {
        int kvb = t * FBK;
        __syncthreads();
        // ---- load K, V tiles (raw uint4 copies) ----
        #pragma unroll
        for (int it = 0; it < 2; it++) {
            int idx = it * 256 + tid;             // 512 x 16B each
            int r = idx >> 3, c8 = (idx & 7) * 8;
            int gr = kvb + r;
            uint4 kv = make_uint4(0u,0u,0u,0u), vv = make_uint4(0u,0u,0u,0u);
            if (gr < Tk) {
                kv = *(const uint4*)(Kp + (long)gr * ldk + c8);
                vv = *(const uint4*)(Vp + (long)gr * ldk + c8);
            }
            *(uint4*)&Ks[r * FST + c8 / 2] = kv;
            *(uint4*)&Vs[r * FST + c8 / 2] = vv;
        }
        __syncthreads();

        // ---- S = Q @ K^T ----
        float sacc[8][4];
        #pragma unroll
        for (int i = 0; i < 8; i++)
            #pragma unroll
            for (int j = 0; j < 4; j++) sacc[i][j] = 0.f;

        #pragma unroll
        for (int ks = 0; ks < 4; ks++) {
            unsigned qa0, qa1, qa2, qa3;
            LDM_X4(qa0, qa1, qa2, qa3, qAddr + ks * 32);
            #pragma unroll
            for (int np = 0; np < 4; np++) {
                unsigned b0, b1, b2, b3;
                LDM_X4(b0, b1, b2, b3, kBase + np * (16 * 144) + kRow + ks * 32);
                mma_f16(sacc[2*np],     qa0, qa1, qa2, qa3, b0, b1);
                mma_f16(sacc[2*np + 1], qa0, qa1, qa2, qa3, b2, b3);
            }
        }

        bool domask = (causal && (kvb + FBK - 1 > row0)) || (kvb + FBK > Tk);
        if (domask) {
            #pragma unroll
            for (int ni = 0; ni < 8; ni++) {
                #pragma unroll
                for (int s = 0; s < 4; s++) {
                    int col = kvb + ni * 8 + tg * 2 + (s & 1);
                    int r = (s < 2) ? r_0 : r_1;
                    bool ok = (col < Tk) && (!causal || col <= r);
                    if (!ok) sacc[ni][s] = -1e30f;
                }
            }
        }

        // ---- online softmax (fp32) ----
        float tm0 = -1e30f, tm1 = -1e30f;
        #pragma unroll
        for (int ni = 0; ni < 8; ni++) {
            tm0 = fmaxf(tm0, fmaxf(sacc[ni][0], sacc[ni][1]));
            tm1 = fmaxf(tm1, fmaxf(sacc[ni][2], sacc[ni][3]));
        }
        tm0 = fmaxf(tm0, __shfl_xor_sync(0xffffffffu, tm0, 1));
        tm0 = fmaxf(tm0, __shfl_xor_sync(0xffffffffu, tm0, 2));
        tm1 = fmaxf(tm1, __shfl_xor_sync(0xffffffffu, tm1, 1));
        tm1 = fmaxf(tm1, __shfl_xor_sync(0xffffffffu, tm1, 2));

        float nm0 = fmaxf(m0, tm0), nm1 = fmaxf(m1, tm1);
        float sc0 = __expf(m0 - nm0), sc1 = __expf(m1 - nm1);
        m0 = nm0; m1 = nm1;

        float rs0 = 0.f, rs1 = 0.f;
        #pragma unroll
        for (int ni = 0; ni < 8; ni++) {
            sacc[ni][0] = __expf(sacc[ni][0] - nm0); rs0 += sacc[ni][0];
            sacc[ni][1] = __expf(sacc[ni][1] - nm0); rs0 += sacc[ni][1];
            sacc[ni][2] = __expf(sacc[ni][2] - nm1); rs1 += sacc[ni][2];
            sacc[ni][3] = __expf(sacc[ni][3] - nm1); rs1 += sacc[ni][3];
        }
        rs0 += __shfl_xor_sync(0xffffffffu, rs0, 1);
        rs0 += __shfl_xor_sync(0xffffffffu, rs0, 2);
        rs1 += __shfl_xor_sync(0xffffffffu, rs1, 1);
        rs1 += __shfl_xor_sync(0xffffffffu, rs1, 2);
        l0 = l0 * sc0 + rs0;
        l1 = l1 * sc1 + rs1;

        #pragma unroll
        for (int ni = 0; ni < 8; ni++) {
            o[ni][0] *= sc0; o[ni][1] *= sc0;
            o[ni][2] *= sc1; o[ni][3] *= sc1;
        }

        // ---- O += P @ V  (A-frags straight from sacc; V via ldmatrix.trans) ----
        #pragma unroll
        for (int ks = 0; ks < 4; ks++) {
            unsigned a0 = hpack(sacc[2*ks][0],     sacc[2*ks][1]);
            unsigned a1 = hpack(sacc[2*ks][2],     sacc[2*ks][3]);
            unsigned a2 = hpack(sacc[2*ks + 1][0], sacc[2*ks + 1][1]);
            unsigned a3 = hpack(sacc[2*ks + 1][2], sacc[2*ks + 1][3]);
            #pragma unroll
            for (int np = 0; np < 4; np++) {
                unsigned b0, b1, b2, b3;
                LDM_X4T(b0, b1, b2, b3, vBase + ks * (16 * 144) + vRow + np * 32);
                mma_f16(o[2*np],     a0, a1, a2, a3, b0, b1);
                mma_f16(o[2*np + 1], a0, a1, a2, a3, b2, b3);
            }
        }
    }

    float inv0 = 1.0f / l0, inv1 = 1.0f / l1;
    #pragma unroll
    for (int nj = 0; nj < 8; nj++) {
        int c = nj * 8 + tg * 2;
        if (r_0 < Tq) {
            __half2 w = __floats2half2_rn(o[nj][0] * inv0, o[nj][1] * inv0);
            *(__half2*)(Op + (long)r_0 * ldo + c) = w;
        }
        if (r_1 < Tq) {
            __half2 w = __floats2half2_rn(o[nj][2] * inv1, o[nj][3] * inv1);
            *(__half2*)(Op + (long)r_1 * ldo + c) = w;
        }
    }
}

// ======== fp16 cp.async 4-stage GEMM, 128x256 block, 64x64 warp tile ========
// A half [M][K] row-major; Bt half [N][K] (pre-transposed weights).
// EPI bits: 1=+bias, 2=+Res(float), 4=GELU, 8=half output
#define BM 128
#define BN 256
#define BKH 32                       // K halves per stage
#define NSTG 4
#define HST 20                       // words per smem row (16 data + 4 pad)
#define AW (BM * HST)                // 2560 words
#define BW (BN * HST)                // 5120 words
#define STG (AW + BW)                // 7680 words
#define GSMEM (STG * NSTG * 4)       // 122880 B

template<int EPI>
__global__ __launch_bounds__(256, 1) void hgemm(
    const __half* __restrict__ A, const __half* __restrict__ Bt,
    const float* __restrict__ bias, const float* __restrict__ Res,
    float* __restrict__ C,
    int M, int N, int K, int lda, int ldbk)
{
    extern __shared__ unsigned dsm[];
    unsigned sbase = (unsigned)__cvta_generic_to_shared(dsm);

    int row0 = blockIdx.y * BM, col0 = blockIdx.x * BN;
    int tid  = threadIdx.x;
    int lane = tid & 31, warp = tid >> 5;
    int wm = (warp & 1) * 64;
    int wn = (warp >> 1) * 64;
    int gid = lane >> 2, tg = lane & 3;

    int ar = tid >> 1;                    // A row 0..127
    int ha = (tid & 1) * 16;              // A half-offset {0,16}

    auto load_stage = [&](int s, int k0) {
        unsigned abase = sbase + (s * STG) * 4;
        unsigned bbase = sbase + (s * STG + AW) * 4;
        const __half* asrc = A + (long)(row0 + ar) * lda + k0 + ha;
        bool av = (row0 + ar) < M;
        unsigned adst = abase + (ar * HST + ha / 2) * 4;
        cpa16(adst, asrc, av);
        cpa16(adst + 16, asrc + 8, av);
        const __half* bsrc = Bt + (long)(col0 + tid) * ldbk + k0;
        unsigned bdst = bbase + (tid * HST) * 4;
        #pragma unroll
        for (int i = 0; i < 4; i++)
            cpa16u(bdst + i * 16, bsrc + i * 8);
    };

    float acc[4][8][4];
    #pragma unroll
    for (int i = 0; i < 4; i++)
        #pragma unroll
        for (int j = 0; j < 8; j++)
            #pragma unroll
            for (int r = 0; r < 4; r++) acc[i][j][r] = 0.f;

    int ntiles = K / BKH;

    #pragma unroll
    for (int s = 0; s < NSTG - 1; s++) {
        if (s < ntiles) load_stage(s, s * BKH);
        cpa_commit();
    }

    for (int t = 0; t < ntiles; t++) {
        cpa_wait<NSTG - 2>();
        __syncthreads();

        int tn = t + NSTG - 1;
        if (tn < ntiles) load_stage(tn % NSTG, tn * BKH);
        cpa_commit();

        int buf = t % NSTG;
        const unsigned* As = dsm + buf * STG;
        const unsigned* Bs = dsm + buf * STG + AW;

        #pragma unroll
        for (int ks = 0; ks < 2; ks++) {
            int k0s = ks * 8;                      // words
            unsigned a[4][4], b[8][2];
            #pragma unroll
            for (int mi = 0; mi < 4; mi++) {
                int r = wm + mi * 16 + gid;
                a[mi][0] = As[r * HST + k0s + tg];
                a[mi][1] = As[(r + 8) * HST + k0s + tg];
                a[mi][2] = As[r * HST + k0s + tg + 4];
                a[mi][3] = As[(r + 8) * HST + k0s + tg + 4];
            }
            #pragma unroll
            for (int ni = 0; ni < 8; ni++) {
                int n = wn + ni * 8 + gid;
                b[ni][0] = Bs[n * HST + k0s + tg];
                b[ni][1] = Bs[n * HST + k0s + tg + 4];
            }
            #pragma unroll
            for (int mi = 0; mi < 4; mi++)
                #pragma unroll
                for (int ni = 0; ni < 8; ni++)
                    mma_f16(acc[mi][ni], a[mi][0], a[mi][1], a[mi][2], a[mi][3],
                            b[ni][0], b[ni][1]);
        }
    }

    #pragma unroll
    for (int mi = 0; mi < 4; mi++) {
        #pragma unroll
        for (int rr = 0; rr < 2; rr++) {
            int r = row0 + wm + mi * 16 + gid + rr * 8;
            if (r >= M) continue;
            #pragma unroll
            for (int ni = 0; ni < 8; ni++) {
                int c = col0 + wn + ni * 8 + tg * 2;
                float v0 = acc[mi][ni][rr * 2 + 0];
                float v1 = acc[mi][ni][rr * 2 + 1];
                if (EPI & 1) { v0 += bias[c]; v1 += bias[c + 1]; }
                if (EPI & 4) {
                    v0 = 0.5f * v0 * (1.0f + erff(v0 * 0.70710678118654752f));
                    v1 = 0.5f * v1 * (1.0f + erff(v1 * 0.70710678118654752f));
                }
                if (EPI & 2) {
                    float2 rv = *(const float2*)(Res + (long)r * N + c);
                    v0 += rv.x; v1 += rv.y;
                }
                if (EPI & 8) {
                    *(__half2*)((__half*)C + (long)r * N + c) = __floats2half2_rn(v0, v1);
                } else {
                    *(float2*)(C + (long)r * N + c) = make_float2(v0, v1);
                }
            }
        }
    }
}

// ---------------- host side ----------------
static inline dim3 ggrid(int M, int N) {
    return dim3((unsigned)((N + BN - 1) / BN), (unsigned)((M + BM - 1) / BM), 1);
}

extern "C" void kernel_launch(void* const* d_in, const int* in_sizes, int n_in,
                              void* d_out, int out_size)
{
    const float* x        = (const float*)d_in[0];
    const float* cond     = (const float*)d_in[1];
    const float* Wqkv     = (const float*)d_in[2];
    const float* Wproj_sa = (const float*)d_in[3];
    const float* bproj_sa = (const float*)d_in[4];
    const float* g1       = (const float*)d_in[5];
    const float* b1       = (const float*)d_in[6];
    const float* Wq_ca    = (const float*)d_in[7];
    const float* Wkv_ca   = (const float*)d_in[8];
    const float* Wproj_ca = (const float*)d_in[9];
    const float* bproj_ca = (const float*)d_in[10];
    const float* g2       = (const float*)d_in[11];
    const float* b2       = (const float*)d_in[12];
    const float* Wff1     = (const float*)d_in[13];
    const float* bff1     = (const float*)d_in[14];
    const float* Wff2     = (const float*)d_in[15];
    const float* bff2     = (const float*)d_in[16];
    const float* g3       = (const float*)d_in[17];
    const float* b3       = (const float*)d_in[18];
    float* out            = (float*)d_out;

    __half *p_ln, *p_qkv, *p_attn, *p_qca, *p_kvca, *p_ff, *p_w;
    float *p_x1, *p_x2;
    cudaGetSymbolAddress((void**)&p_ln,   g_lnH);
    cudaGetSymbolAddress((void**)&p_qkv,  g_qkvH);
    cudaGetSymbolAddress((void**)&p_attn, g_attnH);
    cudaGetSymbolAddress((void**)&p_qca,  g_qcaH);
    cudaGetSymbolAddress((void**)&p_kvca, g_kvcaH);
    cudaGetSymbolAddress((void**)&p_ff,   g_ffH);
    cudaGetSymbolAddress((void**)&p_x1,   g_x1);
    cudaGetSymbolAddress((void**)&p_x2,   g_x2);
    cudaGetSymbolAddress((void**)&p_w,    g_wh);

    static int smem_set = 0;
    if (!smem_set) {
        cudaFuncSetAttribute(flash_kernel, cudaFuncAttributeMaxDynamicSharedMemorySize, FSMEM);
        cudaFuncSetAttribute(hgemm<8>,  cudaFuncAttributeMaxDynamicSharedMemorySize, GSMEM);
        cudaFuncSetAttribute(hgemm<3>,  cudaFuncAttributeMaxDynamicSharedMemorySize, GSMEM);
        cudaFuncSetAttribute(hgemm<13>, cudaFuncAttributeMaxDynamicSharedMemorySize, GSMEM);
        smem_set = 1;
    }

    const long T3D = (long)Tt * 3 * Dm;
    const long TD  = (long)Tt * Dm;
    const long KVb = (long)Cc * 2 * Dm;

    // 0) prep: transpose+convert weights, convert cond
    transpose_h<<<dim3(3*Dm/32, Dm/32), 256>>>(Wqkv,     p_w + OW_QKV,  Dm,  3*Dm);
    transpose_h<<<dim3(Dm/32,   Dm/32), 256>>>(Wproj_sa, p_w + OW_PSA,  Dm,  Dm);
    transpose_h<<<dim3(Dm/32,   Dm/32), 256>>>(Wq_ca,    p_w + OW_QCA,  Dm,  Dm);
    transpose_h<<<dim3(2*Dm/32, DC/32), 256>>>(Wkv_ca,   p_w + OW_KVCA, DC,  2*Dm);
    transpose_h<<<dim3(Dm/32,   Dm/32), 256>>>(Wproj_ca, p_w + OW_PCA,  Dm,  Dm);
    transpose_h<<<dim3(DFF/32,  Dm/32), 256>>>(Wff1,     p_w + OW_FF1,  Dm,  DFF);
    transpose_h<<<dim3(Dm/32,  DFF/32), 256>>>(Wff2,     p_w + OW_FF2,  DFF, Dm);
    conv_h<<<(SZ_COND + 255) / 256, 256>>>(cond, p_w + OW_COND, SZ_COND);

    // 1) ln1 = LN(x) -> half
    ln_kernel<<<MX, 256>>>(x, g1, b1, p_ln);

    // 2) qkv = ln1 @ Wqkv  (half out)
    hgemm<8><<<ggrid(MX, 3*Dm), 256, GSMEM>>>(
        p_ln, p_w + OW_QKV, nullptr, nullptr, (float*)p_qkv, MX, 3*Dm, Dm, Dm, Dm);

    // 3) fused causal self-attention -> g_attnH
    flash_kernel<<<dim3(1, Tt/FBQ, Bb*Hh), 256, FSMEM>>>(
        p_qkv, p_qkv + Dm, p_qkv + 2*Dm, p_attn,
        Tt, Tt, 3*Dm, 3*Dm, Dm,
        T3D, DH, T3D, DH, TD, DH, Hh, 1);

    // 4) x1 = x + attn @ Wproj_sa + b  (float out)
    hgemm<3><<<ggrid(MX, Dm), 256, GSMEM>>>(
        p_attn, p_w + OW_PSA, bproj_sa, x, p_x1, MX, Dm, Dm, Dm, Dm);

    // 5) ln2 = LN(x1) -> half
    ln_kernel<<<MX, 256>>>(p_x1, g2, b2, p_ln);

    // 6) q_ca = ln2 @ Wq_ca  (half out)
    hgemm<8><<<ggrid(MX, Dm), 256, GSMEM>>>(
        p_ln, p_w + OW_QCA, nullptr, nullptr, (float*)p_qca, MX, Dm, Dm, Dm, Dm);

    // 7) kv_ca = cond_h @ Wkv_ca  (half out)
    hgemm<8><<<ggrid(Bb*Cc, 2*Dm), 256, GSMEM>>>(
        p_w + OW_COND, p_w + OW_KVCA, nullptr, nullptr, (float*)p_kvca,
        Bb*Cc, 2*Dm, DC, DC, DC);

    // 8) fused cross-attention -> g_attnH
    flash_kernel<<<dim3(1, Tt/FBQ, Bb*Hh), 256, FSMEM>>>(
        p_qca, p_kvca, p_kvca + Dm, p_attn,
        Tt, Cc, Dm, 2*Dm, Dm,
        TD, DH, KVb, DH, TD, DH, Hh, 0);

    // 9) x2 = x1 + ca_out @ Wproj_ca + b  (float out)
    hgemm<3><<<ggrid(MX, Dm), 256, GSMEM>>>(
        p_attn, p_w + OW_PCA, bproj_ca, p_x1, p_x2, MX, Dm, Dm, Dm, Dm);

    // 10) ln3 = LN(x2) -> half
    ln_kernel<<<MX, 256>>>(p_x2, g3, b3, p_ln);

    // 11) ffh = gelu(ln3 @ Wff1 + bff1)  (half out)
    hgemm<13><<<ggrid(MX, DFF), 256, GSMEM>>>(
        p_ln, p_w + OW_FF1, bff1, nullptr, (float*)p_ff, MX, DFF, Dm, Dm, Dm);

    // 12) out = x2 + ffh @ Wff2 + bff2  (float out)
    hgemm<3><<<ggrid(MX, Dm), 256, GSMEM>>>(
        p_ff, p_w + OW_FF2, bff2, p_x2, out, MX, Dm, DFF, DFF, DFF);
}

// round 13
// speedup vs baseline: 1.7564x; 1.0878x over previous
#include <cuda_runtime.h>
#include <cuda_fp16.h>
#include <math.h>

// ---------------- problem constants ----------------
#define Dm   1024
#define Hh   16
#define DH   64
#define DFF  4096
#define DC   768
#define Tt   2048
#define Bb   2
#define Cc   77
#define MX   4096          // Bb*Tt rows of x

// ---------------- scratch (static device arrays; no allocs) ----------------
__device__ __half g_lnH  [(size_t)MX * Dm];
__device__ __half g_qkvH [(size_t)MX * 3 * Dm];
__device__ __half g_attnH[(size_t)MX * Dm];
__device__ __half g_qcaH [(size_t)MX * Dm];
__device__ __half g_kvcaH[(size_t)Bb * Cc * 2 * Dm];
__device__ __half g_ffH  [(size_t)MX * DFF];
__device__ float  g_x1   [(size_t)MX * Dm];
__device__ float  g_x2   [(size_t)MX * Dm];
__device__ __half g_wh   [(size_t)16400000];   // transposed half weights + cond

// weight-scratch offsets (elements)
#define SZ_QKV  (Dm*3*Dm)
#define SZ_PSA  (Dm*Dm)
#define SZ_QCA  (Dm*Dm)
#define SZ_KVCA (DC*2*Dm)
#define SZ_PCA  (Dm*Dm)
#define SZ_FF1  (Dm*DFF)
#define SZ_FF2  (DFF*Dm)
#define SZ_COND (Bb*Cc*DC)
#define OW_QKV   0
#define OW_PSA   (OW_QKV + SZ_QKV)
#define OW_QCA   (OW_PSA + SZ_PSA)
#define OW_KVCA  (OW_QCA + SZ_QCA)
#define OW_PCA   (OW_KVCA + SZ_KVCA)
#define OW_FF1   (OW_PCA + SZ_PCA)
#define OW_FF2   (OW_FF1 + SZ_FF1)
#define OW_COND  (OW_FF2 + SZ_FF2)

// ---------------- helpers ----------------
__device__ __forceinline__ unsigned hpack(float a, float b) {
    __half2 h = __floats2half2_rn(a, b);
    return *(unsigned*)&h;
}

__device__ __forceinline__ void mma_f16(float c[4],
    unsigned a0, unsigned a1, unsigned a2, unsigned a3,
    unsigned b0, unsigned b1)
{
    asm volatile(
        "mma.sync.aligned.m16n8k16.row.col.f32.f16.f16.f32 "
        "{%0,%1,%2,%3}, {%4,%5,%6,%7}, {%8,%9}, {%0,%1,%2,%3};\n"
        : "+f"(c[0]), "+f"(c[1]), "+f"(c[2]), "+f"(c[3])
        : "r"(a0), "r"(a1), "r"(a2), "r"(a3), "r"(b0), "r"(b1));
}

#define LDM_X4(r0,r1,r2,r3,addr) \
    asm volatile("ldmatrix.sync.aligned.m8n8.x4.shared.b16 {%0,%1,%2,%3}, [%4];" \
        : "=r"(r0),"=r"(r1),"=r"(r2),"=r"(r3) : "r"(addr))
#define LDM_X4T(r0,r1,r2,r3,addr) \
    asm volatile("ldmatrix.sync.aligned.m8n8.x4.trans.shared.b16 {%0,%1,%2,%3}, [%4];" \
        : "=r"(r0),"=r"(r1),"=r"(r2),"=r"(r3) : "r"(addr))

__device__ __forceinline__ void cpa16(unsigned dst, const void* src, bool pred) {
    int sz = pred ? 16 : 0;
    asm volatile("cp.async.cg.shared.global [%0], [%1], 16, %2;\n"
                 :: "r"(dst), "l"(src), "r"(sz));
}
__device__ __forceinline__ void cpa16u(unsigned dst, const void* src) {
    asm volatile("cp.async.cg.shared.global [%0], [%1], 16;\n"
                 :: "r"(dst), "l"(src));
}
__device__ __forceinline__ void cpa_commit() {
    asm volatile("cp.async.commit_group;\n");
}
template<int N>
__device__ __forceinline__ void cpa_wait() {
    asm volatile("cp.async.wait_group %0;\n" :: "n"(N));
}

// ---------------- prep: transpose+convert weights to half [N][K] ----------------
__global__ __launch_bounds__(256) void transpose_h(
    const float* __restrict__ src, __half* __restrict__ dst, int K, int N)
{
    __shared__ float t[32][33];
    int bx = blockIdx.x * 32, by = blockIdx.y * 32;
    int tx = threadIdx.x & 31, ty = threadIdx.x >> 5;   // 32 x 8
    #pragma unroll
    for (int j = 0; j < 32; j += 8)
        t[ty + j][tx] = src[(long)(by + ty + j) * N + bx + tx];
    __syncthreads();
    #pragma unroll
    for (int j = 0; j < 32; j += 8)
        dst[(long)(bx + ty + j) * K + by + tx] = __float2half(t[tx][ty + j]);
}

__global__ __launch_bounds__(256) void conv_h(
    const float* __restrict__ src, __half* __restrict__ dst, int n)
{
    int i = blockIdx.x * 256 + threadIdx.x;
    if (i < n) dst[i] = __float2half(src[i]);
}

// ---------------- reductions ----------------
__device__ __forceinline__ float block_sum(float v, float* sh) {
    #pragma unroll
    for (int o = 16; o > 0; o >>= 1) v += __shfl_xor_sync(0xffffffffu, v, o);
    int w = threadIdx.x >> 5;
    if ((threadIdx.x & 31) == 0) sh[w] = v;
    __syncthreads();
    if (threadIdx.x < 32) {
        float t = (threadIdx.x < 8) ? sh[threadIdx.x] : 0.f;
        #pragma unroll
        for (int o = 4; o > 0; o >>= 1) t += __shfl_xor_sync(0xffffffffu, t, o);
        if (threadIdx.x == 0) sh[0] = t;
    }
    __syncthreads();
    float r = sh[0];
    __syncthreads();
    return r;
}

// ---------------- LayerNorm (half output) ----------------
__global__ __launch_bounds__(256) void ln_kernel(
    const float* __restrict__ x, const float* __restrict__ g,
    const float* __restrict__ b, __half* __restrict__ out)
{
    __shared__ float sh[8];
    long row = blockIdx.x;
    const float4* xr = (const float4*)(x + row * Dm);
    int tid = threadIdx.x;
    float4 v = xr[tid];
    float s = v.x + v.y + v.z + v.w;
    s = block_sum(s, sh);
    float mean = s * (1.0f / Dm);
    float dx = v.x - mean, dy = v.y - mean, dz = v.z - mean, dw = v.w - mean;
    float s2 = dx*dx + dy*dy + dz*dz + dw*dw;
    s2 = block_sum(s2, sh);
    float rstd = rsqrtf(s2 * (1.0f / Dm) + 1e-5f);
    float4 gg = ((const float4*)g)[tid];
    float4 bbv = ((const float4*)b)[tid];
    uint2 u;
    u.x = hpack(dx * rstd * gg.x + bbv.x, dy * rstd * gg.y + bbv.y);
    u.y = hpack(dz * rstd * gg.z + bbv.z, dw * rstd * gg.w + bbv.w);
    ((uint2*)(out + row * Dm))[tid] = u;
}

// ================= fused flash attention (fp16 operands, fp32 softmax) =============
#define FBQ 128
#define FBK 64
#define FST 36                                    // words per row
#define FSMEM ((FBQ + FBK + FBK) * FST * 4)       // 36864 B

__global__ __launch_bounds__(256, 2) void flash_kernel(
    const __half* __restrict__ Qp, const __half* __restrict__ Kp,
    const __half* __restrict__ Vp, __half* __restrict__ Op,
    int Tq, int Tk, int ldq, int ldk, int ldo,
    long sQb, long sQh, long sKb, long sKh, long sOb, long sOh,
    int Hn, int causal)
{
    extern __shared__ unsigned fsm[];
    unsigned* Qs = fsm;
    unsigned* Ks = fsm + FBQ * FST;
    unsigned* Vs = Ks + FBK * FST;
    unsigned sbase = (unsigned)__cvta_generic_to_shared(fsm);

    int z = blockIdx.z, zb = z / Hn, zh = z - zb * Hn;
    Qp += zb * sQb + zh * sQh;
    Kp += zb * sKb + zh * sKh;
    Vp += zb * sKb + zh * sKh;
    Op += zb * sOb + zh * sOh;

    int tid = threadIdx.x, lane = tid & 31, warp = tid >> 5;
    int gid = lane >> 2, tg = lane & 3;
    int sel = lane & 7, grp = lane >> 3;
    int yb = causal ? ((int)gridDim.y - 1 - (int)blockIdx.y) : (int)blockIdx.y;
    int row0 = yb * FBQ;

    const __half2 scale2 = __half2half2(__float2half(0.125f));

    #pragma unroll
    for (int it = 0; it < 4; it++) {
        int idx = it * 256 + tid;
        int r = idx >> 3, c8 = (idx & 7) * 8;
        int gr = row0 + r;
        uint4 v = make_uint4(0u, 0u, 0u, 0u);
        if (gr < Tq) v = *(const uint4*)(Qp + (long)gr * ldq + c8);
        __half2* h = (__half2*)&v;
        h[0] = __hmul2(h[0], scale2); h[1] = __hmul2(h[1], scale2);
        h[2] = __hmul2(h[2], scale2); h[3] = __hmul2(h[3], scale2);
        *(uint4*)&Qs[r * FST + c8 / 2] = v;
    }

    unsigned qAddr = sbase + (unsigned)((warp * 16 + sel + ((grp & 1) << 3)) * 144
                                        + ((grp >> 1) << 4));
    unsigned kBase = sbase + FBQ * 144;
    unsigned vBase = kBase + FBK * 144;
    unsigned kRow = (unsigned)((sel + ((grp >> 1) << 3)) * 144 + ((grp & 1) << 4));
    unsigned vRow = (unsigned)((sel + ((grp & 1) << 3)) * 144 + ((grp >> 1) << 4));

    int r_0 = row0 + warp * 16 + gid;
    int r_1 = r_0 + 8;

    float m0 = -1e30f, m1 = -1e30f, l0 = 0.f, l1 = 0.f;
    float o[8][4];
    #pragma unroll
    for (int i = 0; i < 8; i++)
        #pragma unroll
        for (int j = 0; j < 4; j++) o[i][j] = 0.f;

    int ntile = causal ? (row0 + FBQ) / FBK : (Tk + FBK - 1) / FBK;

    for (int t = 0; t < ntile; t++) {
        int kvb = t * FBK;
        __syncthreads();
        #pragma unroll
        for (int it = 0; it < 2; it++) {
            int idx = it * 256 + tid;
            int r = idx >> 3, c8 = (idx & 7) * 8;
            int gr = kvb + r;
            uint4 kv = make_uint4(0u,0u,0u,0u), vv = make_uint4(0u,0u,0u,0u);
            if (gr < Tk) {
                kv = *(const uint4*)(Kp + (long)gr * ldk + c8);
                vv = *(const uint4*)(Vp + (long)gr * ldk + c8);
            }
            *(uint4*)&Ks[r * FST + c8 / 2] = kv;
            *(uint4*)&Vs[r * FST + c8 / 2] = vv;
        }
        __syncthreads();

        float sacc[8][4];
        #pragma unroll
        for (int i = 0; i < 8; i++)
            #pragma unroll
            for (int j = 0; j < 4; j++) sacc[i][j] = 0.f;

        #pragma unroll
        for (int ks = 0; ks < 4; ks++) {
            unsigned qa0, qa1, qa2, qa3;
            LDM_X4(qa0, qa1, qa2, qa3, qAddr + ks * 32);
            #pragma unroll
            for (int np = 0; np < 4; np++) {
                unsigned b0, b1, b2, b3;
                LDM_X4(b0, b1, b2, b3, kBase + np * (16 * 144) + kRow + ks * 32);
                mma_f16(sacc[2*np],     qa0, qa1, qa2, qa3, b0, b1);
                mma_f16(sacc[2*np + 1], qa0, qa1, qa2, qa3, b2, b3);
            }
        }

        bool domask = (causal && (kvb + FBK - 1 > row0)) || (kvb + FBK > Tk);
        if (domask) {
            #pragma unroll
            for (int ni = 0; ni < 8; ni++) {
                #pragma unroll
                for (int s = 0; s < 4; s++) {
                    int col = kvb + ni * 8 + tg * 2 + (s & 1);
                    int r = (s < 2) ? r_0 : r_1;
                    bool ok = (col < Tk) && (!causal || col <= r);
                    if (!ok) sacc[ni][s] = -1e30f;
                }
            }
        }

        float tm0 = -1e30f, tm1 = -1e30f;
        #pragma unroll
        for (int ni = 0; ni < 8; ni++) {
            tm0 = fmaxf(tm0, fmaxf(sacc[ni][0], sacc[ni][1]));
            tm1 = fmaxf(tm1, fmaxf(sacc[ni][2], sacc[ni][3]));
        }
        tm0 = fmaxf(tm0, __shfl_xor_sync(0xffffffffu, tm0, 1));
        tm0 = fmaxf(tm0, __shfl_xor_sync(0xffffffffu, tm0, 2));
        tm1 = fmaxf(tm1, __shfl_xor_sync(0xffffffffu, tm1, 1));
        tm1 = fmaxf(tm1, __shfl_xor_sync(0xffffffffu, tm1, 2));

        float nm0 = fmaxf(m0, tm0), nm1 = fmaxf(m1, tm1);
        float sc0 = __expf(m0 - nm0), sc1 = __expf(m1 - nm1);
        m0 = nm0; m1 = nm1;

        float rs0 = 0.f, rs1 = 0.f;
        #pragma unroll
        for (int ni = 0; ni < 8; ni++) {
            sacc[ni][0] = __expf(sacc[ni][0] - nm0); rs0 += sacc[ni][0];
            sacc[ni][1] = __expf(sacc[ni][1] - nm0); rs0 += sacc[ni][1];
            sacc[ni][2] = __expf(sacc[ni][2] - nm1); rs1 += sacc[ni][2];
            sacc[ni][3] = __expf(sacc[ni][3] - nm1); rs1 += sacc[ni][3];
        }
        rs0 += __shfl_xor_sync(0xffffffffu, rs0, 1);
        rs0 += __shfl_xor_sync(0xffffffffu, rs0, 2);
        rs1 += __shfl_xor_sync(0xffffffffu, rs1, 1);
        rs1 += __shfl_xor_sync(0xffffffffu, rs1, 2);
        l0 = l0 * sc0 + rs0;
        l1 = l1 * sc1 + rs1;

        #pragma unroll
        for (int ni = 0; ni < 8; ni++) {
            o[ni][0] *= sc0; o[ni][1] *= sc0;
            o[ni][2] *= sc1; o[ni][3] *= sc1;
        }

        #pragma unroll
        for (int ks = 0; ks < 4; ks++) {
            unsigned a0 = hpack(sacc[2*ks][0],     sacc[2*ks][1]);
            unsigned a1 = hpack(sacc[2*ks][2],     sacc[2*ks][3]);
            unsigned a2 = hpack(sacc[2*ks + 1][0], sacc[2*ks + 1][1]);
            unsigned a3 = hpack(sacc[2*ks + 1][2], sacc[2*ks + 1][3]);
            #pragma unroll
            for (int np = 0; np < 4; np++) {
                unsigned b0, b1, b2, b3;
                LDM_X4T(b0, b1, b2, b3, vBase + ks * (16 * 144) + vRow + np * 32);
                mma_f16(o[2*np],     a0, a1, a2, a3, b0, b1);
                mma_f16(o[2*np + 1], a0, a1, a2, a3, b2, b3);
            }
        }
    }

    float inv0 = 1.0f / l0, inv1 = 1.0f / l1;
    #pragma unroll
    for (int nj = 0; nj < 8; nj++) {
        int c = nj * 8 + tg * 2;
        if (r_0 < Tq) {
            __half2 w = __floats2half2_rn(o[nj][0] * inv0, o[nj][1] * inv0);
            *(__half2*)(Op + (long)r_0 * ldo + c) = w;
        }
        if (r_1 < Tq) {
            __half2 w = __floats2half2_rn(o[nj][2] * inv1, o[nj][3] * inv1);
            *(__half2*)(Op + (long)r_1 * ldo + c) = w;
        }
    }
}

// ======== fp16 cp.async 4-stage GEMM, 128x256 block, ldmatrix fragments ========
// A half [M][K] row-major; Bt half [N][K] (pre-transposed weights).
// smem rows: 16 data words + 4 pad (80 B stride -> conflict-free ldmatrix phases).
// EPI bits: 1=+bias, 2=+Res(float), 4=GELU, 8=half output
#define BM 128
#define BN 256
#define BKH 32                       // K halves per stage
#define NSTG 4
#define HST 20                       // words per smem row
#define AW (BM * HST)                // 2560 words
#define BW (BN * HST)                // 5120 words
#define STG (AW + BW)                // 7680 words
#define GSMEM (STG * NSTG * 4)       // 122880 B

template<int EPI>
__global__ __launch_bounds__(256, 1) void hgemm(
    const __half* __restrict__ A, const __half* __restrict__ Bt,
    const float* __restrict__ bias, const float* __restrict__ Res,
    float* __restrict__ C,
    int M, int N, int K, int lda, int ldbk)
{
    extern __shared__ unsigned dsm[];
    unsigned sbase = (unsigned)__cvta_generic_to_shared(dsm);

    int row0 = blockIdx.y * BM, col0 = blockIdx.x * BN;
    int tid  = threadIdx.x;
    int lane = tid & 31, warp = tid >> 5;
    int wm = (warp & 1) * 64;
    int wn = (warp >> 1) * 64;
    int gid = lane >> 2, tg = lane & 3;

    int ar = tid >> 1;                    // A row 0..127
    int ha = (tid & 1) * 16;              // A half-offset {0,16}

    auto load_stage = [&](int s, int k0) {
        unsigned abase = sbase + (s * STG) * 4;
        unsigned bbase = sbase + (s * STG + AW) * 4;
        const __half* asrc = A + (long)(row0 + ar) * lda + k0 + ha;
        bool av = (row0 + ar) < M;
        unsigned adst = abase + (ar * HST + ha / 2) * 4;
        cpa16(adst, asrc, av);
        cpa16(adst + 16, asrc + 8, av);
        const __half* bsrc = Bt + (long)(col0 + tid) * ldbk + k0;
        unsigned bdst = bbase + (tid * HST) * 4;
        #pragma unroll
        for (int i = 0; i < 4; i++)
            cpa16u(bdst + i * 16, bsrc + i * 8);
    };

    // ldmatrix per-thread addresses (within a stage)
    // A groups: (m0-7,k0)(m8-15,k0)(m0-7,k8)(m8-15,k8) -> a0,a1,a2,a3
    unsigned aOff = (unsigned)((wm + (lane & 15)) * (HST * 4) + ((lane >> 4) << 4));
    // B groups: (n0-7,k0)(n0-7,k8)(n8-15,k0)(n8-15,k8) -> b[ni][0],b[ni][1],b[ni+1][0],b[ni+1][1]
    unsigned bOff = (unsigned)(AW * 4 +
        (wn + (lane & 7) + ((lane >> 4) & 1) * 8) * (HST * 4) + (((lane >> 3) & 1) << 4));

    float acc[4][8][4];
    #pragma unroll
    for (int i = 0; i < 4; i++)
        #pragma unroll
        for (int j = 0; j < 8; j++)
            #pragma unroll
            for (int r = 0; r < 4; r++) acc[i][j][r] = 0.f;

    int ntiles = K / BKH;

    #pragma unroll
    for (int s = 0; s < NSTG - 1; s++) {
        if (s < ntiles) load_stage(s, s * BKH);
        cpa_commit();
    }

    for (int t = 0; t < ntiles; t++) {
        cpa_wait<NSTG - 2>();
        __syncthreads();

        int tn = t + NSTG - 1;
        if (tn < ntiles) load_stage(tn % NSTG, tn * BKH);
        cpa_commit();

        int buf = t % NSTG;
        unsigned stg = sbase + (unsigned)(buf * STG * 4);
        unsigned aA = stg + aOff;
        unsigned bA = stg + bOff;

        #pragma unroll
        for (int ks = 0; ks < 2; ks++) {
            unsigned kbyte = ks * 32;
            unsigned a[4][4], b[8][2];
            #pragma unroll
            for (int mi = 0; mi < 4; mi++)
                LDM_X4(a[mi][0], a[mi][1], a[mi][2], a[mi][3],
                       aA + mi * (16 * HST * 4) + kbyte);
            #pragma unroll
            for (int np = 0; np < 4; np++) {
                unsigned b0, b1, b2, b3;
                LDM_X4(b0, b1, b2, b3, bA + np * (16 * HST * 4) + kbyte);
                b[2*np][0] = b0;     b[2*np][1] = b1;
                b[2*np + 1][0] = b2; b[2*np + 1][1] = b3;
            }
            #pragma unroll
            for (int mi = 0; mi < 4; mi++)
                #pragma unroll
                for (int ni = 0; ni < 8; ni++)
                    mma_f16(acc[mi][ni], a[mi][0], a[mi][1], a[mi][2], a[mi][3],
                            b[ni][0], b[ni][1]);
        }
    }

    #pragma unroll
    for (int mi = 0; mi < 4; mi++) {
        #pragma unroll
        for (int rr = 0; rr < 2; rr++) {
            int r = row0 + wm + mi * 16 + gid + rr * 8;
            if (r >= M) continue;
            #pragma unroll
            for (int ni = 0; ni < 8; ni++) {
                int c = col0 + wn + ni * 8 + tg * 2;
                float v0 = acc[mi][ni][rr * 2 + 0];
                float v1 = acc[mi][ni][rr * 2 + 1];
                if (EPI & 1) { v0 += bias[c]; v1 += bias[c + 1]; }
                if (EPI & 4) {
                    v0 = 0.5f * v0 * (1.0f + erff(v0 * 0.70710678118654752f));
                    v1 = 0.5f * v1 * (1.0f + erff(v1 * 0.70710678118654752f));
                }
                if (EPI & 2) {
                    float2 rv = *(const float2*)(Res + (long)r * N + c);
                    v0 += rv.x; v1 += rv.y;
                }
                if (EPI & 8) {
                    *(__half2*)((__half*)C + (long)r * N + c) = __floats2half2_rn(v0, v1);
                } else {
                    *(float2*)(C + (long)r * N + c) = make_float2(v0, v1);
                }
            }
        }
    }
}

// ---------------- host side ----------------
static inline dim3 ggrid(int M, int N) {
    return dim3((unsigned)((N + BN - 1) / BN), (unsigned)((M + BM - 1) / BM), 1);
}

extern "C" void kernel_launch(void* const* d_in, const int* in_sizes, int n_in,
                              void* d_out, int out_size)
{
    const float* x        = (const float*)d_in[0];
    const float* cond     = (const float*)d_in[1];
    const float* Wqkv     = (const float*)d_in[2];
    const float* Wproj_sa = (const float*)d_in[3];
    const float* bproj_sa = (const float*)d_in[4];
    const float* g1       = (const float*)d_in[5];
    const float* b1       = (const float*)d_in[6];
    const float* Wq_ca    = (const float*)d_in[7];
    const float* Wkv_ca   = (const float*)d_in[8];
    const float* Wproj_ca = (const float*)d_in[9];
    const float* bproj_ca = (const float*)d_in[10];
    const float* g2       = (const float*)d_in[11];
    const float* b2       = (const float*)d_in[12];
    const float* Wff1     = (const float*)d_in[13];
    const float* bff1     = (const float*)d_in[14];
    const float* Wff2     = (const float*)d_in[15];
    const float* bff2     = (const float*)d_in[16];
    const float* g3       = (const float*)d_in[17];
    const float* b3       = (const float*)d_in[18];
    float* out            = (float*)d_out;

    __half *p_ln, *p_qkv, *p_attn, *p_qca, *p_kvca, *p_ff, *p_w;
    float *p_x1, *p_x2;
    cudaGetSymbolAddress((void**)&p_ln,   g_lnH);
    cudaGetSymbolAddress((void**)&p_qkv,  g_qkvH);
    cudaGetSymbolAddress((void**)&p_attn, g_attnH);
    cudaGetSymbolAddress((void**)&p_qca,  g_qcaH);
    cudaGetSymbolAddress((void**)&p_kvca, g_kvcaH);
    cudaGetSymbolAddress((void**)&p_ff,   g_ffH);
    cudaGetSymbolAddress((void**)&p_x1,   g_x1);
    cudaGetSymbolAddress((void**)&p_x2,   g_x2);
    cudaGetSymbolAddress((void**)&p_w,    g_wh);

    static int smem_set = 0;
    if (!smem_set) {
        cudaFuncSetAttribute(flash_kernel, cudaFuncAttributeMaxDynamicSharedMemorySize, FSMEM);
        cudaFuncSetAttribute(hgemm<8>,  cudaFuncAttributeMaxDynamicSharedMemorySize, GSMEM);
        cudaFuncSetAttribute(hgemm<3>,  cudaFuncAttributeMaxDynamicSharedMemorySize, GSMEM);
        cudaFuncSetAttribute(hgemm<13>, cudaFuncAttributeMaxDynamicSharedMemorySize, GSMEM);
        smem_set = 1;
    }

    const long T3D = (long)Tt * 3 * Dm;
    const long TD  = (long)Tt * Dm;
    const long KVb = (long)Cc * 2 * Dm;

    // 0) prep: transpose+convert weights, convert cond
    transpose_h<<<dim3(3*Dm/32, Dm/32), 256>>>(Wqkv,     p_w + OW_QKV,  Dm,  3*Dm);
    transpose_h<<<dim3(Dm/32,   Dm/32), 256>>>(Wproj_sa, p_w + OW_PSA,  Dm,  Dm);
    transpose_h<<<dim3(Dm/32,   Dm/32), 256>>>(Wq_ca,    p_w + OW_QCA,  Dm,  Dm);
    transpose_h<<<dim3(2*Dm/32, DC/32), 256>>>(Wkv_ca,   p_w + OW_KVCA, DC,  2*Dm);
    transpose_h<<<dim3(Dm/32,   Dm/32), 256>>>(Wproj_ca, p_w + OW_PCA,  Dm,  Dm);
    transpose_h<<<dim3(DFF/32,  Dm/32), 256>>>(Wff1,     p_w + OW_FF1,  Dm,  DFF);
    transpose_h<<<dim3(Dm/32,  DFF/32), 256>>>(Wff2,     p_w + OW_FF2,  DFF, Dm);
    conv_h<<<(SZ_COND + 255) / 256, 256>>>(cond, p_w + OW_COND, SZ_COND);

    // 1) ln1 = LN(x) -> half
    ln_kernel<<<MX, 256>>>(x, g1, b1, p_ln);

    // 2) qkv = ln1 @ Wqkv  (half out)
    hgemm<8><<<ggrid(MX, 3*Dm), 256, GSMEM>>>(
        p_ln, p_w + OW_QKV, nullptr, nullptr, (float*)p_qkv, MX, 3*Dm, Dm, Dm, Dm);

    // 3) fused causal self-attention -> g_attnH
    flash_kernel<<<dim3(1, Tt/FBQ, Bb*Hh), 256, FSMEM>>>(
        p_qkv, p_qkv + Dm, p_qkv + 2*Dm, p_attn,
        Tt, Tt, 3*Dm, 3*Dm, Dm,
        T3D, DH, T3D, DH, TD, DH, Hh, 1);

    // 4) x1 = x + attn @ Wproj_sa + b  (float out)
    hgemm<3><<<ggrid(MX, Dm), 256, GSMEM>>>(
        p_attn, p_w + OW_PSA, bproj_sa, x, p_x1, MX, Dm, Dm, Dm, Dm);

    // 5) ln2 = LN(x1) -> half
    ln_kernel<<<MX, 256>>>(p_x1, g2, b2, p_ln);

    // 6) q_ca = ln2 @ Wq_ca  (half out)
    hgemm<8><<<ggrid(MX, Dm), 256, GSMEM>>>(
        p_ln, p_w + OW_QCA, nullptr, nullptr, (float*)p_qca, MX, Dm, Dm, Dm, Dm);

    // 7) kv_ca = cond_h @ Wkv_ca  (half out)
    hgemm<8><<<ggrid(Bb*Cc, 2*Dm), 256, GSMEM>>>(
        p_w + OW_COND, p_w + OW_KVCA, nullptr, nullptr, (float*)p_kvca,
        Bb*Cc, 2*Dm, DC, DC, DC);

    // 8) fused cross-attention -> g_attnH
    flash_kernel<<<dim3(1, Tt/FBQ, Bb*Hh), 256, FSMEM>>>(
        p_qca, p_kvca, p_kvca + Dm, p_attn,
        Tt, Cc, Dm, 2*Dm, Dm,
        TD, DH, KVb, DH, TD, DH, Hh, 0);

    // 9) x2 = x1 + ca_out @ Wproj_ca + b  (float out)
    hgemm<3><<<ggrid(MX, Dm), 256, GSMEM>>>(
        p_attn, p_w + OW_PCA, bproj_ca, p_x1, p_x2, MX, Dm, Dm, Dm, Dm);

    // 10) ln3 = LN(x2) -> half
    ln_kernel<<<MX, 256>>>(p_x2, g3, b3, p_ln);

    // 11) ffh = gelu(ln3 @ Wff1 + bff1)  (half out)
    hgemm<13><<<ggrid(MX, DFF), 256, GSMEM>>>(
        p_ln, p_w + OW_FF1, bff1, nullptr, (float*)p_ff, MX, DFF, Dm, Dm, Dm);

    // 12) out = x2 + ffh @ Wff2 + bff2  (float out)
    hgemm<3><<<ggrid(MX, Dm), 256, GSMEM>>>(
        p_ff, p_w + OW_FF2, bff2, p_x2, out, MX, Dm, DFF, DFF, DFF);
}

// round 14
// speedup vs baseline: 1.8104x; 1.0308x over previous
#include <cuda_runtime.h>
#include <cuda_fp16.h>
#include <math.h>

// ---------------- problem constants ----------------
#define Dm   1024
#define Hh   16
#define DH   64
#define DFF  4096
#define DC   768
#define Tt   2048
#define Bb   2
#define Cc   77
#define MX   4096          // Bb*Tt rows of x

// ---------------- scratch (static device arrays; no allocs) ----------------
__device__ __half g_lnH  [(size_t)MX * Dm];
__device__ __half g_qkvH [(size_t)MX * 3 * Dm];
__device__ __half g_attnH[(size_t)MX * Dm];
__device__ __half g_qcaH [(size_t)MX * Dm];
__device__ __half g_kvcaH[(size_t)Bb * Cc * 2 * Dm];
__device__ __half g_ffH  [(size_t)MX * DFF];
__device__ float  g_x1   [(size_t)MX * Dm];
__device__ float  g_x2   [(size_t)MX * Dm];
__device__ __half g_wh   [(size_t)16400000];   // transposed half weights + cond

// weight-scratch offsets (elements)
#define SZ_QKV  (Dm*3*Dm)
#define SZ_PSA  (Dm*Dm)
#define SZ_QCA  (Dm*Dm)
#define SZ_KVCA (DC*2*Dm)
#define SZ_PCA  (Dm*Dm)
#define SZ_FF1  (Dm*DFF)
#define SZ_FF2  (DFF*Dm)
#define SZ_COND (Bb*Cc*DC)
#define OW_QKV   0
#define OW_PSA   (OW_QKV + SZ_QKV)
#define OW_QCA   (OW_PSA + SZ_PSA)
#define OW_KVCA  (OW_QCA + SZ_QCA)
#define OW_PCA   (OW_KVCA + SZ_KVCA)
#define OW_FF1   (OW_PCA + SZ_PCA)
#define OW_FF2   (OW_FF1 + SZ_FF1)
#define OW_COND  (OW_FF2 + SZ_FF2)

// prep tile ranges (32x32 transpose tiles per matrix)
#define TQKV  3072
#define TPSA  (TQKV + 1024)
#define TQCA  (TPSA + 1024)
#define TKVCA (TQCA + 1536)
#define TPCA  (TKVCA + 1024)
#define TFF1  (TPCA + 4096)
#define TFF2  (TFF1 + 4096)
#define TCOND (TFF2 + (SZ_COND / 256))    // 462 conv blocks
// grid = TCOND

// ---------------- helpers ----------------
__device__ __forceinline__ unsigned hpack(float a, float b) {
    __half2 h = __floats2half2_rn(a, b);
    return *(unsigned*)&h;
}

__device__ __forceinline__ void mma_f16(float c[4],
    unsigned a0, unsigned a1, unsigned a2, unsigned a3,
    unsigned b0, unsigned b1)
{
    asm volatile(
        "mma.sync.aligned.m16n8k16.row.col.f32.f16.f16.f32 "
        "{%0,%1,%2,%3}, {%4,%5,%6,%7}, {%8,%9}, {%0,%1,%2,%3};\n"
        : "+f"(c[0]), "+f"(c[1]), "+f"(c[2]), "+f"(c[3])
        : "r"(a0), "r"(a1), "r"(a2), "r"(a3), "r"(b0), "r"(b1));
}

#define LDM_X4(r0,r1,r2,r3,addr) \
    asm volatile("ldmatrix.sync.aligned.m8n8.x4.shared.b16 {%0,%1,%2,%3}, [%4];" \
        : "=r"(r0),"=r"(r1),"=r"(r2),"=r"(r3) : "r"(addr))
#define LDM_X4T(r0,r1,r2,r3,addr) \
    asm volatile("ldmatrix.sync.aligned.m8n8.x4.trans.shared.b16 {%0,%1,%2,%3}, [%4];" \
        : "=r"(r0),"=r"(r1),"=r"(r2),"=r"(r3) : "r"(addr))

__device__ __forceinline__ void cpa16(unsigned dst, const void* src, bool pred) {
    int sz = pred ? 16 : 0;
    asm volatile("cp.async.cg.shared.global [%0], [%1], 16, %2;\n"
                 :: "r"(dst), "l"(src), "r"(sz));
}
__device__ __forceinline__ void cpa16u(unsigned dst, const void* src) {
    asm volatile("cp.async.cg.shared.global [%0], [%1], 16;\n"
                 :: "r"(dst), "l"(src));
}
__device__ __forceinline__ void cpa_commit() {
    asm volatile("cp.async.commit_group;\n");
}
template<int N>
__device__ __forceinline__ void cpa_wait() {
    asm volatile("cp.async.wait_group %0;\n" :: "n"(N));
}

// ---------------- merged prep: all weight transposes + cond convert ----------------
__global__ __launch_bounds__(256) void prep_all(
    const float* __restrict__ wqkv, const float* __restrict__ wpsa,
    const float* __restrict__ wqca, const float* __restrict__ wkvca,
    const float* __restrict__ wpca, const float* __restrict__ wff1,
    const float* __restrict__ wff2, const float* __restrict__ cond,
    __half* __restrict__ dst)
{
    int b = blockIdx.x;
    int tid = threadIdx.x;

    if (b >= TFF2) {               // cond convert: 4 floats per thread
        int i = ((b - TFF2) * 256 + tid) * 1;
        // SZ_COND/256 blocks of 256 elements
        int base = (b - TFF2) * 256 + tid;
        if (base < SZ_COND) dst[OW_COND + base] = __float2half(cond[base]);
        return;
    }

    const float* src; __half* d; int K, N; int tile;
    if      (b < TQKV)  { src = wqkv;  d = dst + OW_QKV;  K = Dm;  N = 3*Dm; tile = b; }
    else if (b < TPSA)  { src = wpsa;  d = dst + OW_PSA;  K = Dm;  N = Dm;   tile = b - TQKV; }
    else if (b < TQCA)  { src = wqca;  d = dst + OW_QCA;  K = Dm;  N = Dm;   tile = b - TPSA; }
    else if (b < TKVCA) { src = wkvca; d = dst + OW_KVCA; K = DC;  N = 2*Dm; tile = b - TQCA; }
    else if (b < TPCA)  { src = wpca;  d = dst + OW_PCA;  K = Dm;  N = Dm;   tile = b - TKVCA; }
    else if (b < TFF1)  { src = wff1;  d = dst + OW_FF1;  K = Dm;  N = DFF;  tile = b - TPCA; }
    else                { src = wff2;  d = dst + OW_FF2;  K = DFF; N = Dm;   tile = b - TFF1; }

    int tX = N >> 5;
    int bx = (tile % tX) * 32, by = (tile / tX) * 32;
    __shared__ float t[32][33];
    int tx = tid & 31, ty = tid >> 5;       // 32 x 8
    #pragma unroll
    for (int j = 0; j < 32; j += 8)
        t[ty + j][tx] = src[(long)(by + ty + j) * N + bx + tx];
    __syncthreads();
    #pragma unroll
    for (int j = 0; j < 32; j += 8)
        d[(long)(bx + ty + j) * K + by + tx] = __float2half(t[tx][ty + j]);
}

// ---------------- reductions ----------------
__device__ __forceinline__ float block_sum(float v, float* sh) {
    #pragma unroll
    for (int o = 16; o > 0; o >>= 1) v += __shfl_xor_sync(0xffffffffu, v, o);
    int w = threadIdx.x >> 5;
    if ((threadIdx.x & 31) == 0) sh[w] = v;
    __syncthreads();
    if (threadIdx.x < 32) {
        float t = (threadIdx.x < 8) ? sh[threadIdx.x] : 0.f;
        #pragma unroll
        for (int o = 4; o > 0; o >>= 1) t += __shfl_xor_sync(0xffffffffu, t, o);
        if (threadIdx.x == 0) sh[0] = t;
    }
    __syncthreads();
    float r = sh[0];
    __syncthreads();
    return r;
}

// ---------------- LayerNorm (half output) ----------------
__global__ __launch_bounds__(256) void ln_kernel(
    const float* __restrict__ x, const float* __restrict__ g,
    const float* __restrict__ b, __half* __restrict__ out)
{
    __shared__ float sh[8];
    long row = blockIdx.x;
    const float4* xr = (const float4*)(x + row * Dm);
    int tid = threadIdx.x;
    float4 v = xr[tid];
    float s = v.x + v.y + v.z + v.w;
    s = block_sum(s, sh);
    float mean = s * (1.0f / Dm);
    float dx = v.x - mean, dy = v.y - mean, dz = v.z - mean, dw = v.w - mean;
    float s2 = dx*dx + dy*dy + dz*dz + dw*dw;
    s2 = block_sum(s2, sh);
    float rstd = rsqrtf(s2 * (1.0f / Dm) + 1e-5f);
    float4 gg = ((const float4*)g)[tid];
    float4 bbv = ((const float4*)b)[tid];
    uint2 u;
    u.x = hpack(dx * rstd * gg.x + bbv.x, dy * rstd * gg.y + bbv.y);
    u.y = hpack(dz * rstd * gg.z + bbv.z, dw * rstd * gg.w + bbv.w);
    ((uint2*)(out + row * Dm))[tid] = u;
}

// ================= fused flash attention (fp16, 128-row KV macro-tiles) =============
#define FBQ 128
#define FBK2 128                                  // KV rows per sync window
#define FST 36                                    // words per row
#define FSMEM ((FBQ + FBK2 + FBK2) * FST * 4)     // 55296 B

__global__ __launch_bounds__(256, 2) void flash_kernel(
    const __half* __restrict__ Qp, const __half* __restrict__ Kp,
    const __half* __restrict__ Vp, __half* __restrict__ Op,
    int Tq, int Tk, int ldq, int ldk, int ldo,
    long sQb, long sQh, long sKb, long sKh, long sOb, long sOh,
    int Hn, int causal)
{
    extern __shared__ unsigned fsm[];
    unsigned* Qs = fsm;
    unsigned* Ks = fsm + FBQ * FST;
    unsigned* Vs = Ks + FBK2 * FST;
    unsigned sbase = (unsigned)__cvta_generic_to_shared(fsm);

    int z = blockIdx.z, zb = z / Hn, zh = z - zb * Hn;
    Qp += zb * sQb + zh * sQh;
    Kp += zb * sKb + zh * sKh;
    Vp += zb * sKb + zh * sKh;
    Op += zb * sOb + zh * sOh;

    int tid = threadIdx.x, lane = tid & 31, warp = tid >> 5;
    int gid = lane >> 2, tg = lane & 3;
    int sel = lane & 7, grp = lane >> 3;
    int yb = causal ? ((int)gridDim.y - 1 - (int)blockIdx.y) : (int)blockIdx.y;
    int row0 = yb * FBQ;
    int wrmax = row0 + warp * 16 + 15;   // last q row owned by this warp

    const __half2 scale2 = __half2half2(__float2half(0.125f));

    // ---- Q tile ----
    #pragma unroll
    for (int it = 0; it < 4; it++) {
        int idx = it * 256 + tid;
        int r = idx >> 3, c8 = (idx & 7) * 8;
        int gr = row0 + r;
        uint4 v = make_uint4(0u, 0u, 0u, 0u);
        if (gr < Tq) v = *(const uint4*)(Qp + (long)gr * ldq + c8);
        __half2* h = (__half2*)&v;
        h[0] = __hmul2(h[0], scale2); h[1] = __hmul2(h[1], scale2);
        h[2] = __hmul2(h[2], scale2); h[3] = __hmul2(h[3], scale2);
        *(uint4*)&Qs[r * FST + c8 / 2] = v;
    }

    unsigned qAddr = sbase + (unsigned)((warp * 16 + sel + ((grp & 1) << 3)) * 144
                                        + ((grp >> 1) << 4));
    unsigned kBase = sbase + FBQ * 144;
    unsigned vBase = kBase + FBK2 * 144;
    unsigned kRow = (unsigned)((sel + ((grp >> 1) << 3)) * 144 + ((grp & 1) << 4));
    unsigned vRow = (unsigned)((sel + ((grp & 1) << 3)) * 144 + ((grp >> 1) << 4));

    int r_0 = row0 + warp * 16 + gid;
    int r_1 = r_0 + 8;

    float m0 = -1e30f, m1 = -1e30f, l0 = 0.f, l1 = 0.f;
    float o[8][4];
    #pragma unroll
    for (int i = 0; i < 8; i++)
        #pragma unroll
        for (int j = 0; j < 4; j++) o[i][j] = 0.f;

    int ntile = causal ? (row0 + FBQ + FBK2 - 1) / FBK2 : (Tk + FBK2 - 1) / FBK2;

    for (int t = 0; t < ntile; t++) {
        int tb = t * FBK2;
        __syncthreads();
        // ---- load 128 K rows + 128 V rows ----
        #pragma unroll
        for (int it = 0; it < 4; it++) {
            int idx = it * 256 + tid;                 // 1024 x 16B
            int r = idx >> 3, c8 = (idx & 7) * 8;
            int gr = tb + r;
            uint4 kv = make_uint4(0u,0u,0u,0u), vv = make_uint4(0u,0u,0u,0u);
            if (gr < Tk) {
                kv = *(const uint4*)(Kp + (long)gr * ldk + c8);
                vv = *(const uint4*)(Vp + (long)gr * ldk + c8);
            }
            *(uint4*)&Ks[r * FST + c8 / 2] = kv;
            *(uint4*)&Vs[r * FST + c8 / 2] = vv;
        }
        __syncthreads();

        #pragma unroll
        for (int sub = 0; sub < 2; sub++) {
            int kvb = tb + sub * 64;
            if (causal && kvb > wrmax) continue;          // warp-uniform skip
            if (!causal && kvb >= Tk) continue;
            unsigned kSub = kBase + (unsigned)(sub * 64 * 144);
            unsigned vSub = vBase + (unsigned)(sub * 64 * 144);

            // ---- S = Q @ K^T ----
            float sacc[8][4];
            #pragma unroll
            for (int i = 0; i < 8; i++)
                #pragma unroll
                for (int j = 0; j < 4; j++) sacc[i][j] = 0.f;

            #pragma unroll
            for (int ks = 0; ks < 4; ks++) {
                unsigned qa0, qa1, qa2, qa3;
                LDM_X4(qa0, qa1, qa2, qa3, qAddr + ks * 32);
                #pragma unroll
                for (int np = 0; np < 4; np++) {
                    unsigned b0, b1, b2, b3;
                    LDM_X4(b0, b1, b2, b3, kSub + np * (16 * 144) + kRow + ks * 32);
                    mma_f16(sacc[2*np],     qa0, qa1, qa2, qa3, b0, b1);
                    mma_f16(sacc[2*np + 1], qa0, qa1, qa2, qa3, b2, b3);
                }
            }

            bool domask = (causal && (kvb + 63 > row0)) || (kvb + 64 > Tk);
            if (domask) {
                #pragma unroll
                for (int ni = 0; ni < 8; ni++) {
                    #pragma unroll
                    for (int s = 0; s < 4; s++) {
                        int col = kvb + ni * 8 + tg * 2 + (s & 1);
                        int r = (s < 2) ? r_0 : r_1;
                        bool ok = (col < Tk) && (!causal || col <= r);
                        if (!ok) sacc[ni][s] = -1e30f;
                    }
                }
            }

            // ---- online softmax (fp32) ----
            float tm0 = -1e30f, tm1 = -1e30f;
            #pragma unroll
            for (int ni = 0; ni < 8; ni++) {
                tm0 = fmaxf(tm0, fmaxf(sacc[ni][0], sacc[ni][1]));
                tm1 = fmaxf(tm1, fmaxf(sacc[ni][2], sacc[ni][3]));
            }
            tm0 = fmaxf(tm0, __shfl_xor_sync(0xffffffffu, tm0, 1));
            tm0 = fmaxf(tm0, __shfl_xor_sync(0xffffffffu, tm0, 2));
            tm1 = fmaxf(tm1, __shfl_xor_sync(0xffffffffu, tm1, 1));
            tm1 = fmaxf(tm1, __shfl_xor_sync(0xffffffffu, tm1, 2));

            float nm0 = fmaxf(m0, tm0), nm1 = fmaxf(m1, tm1);
            float sc0 = __expf(m0 - nm0), sc1 = __expf(m1 - nm1);
            m0 = nm0; m1 = nm1;

            float rs0 = 0.f, rs1 = 0.f;
            #pragma unroll
            for (int ni = 0; ni < 8; ni++) {
                sacc[ni][0] = __expf(sacc[ni][0] - nm0); rs0 += sacc[ni][0];
                sacc[ni][1] = __expf(sacc[ni][1] - nm0); rs0 += sacc[ni][1];
                sacc[ni][2] = __expf(sacc[ni][2] - nm1); rs1 += sacc[ni][2];
                sacc[ni][3] = __expf(sacc[ni][3] - nm1); rs1 += sacc[ni][3];
            }
            rs0 += __shfl_xor_sync(0xffffffffu, rs0, 1);
            rs0 += __shfl_xor_sync(0xffffffffu, rs0, 2);
            rs1 += __shfl_xor_sync(0xffffffffu, rs1, 1);
            rs1 += __shfl_xor_sync(0xffffffffu, rs1, 2);
            l0 = l0 * sc0 + rs0;
            l1 = l1 * sc1 + rs1;

            #pragma unroll
            for (int ni = 0; ni < 8; ni++) {
                o[ni][0] *= sc0; o[ni][1] *= sc0;
                o[ni][2] *= sc1; o[ni][3] *= sc1;
            }

            // ---- O += P @ V ----
            #pragma unroll
            for (int ks = 0; ks < 4; ks++) {
                unsigned a0 = hpack(sacc[2*ks][0],     sacc[2*ks][1]);
                unsigned a1 = hpack(sacc[2*ks][2],     sacc[2*ks][3]);
                unsigned a2 = hpack(sacc[2*ks + 1][0], sacc[2*ks + 1][1]);
                unsigned a3 = hpack(sacc[2*ks + 1][2], sacc[2*ks + 1][3]);
                #pragma unroll
                for (int np = 0; np < 4; np++) {
                    unsigned b0, b1, b2, b3;
                    LDM_X4T(b0, b1, b2, b3, vSub + ks * (16 * 144) + vRow + np * 32);
                    mma_f16(o[2*np],     a0, a1, a2, a3, b0, b1);
                    mma_f16(o[2*np + 1], a0, a1, a2, a3, b2, b3);
                }
            }
        }
    }

    float inv0 = 1.0f / l0, inv1 = 1.0f / l1;
    #pragma unroll
    for (int nj = 0; nj < 8; nj++) {
        int c = nj * 8 + tg * 2;
        if (r_0 < Tq) {
            __half2 w = __floats2half2_rn(o[nj][0] * inv0, o[nj][1] * inv0);
            *(__half2*)(Op + (long)r_0 * ldo + c) = w;
        }
        if (r_1 < Tq) {
            __half2 w = __floats2half2_rn(o[nj][2] * inv1, o[nj][3] * inv1);
            *(__half2*)(Op + (long)r_1 * ldo + c) = w;
        }
    }
}

// ======== fp16 cp.async 4-stage GEMM, 128x256 block, ldmatrix fragments ========
#define BM 128
#define BN 256
#define BKH 32                       // K halves per stage
#define NSTG 4
#define HST 20                       // words per smem row
#define AW (BM * HST)                // 2560 words
#define BW (BN * HST)                // 5120 words
#define STG (AW + BW)                // 7680 words
#define GSMEM (STG * NSTG * 4)       // 122880 B

template<int EPI>
__global__ __launch_bounds__(256, 1) void hgemm(
    const __half* __restrict__ A, const __half* __restrict__ Bt,
    const float* __restrict__ bias, const float* __restrict__ Res,
    float* __restrict__ C,
    int M, int N, int K, int lda, int ldbk)
{
    extern __shared__ unsigned dsm[];
    unsigned sbase = (unsigned)__cvta_generic_to_shared(dsm);

    int row0 = blockIdx.y * BM, col0 = blockIdx.x * BN;
    int tid  = threadIdx.x;
    int lane = tid & 31, warp = tid >> 5;
    int wm = (warp & 1) * 64;
    int wn = (warp >> 1) * 64;
    int gid = lane >> 2, tg = lane & 3;

    int ar = tid >> 1;
    int ha = (tid & 1) * 16;

    auto load_stage = [&](int s, int k0) {
        unsigned abase = sbase + (s * STG) * 4;
        unsigned bbase = sbase + (s * STG + AW) * 4;
        const __half* asrc = A + (long)(row0 + ar) * lda + k0 + ha;
        bool av = (row0 + ar) < M;
        unsigned adst = abase + (ar * HST + ha / 2) * 4;
        cpa16(adst, asrc, av);
        cpa16(adst + 16, asrc + 8, av);
        const __half* bsrc = Bt + (long)(col0 + tid) * ldbk + k0;
        unsigned bdst = bbase + (tid * HST) * 4;
        #pragma unroll
        for (int i = 0; i < 4; i++)
            cpa16u(bdst + i * 16, bsrc + i * 8);
    };

    unsigned aOff = (unsigned)((wm + (lane & 15)) * (HST * 4) + ((lane >> 4) << 4));
    unsigned bOff = (unsigned)(AW * 4 +
        (wn + (lane & 7) + ((lane >> 4) & 1) * 8) * (HST * 4) + (((lane >> 3) & 1) << 4));

    float acc[4][8][4];
    #pragma unroll
    for (int i = 0; i < 4; i++)
        #pragma unroll
        for (int j = 0; j < 8; j++)
            #pragma unroll
            for (int r = 0; r < 4; r++) acc[i][j][r] = 0.f;

    int ntiles = K / BKH;

    #pragma unroll
    for (int s = 0; s < NSTG - 1; s++) {
        if (s < ntiles) load_stage(s, s * BKH);
        cpa_commit();
    }

    for (int t = 0; t < ntiles; t++) {
        cpa_wait<NSTG - 2>();
        __syncthreads();

        int tn = t + NSTG - 1;
        if (tn < ntiles) load_stage(tn % NSTG, tn * BKH);
        cpa_commit();

        int buf = t % NSTG;
        unsigned stg = sbase + (unsigned)(buf * STG * 4);
        unsigned aA = stg + aOff;
        unsigned bA = stg + bOff;

        #pragma unroll
        for (int ks = 0; ks < 2; ks++) {
            unsigned kbyte = ks * 32;
            unsigned a[4][4], b[8][2];
            #pragma unroll
            for (int mi = 0; mi < 4; mi++)
                LDM_X4(a[mi][0], a[mi][1], a[mi][2], a[mi][3],
                       aA + mi * (16 * HST * 4) + kbyte);
            #pragma unroll
            for (int np = 0; np < 4; np++) {
                unsigned b0, b1, b2, b3;
                LDM_X4(b0, b1, b2, b3, bA + np * (16 * HST * 4) + kbyte);
                b[2*np][0] = b0;     b[2*np][1] = b1;
                b[2*np + 1][0] = b2; b[2*np + 1][1] = b3;
            }
            #pragma unroll
            for (int mi = 0; mi < 4; mi++)
                #pragma unroll
                for (int ni = 0; ni < 8; ni++)
                    mma_f16(acc[mi][ni], a[mi][0], a[mi][1], a[mi][2], a[mi][3],
                            b[ni][0], b[ni][1]);
        }
    }

    #pragma unroll
    for (int mi = 0; mi < 4; mi++) {
        #pragma unroll
        for (int rr = 0; rr < 2; rr++) {
            int r = row0 + wm + mi * 16 + gid + rr * 8;
            if (r >= M) continue;
            #pragma unroll
            for (int ni = 0; ni < 8; ni++) {
                int c = col0 + wn + ni * 8 + tg * 2;
                float v0 = acc[mi][ni][rr * 2 + 0];
                float v1 = acc[mi][ni][rr * 2 + 1];
                if (EPI & 1) { v0 += bias[c]; v1 += bias[c + 1]; }
                if (EPI & 4) {
                    v0 = 0.5f * v0 * (1.0f + erff(v0 * 0.70710678118654752f));
                    v1 = 0.5f * v1 * (1.0f + erff(v1 * 0.70710678118654752f));
                }
                if (EPI & 2) {
                    float2 rv = *(const float2*)(Res + (long)r * N + c);
                    v0 += rv.x; v1 += rv.y;
                }
                if (EPI & 8) {
                    *(__half2*)((__half*)C + (long)r * N + c) = __floats2half2_rn(v0, v1);
                } else {
                    *(float2*)(C + (long)r * N + c) = make_float2(v0, v1);
                }
            }
        }
    }
}

// ---------------- host side ----------------
static inline dim3 ggrid(int M, int N) {
    return dim3((unsigned)((N + BN - 1) / BN), (unsigned)((M + BM - 1) / BM), 1);
}

extern "C" void kernel_launch(void* const* d_in, const int* in_sizes, int n_in,
                              void* d_out, int out_size)
{
    const float* x        = (const float*)d_in[0];
    const float* cond     = (const float*)d_in[1];
    const float* Wqkv     = (const float*)d_in[2];
    const float* Wproj_sa = (const float*)d_in[3];
    const float* bproj_sa = (const float*)d_in[4];
    const float* g1       = (const float*)d_in[5];
    const float* b1       = (const float*)d_in[6];
    const float* Wq_ca    = (const float*)d_in[7];
    const float* Wkv_ca   = (const float*)d_in[8];
    const float* Wproj_ca = (const float*)d_in[9];
    const float* bproj_ca = (const float*)d_in[10];
    const float* g2       = (const float*)d_in[11];
    const float* b2       = (const float*)d_in[12];
    const float* Wff1     = (const float*)d_in[13];
    const float* bff1     = (const float*)d_in[14];
    const float* Wff2     = (const float*)d_in[15];
    const float* bff2     = (const float*)d_in[16];
    const float* g3       = (const float*)d_in[17];
    const float* b3       = (const float*)d_in[18];
    float* out            = (float*)d_out;

    __half *p_ln, *p_qkv, *p_attn, *p_qca, *p_kvca, *p_ff, *p_w;
    float *p_x1, *p_x2;
    cudaGetSymbolAddress((void**)&p_ln,   g_lnH);
    cudaGetSymbolAddress((void**)&p_qkv,  g_qkvH);
    cudaGetSymbolAddress((void**)&p_attn, g_attnH);
    cudaGetSymbolAddress((void**)&p_qca,  g_qcaH);
    cudaGetSymbolAddress((void**)&p_kvca, g_kvcaH);
    cudaGetSymbolAddress((void**)&p_ff,   g_ffH);
    cudaGetSymbolAddress((void**)&p_x1,   g_x1);
    cudaGetSymbolAddress((void**)&p_x2,   g_x2);
    cudaGetSymbolAddress((void**)&p_w,    g_wh);

    static int smem_set = 0;
    if (!smem_set) {
        cudaFuncSetAttribute(flash_kernel, cudaFuncAttributeMaxDynamicSharedMemorySize, FSMEM);
        cudaFuncSetAttribute(hgemm<8>,  cudaFuncAttributeMaxDynamicSharedMemorySize, GSMEM);
        cudaFuncSetAttribute(hgemm<3>,  cudaFuncAttributeMaxDynamicSharedMemorySize, GSMEM);
        cudaFuncSetAttribute(hgemm<13>, cudaFuncAttributeMaxDynamicSharedMemorySize, GSMEM);
        smem_set = 1;
    }

    const long T3D = (long)Tt * 3 * Dm;
    const long TD  = (long)Tt * Dm;
    const long KVb = (long)Cc * 2 * Dm;

    // 0) merged prep: all weight transposes + cond convert (one launch)
    prep_all<<<TCOND, 256>>>(Wqkv, Wproj_sa, Wq_ca, Wkv_ca,
                             Wproj_ca, Wff1, Wff2, cond, p_w);

    // 1) ln1 = LN(x) -> half
    ln_kernel<<<MX, 256>>>(x, g1, b1, p_ln);

    // 2) qkv = ln1 @ Wqkv  (half out)
    hgemm<8><<<ggrid(MX, 3*Dm), 256, GSMEM>>>(
        p_ln, p_w + OW_QKV, nullptr, nullptr, (float*)p_qkv, MX, 3*Dm, Dm, Dm, Dm);

    // 3) fused causal self-attention -> g_attnH
    flash_kernel<<<dim3(1, Tt/FBQ, Bb*Hh), 256, FSMEM>>>(
        p_qkv, p_qkv + Dm, p_qkv + 2*Dm, p_attn,
        Tt, Tt, 3*Dm, 3*Dm, Dm,
        T3D, DH, T3D, DH, TD, DH, Hh, 1);

    // 4) x1 = x + attn @ Wproj_sa + b  (float out)
    hgemm<3><<<ggrid(MX, Dm), 256, GSMEM>>>(
        p_attn, p_w + OW_PSA, bproj_sa, x, p_x1, MX, Dm, Dm, Dm, Dm);

    // 5) ln2 = LN(x1) -> half
    ln_kernel<<<MX, 256>>>(p_x1, g2, b2, p_ln);

    // 6) q_ca = ln2 @ Wq_ca  (half out)
    hgemm<8><<<ggrid(MX, Dm), 256, GSMEM>>>(
        p_ln, p_w + OW_QCA, nullptr, nullptr, (float*)p_qca, MX, Dm, Dm, Dm, Dm);

    // 7) kv_ca = cond_h @ Wkv_ca  (half out)
    hgemm<8><<<ggrid(Bb*Cc, 2*Dm), 256, GSMEM>>>(
        p_w + OW_COND, p_w + OW_KVCA, nullptr, nullptr, (float*)p_kvca,
        Bb*Cc, 2*Dm, DC, DC, DC);

    // 8) fused cross-attention -> g_attnH
    flash_kernel<<<dim3(1, Tt/FBQ, Bb*Hh), 256, FSMEM>>>(
        p_qca, p_kvca, p_kvca + Dm, p_attn,
        Tt, Cc, Dm, 2*Dm, Dm,
        TD, DH, KVb, DH, TD, DH, Hh, 0);

    // 9) x2 = x1 + ca_out @ Wproj_ca + b  (float out)
    hgemm<3><<<ggrid(MX, Dm), 256, GSMEM>>>(
        p_attn, p_w + OW_PCA, bproj_ca, p_x1, p_x2, MX, Dm, Dm, Dm, Dm);

    // 10) ln3 = LN(x2) -> half
    ln_kernel<<<MX, 256>>>(p_x2, g3, b3, p_ln);

    // 11) ffh = gelu(ln3 @ Wff1 + bff1)  (half out)
    hgemm<13><<<ggrid(MX, DFF), 256, GSMEM>>>(
        p_ln, p_w + OW_FF1, bff1, nullptr, (float*)p_ff, MX, DFF, Dm, Dm, Dm);

    // 12) out = x2 + ffh @ Wff2 + bff2  (float out)
    hgemm<3><<<ggrid(MX, Dm), 256, GSMEM>>>(
        p_ff, p_w + OW_FF2, bff2, p_x2, out, MX, Dm, DFF, DFF, DFF);
}

// round 15
// speedup vs baseline: 1.9088x; 1.0543x over previous
#include <cuda_runtime.h>
#include <cuda_fp16.h>
#include <math.h>

// ---------------- problem constants ----------------
#define Dm   1024
#define Hh   16
#define DH   64
#define DFF  4096
#define DC   768
#define Tt   2048
#define Bb   2
#define Cc   77
#define MX   4096          // Bb*Tt rows of x

// ---------------- scratch (static device arrays; no allocs) ----------------
__device__ __half g_lnH  [(size_t)MX * Dm];
__device__ __half g_qkvH [(size_t)MX * 3 * Dm];
__device__ __half g_attnH[(size_t)MX * Dm];
__device__ __half g_qcaH [(size_t)MX * Dm];
__device__ __half g_kvcaH[(size_t)Bb * Cc * 2 * Dm];
__device__ __half g_ffH  [(size_t)MX * DFF];
__device__ float  g_x1   [(size_t)MX * Dm];
__device__ float  g_x2   [(size_t)MX * Dm];
__device__ __half g_wh   [(size_t)16400000];   // transposed half weights + cond

// weight-scratch offsets (elements)
#define SZ_QKV  (Dm*3*Dm)
#define SZ_PSA  (Dm*Dm)
#define SZ_QCA  (Dm*Dm)
#define SZ_KVCA (DC*2*Dm)
#define SZ_PCA  (Dm*Dm)
#define SZ_FF1  (Dm*DFF)
#define SZ_FF2  (DFF*Dm)
#define SZ_COND (Bb*Cc*DC)
#define OW_QKV   0
#define OW_PSA   (OW_QKV + SZ_QKV)
#define OW_QCA   (OW_PSA + SZ_PSA)
#define OW_KVCA  (OW_QCA + SZ_QCA)
#define OW_PCA   (OW_KVCA + SZ_KVCA)
#define OW_FF1   (OW_PCA + SZ_PCA)
#define OW_FF2   (OW_FF1 + SZ_FF1)
#define OW_COND  (OW_FF2 + SZ_FF2)

// prep tile ranges (32x32 transpose tiles per matrix)
#define TQKV  3072
#define TPSA  (TQKV + 1024)
#define TQCA  (TPSA + 1024)
#define TKVCA (TQCA + 1536)
#define TPCA  (TKVCA + 1024)
#define TFF1  (TPCA + 4096)
#define TFF2  (TFF1 + 4096)
#define TCOND (TFF2 + (SZ_COND / 256))

// ---------------- helpers ----------------
__device__ __forceinline__ unsigned hpack(float a, float b) {
    __half2 h = __floats2half2_rn(a, b);
    return *(unsigned*)&h;
}

__device__ __forceinline__ void mma_f16(float c[4],
    unsigned a0, unsigned a1, unsigned a2, unsigned a3,
    unsigned b0, unsigned b1)
{
    asm volatile(
        "mma.sync.aligned.m16n8k16.row.col.f32.f16.f16.f32 "
        "{%0,%1,%2,%3}, {%4,%5,%6,%7}, {%8,%9}, {%0,%1,%2,%3};\n"
        : "+f"(c[0]), "+f"(c[1]), "+f"(c[2]), "+f"(c[3])
        : "r"(a0), "r"(a1), "r"(a2), "r"(a3), "r"(b0), "r"(b1));
}

#define LDM_X4(r0,r1,r2,r3,addr) \
    asm volatile("ldmatrix.sync.aligned.m8n8.x4.shared.b16 {%0,%1,%2,%3}, [%4];" \
        : "=r"(r0),"=r"(r1),"=r"(r2),"=r"(r3) : "r"(addr))
#define LDM_X4T(r0,r1,r2,r3,addr) \
    asm volatile("ldmatrix.sync.aligned.m8n8.x4.trans.shared.b16 {%0,%1,%2,%3}, [%4];" \
        : "=r"(r0),"=r"(r1),"=r"(r2),"=r"(r3) : "r"(addr))

__device__ __forceinline__ void cpa16(unsigned dst, const void* src, bool pred) {
    int sz = pred ? 16 : 0;
    asm volatile("cp.async.cg.shared.global [%0], [%1], 16, %2;\n"
                 :: "r"(dst), "l"(src), "r"(sz));
}
__device__ __forceinline__ void cpa16u(unsigned dst, const void* src) {
    asm volatile("cp.async.cg.shared.global [%0], [%1], 16;\n"
                 :: "r"(dst), "l"(src));
}
__device__ __forceinline__ void cpa_commit() {
    asm volatile("cp.async.commit_group;\n");
}
template<int N>
__device__ __forceinline__ void cpa_wait() {
    asm volatile("cp.async.wait_group %0;\n" :: "n"(N));
}

// ---------------- merged prep: all weight transposes + cond convert ----------------
__global__ __launch_bounds__(256) void prep_all(
    const float* __restrict__ wqkv, const float* __restrict__ wpsa,
    const float* __restrict__ wqca, const float* __restrict__ wkvca,
    const float* __restrict__ wpca, const float* __restrict__ wff1,
    const float* __restrict__ wff2, const float* __restrict__ cond,
    __half* __restrict__ dst)
{
    int b = blockIdx.x;
    int tid = threadIdx.x;

    if (b >= TFF2) {
        int base = (b - TFF2) * 256 + tid;
        if (base < SZ_COND) dst[OW_COND + base] = __float2half(cond[base]);
        return;
    }

    const float* src; __half* d; int K, N; int tile;
    if      (b < TQKV)  { src = wqkv;  d = dst + OW_QKV;  K = Dm;  N = 3*Dm; tile = b; }
    else if (b < TPSA)  { src = wpsa;  d = dst + OW_PSA;  K = Dm;  N = Dm;   tile = b - TQKV; }
    else if (b < TQCA)  { src = wqca;  d = dst + OW_QCA;  K = Dm;  N = Dm;   tile = b - TPSA; }
    else if (b < TKVCA) { src = wkvca; d = dst + OW_KVCA; K = DC;  N = 2*Dm; tile = b - TQCA; }
    else if (b < TPCA)  { src = wpca;  d = dst + OW_PCA;  K = Dm;  N = Dm;   tile = b - TKVCA; }
    else if (b < TFF1)  { src = wff1;  d = dst + OW_FF1;  K = Dm;  N = DFF;  tile = b - TPCA; }
    else                { src = wff2;  d = dst + OW_FF2;  K = DFF; N = Dm;   tile = b - TFF1; }

    int tX = N >> 5;
    int bx = (tile % tX) * 32, by = (tile / tX) * 32;
    __shared__ float t[32][33];
    int tx = tid & 31, ty = tid >> 5;
    #pragma unroll
    for (int j = 0; j < 32; j += 8)
        t[ty + j][tx] = src[(long)(by + ty + j) * N + bx + tx];
    __syncthreads();
    #pragma unroll
    for (int j = 0; j < 32; j += 8)
        d[(long)(bx + ty + j) * K + by + tx] = __float2half(t[tx][ty + j]);
}

// ---------------- reductions ----------------
__device__ __forceinline__ float block_sum(float v, float* sh) {
    #pragma unroll
    for (int o = 16; o > 0; o >>= 1) v += __shfl_xor_sync(0xffffffffu, v, o);
    int w = threadIdx.x >> 5;
    if ((threadIdx.x & 31) == 0) sh[w] = v;
    __syncthreads();
    if (threadIdx.x < 32) {
        float t = (threadIdx.x < 8) ? sh[threadIdx.x] : 0.f;
        #pragma unroll
        for (int o = 4; o > 0; o >>= 1) t += __shfl_xor_sync(0xffffffffu, t, o);
        if (threadIdx.x == 0) sh[0] = t;
    }
    __syncthreads();
    float r = sh[0];
    __syncthreads();
    return r;
}

// ---------------- LayerNorm (half output) ----------------
__global__ __launch_bounds__(256) void ln_kernel(
    const float* __restrict__ x, const float* __restrict__ g,
    const float* __restrict__ b, __half* __restrict__ out)
{
    __shared__ float sh[8];
    long row = blockIdx.x;
    const float4* xr = (const float4*)(x + row * Dm);
    int tid = threadIdx.x;
    float4 v = xr[tid];
    float s = v.x + v.y + v.z + v.w;
    s = block_sum(s, sh);
    float mean = s * (1.0f / Dm);
    float dx = v.x - mean, dy = v.y - mean, dz = v.z - mean, dw = v.w - mean;
    float s2 = dx*dx + dy*dy + dz*dz + dw*dw;
    s2 = block_sum(s2, sh);
    float rstd = rsqrtf(s2 * (1.0f / Dm) + 1e-5f);
    float4 gg = ((const float4*)g)[tid];
    float4 bbv = ((const float4*)b)[tid];
    uint2 u;
    u.x = hpack(dx * rstd * gg.x + bbv.x, dy * rstd * gg.y + bbv.y);
    u.y = hpack(dz * rstd * gg.z + bbv.z, dw * rstd * gg.w + bbv.w);
    ((uint2*)(out + row * Dm))[tid] = u;
}

// ================= fused flash attention (fp16, 128-row KV macro-tiles) =============
#define FBQ 128
#define FBK2 128
#define FST 36
#define FSMEM ((FBQ + FBK2 + FBK2) * FST * 4)     // 55296 B

__global__ __launch_bounds__(256, 2) void flash_kernel(
    const __half* __restrict__ Qp, const __half* __restrict__ Kp,
    const __half* __restrict__ Vp, __half* __restrict__ Op,
    int Tq, int Tk, int ldq, int ldk, int ldo,
    long sQb, long sQh, long sKb, long sKh, long sOb, long sOh,
    int Hn, int causal)
{
    extern __shared__ unsigned fsm[];
    unsigned* Qs = fsm;
    unsigned* Ks = fsm + FBQ * FST;
    unsigned* Vs = Ks + FBK2 * FST;
    unsigned sbase = (unsigned)__cvta_generic_to_shared(fsm);

    int z = blockIdx.z, zb = z / Hn, zh = z - zb * Hn;
    Qp += zb * sQb + zh * sQh;
    Kp += zb * sKb + zh * sKh;
    Vp += zb * sKb + zh * sKh;
    Op += zb * sOb + zh * sOh;

    int tid = threadIdx.x, lane = tid & 31, warp = tid >> 5;
    int gid = lane >> 2, tg = lane & 3;
    int sel = lane & 7, grp = lane >> 3;
    int yb = causal ? ((int)gridDim.y - 1 - (int)blockIdx.y) : (int)blockIdx.y;
    int row0 = yb * FBQ;
    int wrmax = row0 + warp * 16 + 15;

    const __half2 scale2 = __half2half2(__float2half(0.125f));

    #pragma unroll
    for (int it = 0; it < 4; it++) {
        int idx = it * 256 + tid;
        int r = idx >> 3, c8 = (idx & 7) * 8;
        int gr = row0 + r;
        uint4 v = make_uint4(0u, 0u, 0u, 0u);
        if (gr < Tq) v = *(const uint4*)(Qp + (long)gr * ldq + c8);
        __half2* h = (__half2*)&v;
        h[0] = __hmul2(h[0], scale2); h[1] = __hmul2(h[1], scale2);
        h[2] = __hmul2(h[2], scale2); h[3] = __hmul2(h[3], scale2);
        *(uint4*)&Qs[r * FST + c8 / 2] = v;
    }

    unsigned qAddr = sbase + (unsigned)((warp * 16 + sel + ((grp & 1) << 3)) * 144
                                        + ((grp >> 1) << 4));
    unsigned kBase = sbase + FBQ * 144;
    unsigned vBase = kBase + FBK2 * 144;
    unsigned kRow = (unsigned)((sel + ((grp >> 1) << 3)) * 144 + ((grp & 1) << 4));
    unsigned vRow = (unsigned)((sel + ((grp & 1) << 3)) * 144 + ((grp >> 1) << 4));

    int r_0 = row0 + warp * 16 + gid;
    int r_1 = r_0 + 8;

    float m0 = -1e30f, m1 = -1e30f, l0 = 0.f, l1 = 0.f;
    float o[8][4];
    #pragma unroll
    for (int i = 0; i < 8; i++)
        #pragma unroll
        for (int j = 0; j < 4; j++) o[i][j] = 0.f;

    int ntile = causal ? (row0 + FBQ + FBK2 - 1) / FBK2 : (Tk + FBK2 - 1) / FBK2;

    for (int t = 0; t < ntile; t++) {
        int tb = t * FBK2;
        __syncthreads();
        #pragma unroll
        for (int it = 0; it < 4; it++) {
            int idx = it * 256 + tid;
            int r = idx >> 3, c8 = (idx & 7) * 8;
            int gr = tb + r;
            uint4 kv = make_uint4(0u,0u,0u,0u), vv = make_uint4(0u,0u,0u,0u);
            if (gr < Tk) {
                kv = *(const uint4*)(Kp + (long)gr * ldk + c8);
                vv = *(const uint4*)(Vp + (long)gr * ldk + c8);
            }
            *(uint4*)&Ks[r * FST + c8 / 2] = kv;
            *(uint4*)&Vs[r * FST + c8 / 2] = vv;
        }
        __syncthreads();

        #pragma unroll
        for (int sub = 0; sub < 2; sub++) {
            int kvb = tb + sub * 64;
            if (causal && kvb > wrmax) continue;
            if (!causal && kvb >= Tk) continue;
            unsigned kSub = kBase + (unsigned)(sub * 64 * 144);
            unsigned vSub = vBase + (unsigned)(sub * 64 * 144);

            float sacc[8][4];
            #pragma unroll
            for (int i = 0; i < 8; i++)
                #pragma unroll
                for (int j = 0; j < 4; j++) sacc[i][j] = 0.f;

            #pragma unroll
            for (int ks = 0; ks < 4; ks++) {
                unsigned qa0, qa1, qa2, qa3;
                LDM_X4(qa0, qa1, qa2, qa3, qAddr + ks * 32);
                #pragma unroll
                for (int np = 0; np < 4; np++) {
                    unsigned b0, b1, b2, b3;
                    LDM_X4(b0, b1, b2, b3, kSub + np * (16 * 144) + kRow + ks * 32);
                    mma_f16(sacc[2*np],     qa0, qa1, qa2, qa3, b0, b1);
                    mma_f16(sacc[2*np + 1], qa0, qa1, qa2, qa3, b2, b3);
                }
            }

            bool domask = (causal && (kvb + 63 > row0)) || (kvb + 64 > Tk);
            if (domask) {
                #pragma unroll
                for (int ni = 0; ni < 8; ni++) {
                    #pragma unroll
                    for (int s = 0; s < 4; s++) {
                        int col = kvb + ni * 8 + tg * 2 + (s & 1);
                        int r = (s < 2) ? r_0 : r_1;
                        bool ok = (col < Tk) && (!causal || col <= r);
                        if (!ok) sacc[ni][s] = -1e30f;
                    }
                }
            }

            float tm0 = -1e30f, tm1 = -1e30f;
            #pragma unroll
            for (int ni = 0; ni < 8; ni++) {
                tm0 = fmaxf(tm0, fmaxf(sacc[ni][0], sacc[ni][1]));
                tm1 = fmaxf(tm1, fmaxf(sacc[ni][2], sacc[ni][3]));
            }
            tm0 = fmaxf(tm0, __shfl_xor_sync(0xffffffffu, tm0, 1));
            tm0 = fmaxf(tm0, __shfl_xor_sync(0xffffffffu, tm0, 2));
            tm1 = fmaxf(tm1, __shfl_xor_sync(0xffffffffu, tm1, 1));
            tm1 = fmaxf(tm1, __shfl_xor_sync(0xffffffffu, tm1, 2));

            float nm0 = fmaxf(m0, tm0), nm1 = fmaxf(m1, tm1);
            float sc0 = __expf(m0 - nm0), sc1 = __expf(m1 - nm1);
            m0 = nm0; m1 = nm1;

            float rs0 = 0.f, rs1 = 0.f;
            #pragma unroll
            for (int ni = 0; ni < 8; ni++) {
                sacc[ni][0] = __expf(sacc[ni][0] - nm0); rs0 += sacc[ni][0];
                sacc[ni][1] = __expf(sacc[ni][1] - nm0); rs0 += sacc[ni][1];
                sacc[ni][2] = __expf(sacc[ni][2] - nm1); rs1 += sacc[ni][2];
                sacc[ni][3] = __expf(sacc[ni][3] - nm1); rs1 += sacc[ni][3];
            }
            rs0 += __shfl_xor_sync(0xffffffffu, rs0, 1);
            rs0 += __shfl_xor_sync(0xffffffffu, rs0, 2);
            rs1 += __shfl_xor_sync(0xffffffffu, rs1, 1);
            rs1 += __shfl_xor_sync(0xffffffffu, rs1, 2);
            l0 = l0 * sc0 + rs0;
            l1 = l1 * sc1 + rs1;

            #pragma unroll
            for (int ni = 0; ni < 8; ni++) {
                o[ni][0] *= sc0; o[ni][1] *= sc0;
                o[ni][2] *= sc1; o[ni][3] *= sc1;
            }

            #pragma unroll
            for (int ks = 0; ks < 4; ks++) {
                unsigned a0 = hpack(sacc[2*ks][0],     sacc[2*ks][1]);
                unsigned a1 = hpack(sacc[2*ks][2],     sacc[2*ks][3]);
                unsigned a2 = hpack(sacc[2*ks + 1][0], sacc[2*ks + 1][1]);
                unsigned a3 = hpack(sacc[2*ks + 1][2], sacc[2*ks + 1][3]);
                #pragma unroll
                for (int np = 0; np < 4; np++) {
                    unsigned b0, b1, b2, b3;
                    LDM_X4T(b0, b1, b2, b3, vSub + ks * (16 * 144) + vRow + np * 32);
                    mma_f16(o[2*np],     a0, a1, a2, a3, b0, b1);
                    mma_f16(o[2*np + 1], a0, a1, a2, a3, b2, b3);
                }
            }
        }
    }

    float inv0 = 1.0f / l0, inv1 = 1.0f / l1;
    #pragma unroll
    for (int nj = 0; nj < 8; nj++) {
        int c = nj * 8 + tg * 2;
        if (r_0 < Tq) {
            __half2 w = __floats2half2_rn(o[nj][0] * inv0, o[nj][1] * inv0);
            *(__half2*)(Op + (long)r_0 * ldo + c) = w;
        }
        if (r_1 < Tq) {
            __half2 w = __floats2half2_rn(o[nj][2] * inv1, o[nj][3] * inv1);
            *(__half2*)(Op + (long)r_1 * ldo + c) = w;
        }
    }
}

// ======== fp16 cp.async 4-stage GEMM, 128x256 block (wide-N) ========
#define BM 128
#define BN 256
#define BKH 32
#define NSTG 4
#define HST 20
#define AW (BM * HST)
#define BW (BN * HST)
#define STG (AW + BW)
#define GSMEM (STG * NSTG * 4)

template<int EPI>
__global__ __launch_bounds__(256, 1) void hgemm(
    const __half* __restrict__ A, const __half* __restrict__ Bt,
    const float* __restrict__ bias, const float* __restrict__ Res,
    float* __restrict__ C,
    int M, int N, int K, int lda, int ldbk)
{
    extern __shared__ unsigned dsm[];
    unsigned sbase = (unsigned)__cvta_generic_to_shared(dsm);

    int row0 = blockIdx.y * BM, col0 = blockIdx.x * BN;
    int tid  = threadIdx.x;
    int lane = tid & 31, warp = tid >> 5;
    int wm = (warp & 1) * 64;
    int wn = (warp >> 1) * 64;
    int gid = lane >> 2, tg = lane & 3;

    int ar = tid >> 1;
    int ha = (tid & 1) * 16;

    auto load_stage = [&](int s, int k0) {
        unsigned abase = sbase + (s * STG) * 4;
        unsigned bbase = sbase + (s * STG + AW) * 4;
        const __half* asrc = A + (long)(row0 + ar) * lda + k0 + ha;
        bool av = (row0 + ar) < M;
        unsigned adst = abase + (ar * HST + ha / 2) * 4;
        cpa16(adst, asrc, av);
        cpa16(adst + 16, asrc + 8, av);
        const __half* bsrc = Bt + (long)(col0 + tid) * ldbk + k0;
        unsigned bdst = bbase + (tid * HST) * 4;
        #pragma unroll
        for (int i = 0; i < 4; i++)
            cpa16u(bdst + i * 16, bsrc + i * 8);
    };

    unsigned aOff = (unsigned)((wm + (lane & 15)) * (HST * 4) + ((lane >> 4) << 4));
    unsigned bOff = (unsigned)(AW * 4 +
        (wn + (lane & 7) + ((lane >> 4) & 1) * 8) * (HST * 4) + (((lane >> 3) & 1) << 4));

    float acc[4][8][4];
    #pragma unroll
    for (int i = 0; i < 4; i++)
        #pragma unroll
        for (int j = 0; j < 8; j++)
            #pragma unroll
            for (int r = 0; r < 4; r++) acc[i][j][r] = 0.f;

    int ntiles = K / BKH;

    #pragma unroll
    for (int s = 0; s < NSTG - 1; s++) {
        if (s < ntiles) load_stage(s, s * BKH);
        cpa_commit();
    }

    for (int t = 0; t < ntiles; t++) {
        cpa_wait<NSTG - 2>();
        __syncthreads();

        int tn = t + NSTG - 1;
        if (tn < ntiles) load_stage(tn % NSTG, tn * BKH);
        cpa_commit();

        int buf = t % NSTG;
        unsigned stg = sbase + (unsigned)(buf * STG * 4);
        unsigned aA = stg + aOff;
        unsigned bA = stg + bOff;

        #pragma unroll
        for (int ks = 0; ks < 2; ks++) {
            unsigned kbyte = ks * 32;
            unsigned a[4][4], b[8][2];
            #pragma unroll
            for (int mi = 0; mi < 4; mi++)
                LDM_X4(a[mi][0], a[mi][1], a[mi][2], a[mi][3],
                       aA + mi * (16 * HST * 4) + kbyte);
            #pragma unroll
            for (int np = 0; np < 4; np++) {
                unsigned b0, b1, b2, b3;
                LDM_X4(b0, b1, b2, b3, bA + np * (16 * HST * 4) + kbyte);
                b[2*np][0] = b0;     b[2*np][1] = b1;
                b[2*np + 1][0] = b2; b[2*np + 1][1] = b3;
            }
            #pragma unroll
            for (int mi = 0; mi < 4; mi++)
                #pragma unroll
                for (int ni = 0; ni < 8; ni++)
                    mma_f16(acc[mi][ni], a[mi][0], a[mi][1], a[mi][2], a[mi][3],
                            b[ni][0], b[ni][1]);
        }
    }

    #pragma unroll
    for (int mi = 0; mi < 4; mi++) {
        #pragma unroll
        for (int rr = 0; rr < 2; rr++) {
            int r = row0 + wm + mi * 16 + gid + rr * 8;
            if (r >= M) continue;
            #pragma unroll
            for (int ni = 0; ni < 8; ni++) {
                int c = col0 + wn + ni * 8 + tg * 2;
                float v0 = acc[mi][ni][rr * 2 + 0];
                float v1 = acc[mi][ni][rr * 2 + 1];
                if (EPI & 1) { v0 += bias[c]; v1 += bias[c + 1]; }
                if (EPI & 4) {
                    v0 = 0.5f * v0 * (1.0f + erff(v0 * 0.70710678118654752f));
                    v1 = 0.5f * v1 * (1.0f + erff(v1 * 0.70710678118654752f));
                }
                if (EPI & 2) {
                    float2 rv = *(const float2*)(Res + (long)r * N + c);
                    v0 += rv.x; v1 += rv.y;
                }
                if (EPI & 8) {
                    *(__half2*)((__half*)C + (long)r * N + c) = __floats2half2_rn(v0, v1);
                } else {
                    *(float2*)(C + (long)r * N + c) = make_float2(v0, v1);
                }
            }
        }
    }
}

// ======== fp16 GEMM, 128x128 block, 64x32 warp tile, 2 CTAs/SM (narrow-N) ========
#define QBN 128
#define QBW (QBN * HST)              // 2560 words
#define QSTG (AW + QBW)              // 5120 words
#define QSMEM (QSTG * NSTG * 4)      // 81920 B

template<int EPI>
__global__ __launch_bounds__(256, 2) void hgemm2(
    const __half* __restrict__ A, const __half* __restrict__ Bt,
    const float* __restrict__ bias, const float* __restrict__ Res,
    float* __restrict__ C,
    int M, int N, int K, int lda, int ldbk)
{
    extern __shared__ unsigned dsm[];
    unsigned sbase = (unsigned)__cvta_generic_to_shared(dsm);

    int row0 = blockIdx.y * BM, col0 = blockIdx.x * QBN;
    int tid  = threadIdx.x;
    int lane = tid & 31, warp = tid >> 5;
    int wm = (warp & 1) * 64;
    int wn = (warp >> 1) * 32;       // 4 warps over N=128
    int gid = lane >> 2, tg = lane & 3;

    int ar = tid >> 1;
    int ha = (tid & 1) * 16;

    auto load_stage = [&](int s, int k0) {
        unsigned abase = sbase + (s * QSTG) * 4;
        unsigned bbase = sbase + (s * QSTG + AW) * 4;
        const __half* asrc = A + (long)(row0 + ar) * lda + k0 + ha;
        bool av = (row0 + ar) < M;
        unsigned adst = abase + (ar * HST + ha / 2) * 4;
        cpa16(adst, asrc, av);
        cpa16(adst + 16, asrc + 8, av);
        const __half* bsrc = Bt + (long)(col0 + ar) * ldbk + k0 + ha;
        unsigned bdst = bbase + (ar * HST + ha / 2) * 4;
        cpa16u(bdst, bsrc);
        cpa16u(bdst + 16, bsrc + 8);
    };

    unsigned aOff = (unsigned)((wm + (lane & 15)) * (HST * 4) + ((lane >> 4) << 4));
    unsigned bOff = (unsigned)(AW * 4 +
        (wn + (lane & 7) + ((lane >> 4) & 1) * 8) * (HST * 4) + (((lane >> 3) & 1) << 4));

    float acc[4][4][4];
    #pragma unroll
    for (int i = 0; i < 4; i++)
        #pragma unroll
        for (int j = 0; j < 4; j++)
            #pragma unroll
            for (int r = 0; r < 4; r++) acc[i][j][r] = 0.f;

    int ntiles = K / BKH;

    #pragma unroll
    for (int s = 0; s < NSTG - 1; s++) {
        if (s < ntiles) load_stage(s, s * BKH);
        cpa_commit();
    }

    for (int t = 0; t < ntiles; t++) {
        cpa_wait<NSTG - 2>();
        __syncthreads();

        int tn = t + NSTG - 1;
        if (tn < ntiles) load_stage(tn % NSTG, tn * BKH);
        cpa_commit();

        int buf = t % NSTG;
        unsigned stg = sbase + (unsigned)(buf * QSTG * 4);
        unsigned aA = stg + aOff;
        unsigned bA = stg + bOff;

        #pragma unroll
        for (int ks = 0; ks < 2; ks++) {
            unsigned kbyte = ks * 32;
            unsigned a[4][4], b[4][2];
            #pragma unroll
            for (int mi = 0; mi < 4; mi++)
                LDM_X4(a[mi][0], a[mi][1], a[mi][2], a[mi][3],
                       aA + mi * (16 * HST * 4) + kbyte);
            #pragma unroll
            for (int np = 0; np < 2; np++) {
                unsigned b0, b1, b2, b3;
                LDM_X4(b0, b1, b2, b3, bA + np * (16 * HST * 4) + kbyte);
                b[2*np][0] = b0;     b[2*np][1] = b1;
                b[2*np + 1][0] = b2; b[2*np + 1][1] = b3;
            }
            #pragma unroll
            for (int mi = 0; mi < 4; mi++)
                #pragma unroll
                for (int ni = 0; ni < 4; ni++)
                    mma_f16(acc[mi][ni], a[mi][0], a[mi][1], a[mi][2], a[mi][3],
                            b[ni][0], b[ni][1]);
        }
    }

    #pragma unroll
    for (int mi = 0; mi < 4; mi++) {
        #pragma unroll
        for (int rr = 0; rr < 2; rr++) {
            int r = row0 + wm + mi * 16 + gid + rr * 8;
            if (r >= M) continue;
            #pragma unroll
            for (int ni = 0; ni < 4; ni++) {
                int c = col0 + wn + ni * 8 + tg * 2;
                float v0 = acc[mi][ni][rr * 2 + 0];
                float v1 = acc[mi][ni][rr * 2 + 1];
                if (EPI & 1) { v0 += bias[c]; v1 += bias[c + 1]; }
                if (EPI & 4) {
                    v0 = 0.5f * v0 * (1.0f + erff(v0 * 0.70710678118654752f));
                    v1 = 0.5f * v1 * (1.0f + erff(v1 * 0.70710678118654752f));
                }
                if (EPI & 2) {
                    float2 rv = *(const float2*)(Res + (long)r * N + c);
                    v0 += rv.x; v1 += rv.y;
                }
                if (EPI & 8) {
                    *(__half2*)((__half*)C + (long)r * N + c) = __floats2half2_rn(v0, v1);
                } else {
                    *(float2*)(C + (long)r * N + c) = make_float2(v0, v1);
                }
            }
        }
    }
}

// ---------------- host side ----------------
static inline dim3 ggrid(int M, int N) {
    return dim3((unsigned)((N + BN - 1) / BN), (unsigned)((M + BM - 1) / BM), 1);
}
static inline dim3 qgrid(int M, int N) {
    return dim3((unsigned)((N + QBN - 1) / QBN), (unsigned)((M + BM - 1) / BM), 1);
}

extern "C" void kernel_launch(void* const* d_in, const int* in_sizes, int n_in,
                              void* d_out, int out_size)
{
    const float* x        = (const float*)d_in[0];
    const float* cond     = (const float*)d_in[1];
    const float* Wqkv     = (const float*)d_in[2];
    const float* Wproj_sa = (const float*)d_in[3];
    const float* bproj_sa = (const float*)d_in[4];
    const float* g1       = (const float*)d_in[5];
    const float* b1       = (const float*)d_in[6];
    const float* Wq_ca    = (const float*)d_in[7];
    const float* Wkv_ca   = (const float*)d_in[8];
    const float* Wproj_ca = (const float*)d_in[9];
    const float* bproj_ca = (const float*)d_in[10];
    const float* g2       = (const float*)d_in[11];
    const float* b2       = (const float*)d_in[12];
    const float* Wff1     = (const float*)d_in[13];
    const float* bff1     = (const float*)d_in[14];
    const float* Wff2     = (const float*)d_in[15];
    const float* bff2     = (const float*)d_in[16];
    const float* g3       = (const float*)d_in[17];
    const float* b3       = (const float*)d_in[18];
    float* out            = (float*)d_out;

    __half *p_ln, *p_qkv, *p_attn, *p_qca, *p_kvca, *p_ff, *p_w;
    float *p_x1, *p_x2;
    cudaGetSymbolAddress((void**)&p_ln,   g_lnH);
    cudaGetSymbolAddress((void**)&p_qkv,  g_qkvH);
    cudaGetSymbolAddress((void**)&p_attn, g_attnH);
    cudaGetSymbolAddress((void**)&p_qca,  g_qcaH);
    cudaGetSymbolAddress((void**)&p_kvca, g_kvcaH);
    cudaGetSymbolAddress((void**)&p_ff,   g_ffH);
    cudaGetSymbolAddress((void**)&p_x1,   g_x1);
    cudaGetSymbolAddress((void**)&p_x2,   g_x2);
    cudaGetSymbolAddress((void**)&p_w,    g_wh);

    static int smem_set = 0;
    if (!smem_set) {
        cudaFuncSetAttribute(flash_kernel, cudaFuncAttributeMaxDynamicSharedMemorySize, FSMEM);
        cudaFuncSetAttribute(hgemm<8>,   cudaFuncAttributeMaxDynamicSharedMemorySize, GSMEM);
        cudaFuncSetAttribute(hgemm<13>,  cudaFuncAttributeMaxDynamicSharedMemorySize, GSMEM);
        cudaFuncSetAttribute(hgemm2<3>,  cudaFuncAttributeMaxDynamicSharedMemorySize, QSMEM);
        cudaFuncSetAttribute(hgemm2<8>,  cudaFuncAttributeMaxDynamicSharedMemorySize, QSMEM);
        smem_set = 1;
    }

    const long T3D = (long)Tt * 3 * Dm;
    const long TD  = (long)Tt * Dm;
    const long KVb = (long)Cc * 2 * Dm;

    // 0) merged prep
    prep_all<<<TCOND, 256>>>(Wqkv, Wproj_sa, Wq_ca, Wkv_ca,
                             Wproj_ca, Wff1, Wff2, cond, p_w);

    // 1) ln1 = LN(x) -> half
    ln_kernel<<<MX, 256>>>(x, g1, b1, p_ln);

    // 2) qkv = ln1 @ Wqkv  (wide-N)
    hgemm<8><<<ggrid(MX, 3*Dm), 256, GSMEM>>>(
        p_ln, p_w + OW_QKV, nullptr, nullptr, (float*)p_qkv, MX, 3*Dm, Dm, Dm, Dm);

    // 3) fused causal self-attention
    flash_kernel<<<dim3(1, Tt/FBQ, Bb*Hh), 256, FSMEM>>>(
        p_qkv, p_qkv + Dm, p_qkv + 2*Dm, p_attn,
        Tt, Tt, 3*Dm, 3*Dm, Dm,
        T3D, DH, T3D, DH, TD, DH, Hh, 1);

    // 4) x1 = x + attn @ Wproj_sa + b  (narrow-N, 2 CTA/SM)
    hgemm2<3><<<qgrid(MX, Dm), 256, QSMEM>>>(
        p_attn, p_w + OW_PSA, bproj_sa, x, p_x1, MX, Dm, Dm, Dm, Dm);

    // 5) ln2 = LN(x1)
    ln_kernel<<<MX, 256>>>(p_x1, g2, b2, p_ln);

    // 6) q_ca = ln2 @ Wq_ca  (narrow-N)
    hgemm2<8><<<qgrid(MX, Dm), 256, QSMEM>>>(
        p_ln, p_w + OW_QCA, nullptr, nullptr, (float*)p_qca, MX, Dm, Dm, Dm, Dm);

    // 7) kv_ca = cond_h @ Wkv_ca  (narrow-N)
    hgemm2<8><<<qgrid(Bb*Cc, 2*Dm), 256, QSMEM>>>(
        p_w + OW_COND, p_w + OW_KVCA, nullptr, nullptr, (float*)p_kvca,
        Bb*Cc, 2*Dm, DC, DC, DC);

    // 8) fused cross-attention
    flash_kernel<<<dim3(1, Tt/FBQ, Bb*Hh), 256, FSMEM>>>(
        p_qca, p_kvca, p_kvca + Dm, p_attn,
        Tt, Cc, Dm, 2*Dm, Dm,
        TD, DH, KVb, DH, TD, DH, Hh, 0);

    // 9) x2 = x1 + ca_out @ Wproj_ca + b  (narrow-N)
    hgemm2<3><<<qgrid(MX, Dm), 256, QSMEM>>>(
        p_attn, p_w + OW_PCA, bproj_ca, p_x1, p_x2, MX, Dm, Dm, Dm, Dm);

    // 10) ln3 = LN(x2)
    ln_kernel<<<MX, 256>>>(p_x2, g3, b3, p_ln);

    // 11) ffh = gelu(ln3 @ Wff1 + bff1)  (wide-N)
    hgemm<13><<<ggrid(MX, DFF), 256, GSMEM>>>(
        p_ln, p_w + OW_FF1, bff1, nullptr, (float*)p_ff, MX, DFF, Dm, Dm, Dm);

    // 12) out = x2 + ffh @ Wff2 + bff2  (narrow-N, K=4096)
    hgemm2<3><<<qgrid(MX, Dm), 256, QSMEM>>>(
        p_ff, p_w + OW_FF2, bff2, p_x2, out, MX, Dm, DFF, DFF, DFF);
}

// round 16
// speedup vs baseline: 2.0637x; 1.0812x over previous
#include <cuda_runtime.h>
#include <cuda_fp16.h>
#include <math.h>

// ---------------- problem constants ----------------
#define Dm   1024
#define Hh   16
#define DH   64
#define DFF  4096
#define DC   768
#define Tt   2048
#define Bb   2
#define Cc   77
#define MX   4096          // Bb*Tt rows of x

// ---------------- scratch (static device arrays; no allocs) ----------------
__device__ __half g_lnH  [(size_t)MX * Dm];
__device__ __half g_qkvH [(size_t)MX * 3 * Dm];
__device__ __half g_attnH[(size_t)MX * Dm];
__device__ __half g_qcaH [(size_t)MX * Dm];
__device__ __half g_kvcaH[(size_t)Bb * Cc * 2 * Dm];
__device__ __half g_ffH  [(size_t)MX * DFF];
__device__ float  g_x1   [(size_t)MX * Dm];
__device__ float  g_x2   [(size_t)MX * Dm];
__device__ __half g_wh   [(size_t)16400000];   // transposed half weights + cond

// weight-scratch offsets (elements)
#define SZ_QKV  (Dm*3*Dm)
#define SZ_PSA  (Dm*Dm)
#define SZ_QCA  (Dm*Dm)
#define SZ_KVCA (DC*2*Dm)
#define SZ_PCA  (Dm*Dm)
#define SZ_FF1  (Dm*DFF)
#define SZ_FF2  (DFF*Dm)
#define SZ_COND (Bb*Cc*DC)
#define OW_QKV   0
#define OW_PSA   (OW_QKV + SZ_QKV)
#define OW_QCA   (OW_PSA + SZ_PSA)
#define OW_KVCA  (OW_QCA + SZ_QCA)
#define OW_PCA   (OW_KVCA + SZ_KVCA)
#define OW_FF1   (OW_PCA + SZ_PCA)
#define OW_FF2   (OW_FF1 + SZ_FF1)
#define OW_COND  (OW_FF2 + SZ_FF2)

// prep tile ranges (32x32 transpose tiles per matrix)
#define TQKV  3072
#define TPSA  (TQKV + 1024)
#define TQCA  (TPSA + 1024)
#define TKVCA (TQCA + 1536)
#define TPCA  (TKVCA + 1024)
#define TFF1  (TPCA + 4096)
#define TFF2  (TFF1 + 4096)
#define TCOND (TFF2 + (SZ_COND / 256))

// ---------------- helpers ----------------
__device__ __forceinline__ unsigned hpack(float a, float b) {
    __half2 h = __floats2half2_rn(a, b);
    return *(unsigned*)&h;
}

__device__ __forceinline__ void mma_f16(float c[4],
    unsigned a0, unsigned a1, unsigned a2, unsigned a3,
    unsigned b0, unsigned b1)
{
    asm volatile(
        "mma.sync.aligned.m16n8k16.row.col.f32.f16.f16.f32 "
        "{%0,%1,%2,%3}, {%4,%5,%6,%7}, {%8,%9}, {%0,%1,%2,%3};\n"
        : "+f"(c[0]), "+f"(c[1]), "+f"(c[2]), "+f"(c[3])
        : "r"(a0), "r"(a1), "r"(a2), "r"(a3), "r"(b0), "r"(b1));
}

#define LDM_X4(r0,r1,r2,r3,addr) \
    asm volatile("ldmatrix.sync.aligned.m8n8.x4.shared.b16 {%0,%1,%2,%3}, [%4];" \
        : "=r"(r0),"=r"(r1),"=r"(r2),"=r"(r3) : "r"(addr))
#define LDM_X4T(r0,r1,r2,r3,addr) \
    asm volatile("ldmatrix.sync.aligned.m8n8.x4.trans.shared.b16 {%0,%1,%2,%3}, [%4];" \
        : "=r"(r0),"=r"(r1),"=r"(r2),"=r"(r3) : "r"(addr))

__device__ __forceinline__ void cpa16(unsigned dst, const void* src, bool pred) {
    int sz = pred ? 16 : 0;
    asm volatile("cp.async.cg.shared.global [%0], [%1], 16, %2;\n"
                 :: "r"(dst), "l"(src), "r"(sz));
}
__device__ __forceinline__ void cpa16u(unsigned dst, const void* src) {
    asm volatile("cp.async.cg.shared.global [%0], [%1], 16;\n"
                 :: "r"(dst), "l"(src));
}
__device__ __forceinline__ void cpa_commit() {
    asm volatile("cp.async.commit_group;\n");
}
template<int N>
__device__ __forceinline__ void cpa_wait() {
    asm volatile("cp.async.wait_group %0;\n" :: "n"(N));
}

// ---------------- merged prep: all weight transposes + cond convert ----------------
__global__ __launch_bounds__(256) void prep_all(
    const float* __restrict__ wqkv, const float* __restrict__ wpsa,
    const float* __restrict__ wqca, const float* __restrict__ wkvca,
    const float* __restrict__ wpca, const float* __restrict__ wff1,
    const float* __restrict__ wff2, const float* __restrict__ cond,
    __half* __restrict__ dst)
{
    int b = blockIdx.x;
    int tid = threadIdx.x;

    if (b >= TFF2) {
        int base = (b - TFF2) * 256 + tid;
        if (base < SZ_COND) dst[OW_COND + base] = __float2half(cond[base]);
        return;
    }

    const float* src; __half* d; int K, N; int tile;
    if      (b < TQKV)  { src = wqkv;  d = dst + OW_QKV;  K = Dm;  N = 3*Dm; tile = b; }
    else if (b < TPSA)  { src = wpsa;  d = dst + OW_PSA;  K = Dm;  N = Dm;   tile = b - TQKV; }
    else if (b < TQCA)  { src = wqca;  d = dst + OW_QCA;  K = Dm;  N = Dm;   tile = b - TPSA; }
    else if (b < TKVCA) { src = wkvca; d = dst + OW_KVCA; K = DC;  N = 2*Dm; tile = b - TQCA; }
    else if (b < TPCA)  { src = wpca;  d = dst + OW_PCA;  K = Dm;  N = Dm;   tile = b - TKVCA; }
    else if (b < TFF1)  { src = wff1;  d = dst + OW_FF1;  K = Dm;  N = DFF;  tile = b - TPCA; }
    else                { src = wff2;  d = dst + OW_FF2;  K = DFF; N = Dm;   tile = b - TFF1; }

    int tX = N >> 5;
    int bx = (tile % tX) * 32, by = (tile / tX) * 32;
    __shared__ float t[32][33];
    int tx = tid & 31, ty = tid >> 5;
    #pragma unroll
    for (int j = 0; j < 32; j += 8)
        t[ty + j][tx] = src[(long)(by + ty + j) * N + bx + tx];
    __syncthreads();
    #pragma unroll
    for (int j = 0; j < 32; j += 8)
        d[(long)(bx + ty + j) * K + by + tx] = __float2half(t[tx][ty + j]);
}

// ---------------- reductions ----------------
__device__ __forceinline__ float block_sum(float v, float* sh) {
    #pragma unroll
    for (int o = 16; o > 0; o >>= 1) v += __shfl_xor_sync(0xffffffffu, v, o);
    int w = threadIdx.x >> 5;
    if ((threadIdx.x & 31) == 0) sh[w] = v;
    __syncthreads();
    if (threadIdx.x < 32) {
        float t = (threadIdx.x < 8) ? sh[threadIdx.x] : 0.f;
        #pragma unroll
        for (int o = 4; o > 0; o >>= 1) t += __shfl_xor_sync(0xffffffffu, t, o);
        if (threadIdx.x == 0) sh[0] = t;
    }
    __syncthreads();
    float r = sh[0];
    __syncthreads();
    return r;
}

// ---------------- LayerNorm (half output) ----------------
__global__ __launch_bounds__(256) void ln_kernel(
    const float* __restrict__ x, const float* __restrict__ g,
    const float* __restrict__ b, __half* __restrict__ out)
{
    __shared__ float sh[8];
    long row = blockIdx.x;
    const float4* xr = (const float4*)(x + row * Dm);
    int tid = threadIdx.x;
    float4 v = xr[tid];
    float s = v.x + v.y + v.z + v.w;
    s = block_sum(s, sh);
    float mean = s * (1.0f / Dm);
    float dx = v.x - mean, dy = v.y - mean, dz = v.z - mean, dw = v.w - mean;
    float s2 = dx*dx + dy*dy + dz*dz + dw*dw;
    s2 = block_sum(s2, sh);
    float rstd = rsqrtf(s2 * (1.0f / Dm) + 1e-5f);
    float4 gg = ((const float4*)g)[tid];
    float4 bbv = ((const float4*)b)[tid];
    uint2 u;
    u.x = hpack(dx * rstd * gg.x + bbv.x, dy * rstd * gg.y + bbv.y);
    u.y = hpack(dz * rstd * gg.z + bbv.z, dw * rstd * gg.w + bbv.w);
    ((uint2*)(out + row * Dm))[tid] = u;
}

// ================= fused flash attention (fp16, 128-row KV macro-tiles) =============
#define FBQ 128
#define FBK2 128
#define FST 36
#define FSMEM ((FBQ + FBK2 + FBK2) * FST * 4)     // 55296 B

__global__ __launch_bounds__(256, 2) void flash_kernel(
    const __half* __restrict__ Qp, const __half* __restrict__ Kp,
    const __half* __restrict__ Vp, __half* __restrict__ Op,
    int Tq, int Tk, int ldq, int ldk, int ldo,
    long sQb, long sQh, long sKb, long sKh, long sOb, long sOh,
    int Hn, int causal)
{
    extern __shared__ unsigned fsm[];
    unsigned* Qs = fsm;
    unsigned* Ks = fsm + FBQ * FST;
    unsigned* Vs = Ks + FBK2 * FST;
    unsigned sbase = (unsigned)__cvta_generic_to_shared(fsm);

    int z = blockIdx.z, zb = z / Hn, zh = z - zb * Hn;
    Qp += zb * sQb + zh * sQh;
    Kp += zb * sKb + zh * sKh;
    Vp += zb * sKb + zh * sKh;
    Op += zb * sOb + zh * sOh;

    int tid = threadIdx.x, lane = tid & 31, warp = tid >> 5;
    int gid = lane >> 2, tg = lane & 3;
    int sel = lane & 7, grp = lane >> 3;
    int yb = causal ? ((int)gridDim.y - 1 - (int)blockIdx.y) : (int)blockIdx.y;
    int row0 = yb * FBQ;
    int wrmax = row0 + warp * 16 + 15;

    const __half2 scale2 = __half2half2(__float2half(0.125f));

    #pragma unroll
    for (int it = 0; it < 4; it++) {
        int idx = it * 256 + tid;
        int r = idx >> 3, c8 = (idx & 7) * 8;
        int gr = row0 + r;
        uint4 v = make_uint4(0u, 0u, 0u, 0u);
        if (gr < Tq) v = *(const uint4*)(Qp + (long)gr * ldq + c8);
        __half2* h = (__half2*)&v;
        h[0] = __hmul2(h[0], scale2); h[1] = __hmul2(h[1], scale2);
        h[2] = __hmul2(h[2], scale2); h[3] = __hmul2(h[3], scale2);
        *(uint4*)&Qs[r * FST + c8 / 2] = v;
    }

    unsigned qAddr = sbase + (unsigned)((warp * 16 + sel + ((grp & 1) << 3)) * 144
                                        + ((grp >> 1) << 4));
    unsigned kBase = sbase + FBQ * 144;
    unsigned vBase = kBase + FBK2 * 144;
    unsigned kRow = (unsigned)((sel + ((grp >> 1) << 3)) * 144 + ((grp & 1) << 4));
    unsigned vRow = (unsigned)((sel + ((grp & 1) << 3)) * 144 + ((grp >> 1) << 4));

    int r_0 = row0 + warp * 16 + gid;
    int r_1 = r_0 + 8;

    float m0 = -1e30f, m1 = -1e30f, l0 = 0.f, l1 = 0.f;
    float o[8][4];
    #pragma unroll
    for (int i = 0; i < 8; i++)
        #pragma unroll
        for (int j = 0; j < 4; j++) o[i][j] = 0.f;

    int ntile = causal ? (row0 + FBQ + FBK2 - 1) / FBK2 : (Tk + FBK2 - 1) / FBK2;

    for (int t = 0; t < ntile; t++) {
        int tb = t * FBK2;
        __syncthreads();
        #pragma unroll
        for (int it = 0; it < 4; it++) {
            int idx = it * 256 + tid;
            int r = idx >> 3, c8 = (idx & 7) * 8;
            int gr = tb + r;
            uint4 kv = make_uint4(0u,0u,0u,0u), vv = make_uint4(0u,0u,0u,0u);
            if (gr < Tk) {
                kv = *(const uint4*)(Kp + (long)gr * ldk + c8);
                vv = *(const uint4*)(Vp + (long)gr * ldk + c8);
            }
            *(uint4*)&Ks[r * FST + c8 / 2] = kv;
            *(uint4*)&Vs[r * FST + c8 / 2] = vv;
        }
        __syncthreads();

        #pragma unroll
        for (int sub = 0; sub < 2; sub++) {
            int kvb = tb + sub * 64;
            if (causal && kvb > wrmax) continue;
            if (!causal && kvb >= Tk) continue;
            unsigned kSub = kBase + (unsigned)(sub * 64 * 144);
            unsigned vSub = vBase + (unsigned)(sub * 64 * 144);

            float sacc[8][4];
            #pragma unroll
            for (int i = 0; i < 8; i++)
                #pragma unroll
                for (int j = 0; j < 4; j++) sacc[i][j] = 0.f;

            #pragma unroll
            for (int ks = 0; ks < 4; ks++) {
                unsigned qa0, qa1, qa2, qa3;
                LDM_X4(qa0, qa1, qa2, qa3, qAddr + ks * 32);
                #pragma unroll
                for (int np = 0; np < 4; np++) {
                    unsigned b0, b1, b2, b3;
                    LDM_X4(b0, b1, b2, b3, kSub + np * (16 * 144) + kRow + ks * 32);
                    mma_f16(sacc[2*np],     qa0, qa1, qa2, qa3, b0, b1);
                    mma_f16(sacc[2*np + 1], qa0, qa1, qa2, qa3, b2, b3);
                }
            }

            bool domask = (causal && (kvb + 63 > row0)) || (kvb + 64 > Tk);
            if (domask) {
                #pragma unroll
                for (int ni = 0; ni < 8; ni++) {
                    #pragma unroll
                    for (int s = 0; s < 4; s++) {
                        int col = kvb + ni * 8 + tg * 2 + (s & 1);
                        int r = (s < 2) ? r_0 : r_1;
                        bool ok = (col < Tk) && (!causal || col <= r);
                        if (!ok) sacc[ni][s] = -1e30f;
                    }
                }
            }

            float tm0 = -1e30f, tm1 = -1e30f;
            #pragma unroll
            for (int ni = 0; ni < 8; ni++) {
                tm0 = fmaxf(tm0, fmaxf(sacc[ni][0], sacc[ni][1]));
                tm1 = fmaxf(tm1, fmaxf(sacc[ni][2], sacc[ni][3]));
            }
            tm0 = fmaxf(tm0, __shfl_xor_sync(0xffffffffu, tm0, 1));
            tm0 = fmaxf(tm0, __shfl_xor_sync(0xffffffffu, tm0, 2));
            tm1 = fmaxf(tm1, __shfl_xor_sync(0xffffffffu, tm1, 1));
            tm1 = fmaxf(tm1, __shfl_xor_sync(0xffffffffu, tm1, 2));

            float nm0 = fmaxf(m0, tm0), nm1 = fmaxf(m1, tm1);
            float sc0 = __expf(m0 - nm0), sc1 = __expf(m1 - nm1);
            m0 = nm0; m1 = nm1;

            float rs0 = 0.f, rs1 = 0.f;
            #pragma unroll
            for (int ni = 0; ni < 8; ni++) {
                sacc[ni][0] = __expf(sacc[ni][0] - nm0); rs0 += sacc[ni][0];
                sacc[ni][1] = __expf(sacc[ni][1] - nm0); rs0 += sacc[ni][1];
                sacc[ni][2] = __expf(sacc[ni][2] - nm1); rs1 += sacc[ni][2];
                sacc[ni][3] = __expf(sacc[ni][3] - nm1); rs1 += sacc[ni][3];
            }
            rs0 += __shfl_xor_sync(0xffffffffu, rs0, 1);
            rs0 += __shfl_xor_sync(0xffffffffu, rs0, 2);
            rs1 += __shfl_xor_sync(0xffffffffu, rs1, 1);
            rs1 += __shfl_xor_sync(0xffffffffu, rs1, 2);
            l0 = l0 * sc0 + rs0;
            l1 = l1 * sc1 + rs1;

            #pragma unroll
            for (int ni = 0; ni < 8; ni++) {
                o[ni][0] *= sc0; o[ni][1] *= sc0;
                o[ni][2] *= sc1; o[ni][3] *= sc1;
            }

            #pragma unroll
            for (int ks = 0; ks < 4; ks++) {
                unsigned a0 = hpack(sacc[2*ks][0],     sacc[2*ks][1]);
                unsigned a1 = hpack(sacc[2*ks][2],     sacc[2*ks][3]);
                unsigned a2 = hpack(sacc[2*ks + 1][0], sacc[2*ks + 1][1]);
                unsigned a3 = hpack(sacc[2*ks + 1][2], sacc[2*ks + 1][3]);
                #pragma unroll
                for (int np = 0; np < 4; np++) {
                    unsigned b0, b1, b2, b3;
                    LDM_X4T(b0, b1, b2, b3, vSub + ks * (16 * 144) + vRow + np * 32);
                    mma_f16(o[2*np],     a0, a1, a2, a3, b0, b1);
                    mma_f16(o[2*np + 1], a0, a1, a2, a3, b2, b3);
                }
            }
        }
    }

    float inv0 = 1.0f / l0, inv1 = 1.0f / l1;
    #pragma unroll
    for (int nj = 0; nj < 8; nj++) {
        int c = nj * 8 + tg * 2;
        if (r_0 < Tq) {
            __half2 w = __floats2half2_rn(o[nj][0] * inv0, o[nj][1] * inv0);
            *(__half2*)(Op + (long)r_0 * ldo + c) = w;
        }
        if (r_1 < Tq) {
            __half2 w = __floats2half2_rn(o[nj][2] * inv1, o[nj][3] * inv1);
            *(__half2*)(Op + (long)r_1 * ldo + c) = w;
        }
    }
}

// ======== fp16 GEMM, 128x128 block, 64x32 warp tile, 2 CTAs/SM (all shapes) ========
#define BM 128
#define QBN 128
#define BKH 32
#define NSTG 4
#define HST 20
#define AW (BM * HST)                // 2560 words
#define QBW (QBN * HST)              // 2560 words
#define QSTG (AW + QBW)              // 5120 words
#define QSMEM (QSTG * NSTG * 4)      // 81920 B

template<int EPI>
__global__ __launch_bounds__(256, 2) void hgemm2(
    const __half* __restrict__ A, const __half* __restrict__ Bt,
    const float* __restrict__ bias, const float* __restrict__ Res,
    float* __restrict__ C,
    int M, int N, int K, int lda, int ldbk)
{
    extern __shared__ unsigned dsm[];
    unsigned sbase = (unsigned)__cvta_generic_to_shared(dsm);

    int row0 = blockIdx.y * BM, col0 = blockIdx.x * QBN;
    int tid  = threadIdx.x;
    int lane = tid & 31, warp = tid >> 5;
    int wm = (warp & 1) * 64;
    int wn = (warp >> 1) * 32;
    int gid = lane >> 2, tg = lane & 3;

    int ar = tid >> 1;
    int ha = (tid & 1) * 16;

    auto load_stage = [&](int s, int k0) {
        unsigned abase = sbase + (s * QSTG) * 4;
        unsigned bbase = sbase + (s * QSTG + AW) * 4;
        const __half* asrc = A + (long)(row0 + ar) * lda + k0 + ha;
        bool av = (row0 + ar) < M;
        unsigned adst = abase + (ar * HST + ha / 2) * 4;
        cpa16(adst, asrc, av);
        cpa16(adst + 16, asrc + 8, av);
        const __half* bsrc = Bt + (long)(col0 + ar) * ldbk + k0 + ha;
        unsigned bdst = bbase + (ar * HST + ha / 2) * 4;
        cpa16u(bdst, bsrc);
        cpa16u(bdst + 16, bsrc + 8);
    };

    unsigned aOff = (unsigned)((wm + (lane & 15)) * (HST * 4) + ((lane >> 4) << 4));
    unsigned bOff = (unsigned)(AW * 4 +
        (wn + (lane & 7) + ((lane >> 4) & 1) * 8) * (HST * 4) + (((lane >> 3) & 1) << 4));

    float acc[4][4][4];
    #pragma unroll
    for (int i = 0; i < 4; i++)
        #pragma unroll
        for (int j = 0; j < 4; j++)
            #pragma unroll
            for (int r = 0; r < 4; r++) acc[i][j][r] = 0.f;

    int ntiles = K / BKH;

    #pragma unroll
    for (int s = 0; s < NSTG - 1; s++) {
        if (s < ntiles) load_stage(s, s * BKH);
        cpa_commit();
    }

    for (int t = 0; t < ntiles; t++) {
        cpa_wait<NSTG - 2>();
        __syncthreads();

        int tn = t + NSTG - 1;
        if (tn < ntiles) load_stage(tn % NSTG, tn * BKH);
        cpa_commit();

        int buf = t % NSTG;
        unsigned stg = sbase + (unsigned)(buf * QSTG * 4);
        unsigned aA = stg + aOff;
        unsigned bA = stg + bOff;

        #pragma unroll
        for (int ks = 0; ks < 2; ks++) {
            unsigned kbyte = ks * 32;
            unsigned a[4][4], b[4][2];
            #pragma unroll
            for (int mi = 0; mi < 4; mi++)
                LDM_X4(a[mi][0], a[mi][1], a[mi][2], a[mi][3],
                       aA + mi * (16 * HST * 4) + kbyte);
            #pragma unroll
            for (int np = 0; np < 2; np++) {
                unsigned b0, b1, b2, b3;
                LDM_X4(b0, b1, b2, b3, bA + np * (16 * HST * 4) + kbyte);
                b[2*np][0] = b0;     b[2*np][1] = b1;
                b[2*np + 1][0] = b2; b[2*np + 1][1] = b3;
            }
            #pragma unroll
            for (int mi = 0; mi < 4; mi++)
                #pragma unroll
                for (int ni = 0; ni < 4; ni++)
                    mma_f16(acc[mi][ni], a[mi][0], a[mi][1], a[mi][2], a[mi][3],
                            b[ni][0], b[ni][1]);
        }
    }

    #pragma unroll
    for (int mi = 0; mi < 4; mi++) {
        #pragma unroll
        for (int rr = 0; rr < 2; rr++) {
            int r = row0 + wm + mi * 16 + gid + rr * 8;
            if (r >= M) continue;
            #pragma unroll
            for (int ni = 0; ni < 4; ni++) {
                int c = col0 + wn + ni * 8 + tg * 2;
                float v0 = acc[mi][ni][rr * 2 + 0];
                float v1 = acc[mi][ni][rr * 2 + 1];
                if (EPI & 1) { v0 += bias[c]; v1 += bias[c + 1]; }
                if (EPI & 4) {
                    v0 = 0.5f * v0 * (1.0f + erff(v0 * 0.70710678118654752f));
                    v1 = 0.5f * v1 * (1.0f + erff(v1 * 0.70710678118654752f));
                }
                if (EPI & 2) {
                    float2 rv = *(const float2*)(Res + (long)r * N + c);
                    v0 += rv.x; v1 += rv.y;
                }
                if (EPI & 8) {
                    *(__half2*)((__half*)C + (long)r * N + c) = __floats2half2_rn(v0, v1);
                } else {
                    *(float2*)(C + (long)r * N + c) = make_float2(v0, v1);
                }
            }
        }
    }
}

// ---------------- host side ----------------
static inline dim3 qgrid(int M, int N) {
    return dim3((unsigned)((N + QBN - 1) / QBN), (unsigned)((M + BM - 1) / BM), 1);
}

extern "C" void kernel_launch(void* const* d_in, const int* in_sizes, int n_in,
                              void* d_out, int out_size)
{
    const float* x        = (const float*)d_in[0];
    const float* cond     = (const float*)d_in[1];
    const float* Wqkv     = (const float*)d_in[2];
    const float* Wproj_sa = (const float*)d_in[3];
    const float* bproj_sa = (const float*)d_in[4];
    const float* g1       = (const float*)d_in[5];
    const float* b1       = (const float*)d_in[6];
    const float* Wq_ca    = (const float*)d_in[7];
    const float* Wkv_ca   = (const float*)d_in[8];
    const float* Wproj_ca = (const float*)d_in[9];
    const float* bproj_ca = (const float*)d_in[10];
    const float* g2       = (const float*)d_in[11];
    const float* b2       = (const float*)d_in[12];
    const float* Wff1     = (const float*)d_in[13];
    const float* bff1     = (const float*)d_in[14];
    const float* Wff2     = (const float*)d_in[15];
    const float* bff2     = (const float*)d_in[16];
    const float* g3       = (const float*)d_in[17];
    const float* b3       = (const float*)d_in[18];
    float* out            = (float*)d_out;

    __half *p_ln, *p_qkv, *p_attn, *p_qca, *p_kvca, *p_ff, *p_w;
    float *p_x1, *p_x2;
    cudaGetSymbolAddress((void**)&p_ln,   g_lnH);
    cudaGetSymbolAddress((void**)&p_qkv,  g_qkvH);
    cudaGetSymbolAddress((void**)&p_attn, g_attnH);
    cudaGetSymbolAddress((void**)&p_qca,  g_qcaH);
    cudaGetSymbolAddress((void**)&p_kvca, g_kvcaH);
    cudaGetSymbolAddress((void**)&p_ff,   g_ffH);
    cudaGetSymbolAddress((void**)&p_x1,   g_x1);
    cudaGetSymbolAddress((void**)&p_x2,   g_x2);
    cudaGetSymbolAddress((void**)&p_w,    g_wh);

    static int smem_set = 0;
    if (!smem_set) {
        cudaFuncSetAttribute(flash_kernel, cudaFuncAttributeMaxDynamicSharedMemorySize, FSMEM);
        cudaFuncSetAttribute(hgemm2<3>,  cudaFuncAttributeMaxDynamicSharedMemorySize, QSMEM);
        cudaFuncSetAttribute(hgemm2<8>,  cudaFuncAttributeMaxDynamicSharedMemorySize, QSMEM);
        cudaFuncSetAttribute(hgemm2<13>, cudaFuncAttributeMaxDynamicSharedMemorySize, QSMEM);
        smem_set = 1;
    }

    const long T3D = (long)Tt * 3 * Dm;
    const long TD  = (long)Tt * Dm;
    const long KVb = (long)Cc * 2 * Dm;

    // 0) merged prep
    prep_all<<<TCOND, 256>>>(Wqkv, Wproj_sa, Wq_ca, Wkv_ca,
                             Wproj_ca, Wff1, Wff2, cond, p_w);

    // 1) ln1 = LN(x) -> half
    ln_kernel<<<MX, 256>>>(x, g1, b1, p_ln);

    // 2) qkv = ln1 @ Wqkv
    hgemm2<8><<<qgrid(MX, 3*Dm), 256, QSMEM>>>(
        p_ln, p_w + OW_QKV, nullptr, nullptr, (float*)p_qkv, MX, 3*Dm, Dm, Dm, Dm);

    // 3) fused causal self-attention
    flash_kernel<<<dim3(1, Tt/FBQ, Bb*Hh), 256, FSMEM>>>(
        p_qkv, p_qkv + Dm, p_qkv + 2*Dm, p_attn,
        Tt, Tt, 3*Dm, 3*Dm, Dm,
        T3D, DH, T3D, DH, TD, DH, Hh, 1);

    // 4) x1 = x + attn @ Wproj_sa + b
    hgemm2<3><<<qgrid(MX, Dm), 256, QSMEM>>>(
        p_attn, p_w + OW_PSA, bproj_sa, x, p_x1, MX, Dm, Dm, Dm, Dm);

    // 5) ln2 = LN(x1)
    ln_kernel<<<MX, 256>>>(p_x1, g2, b2, p_ln);

    // 6) q_ca = ln2 @ Wq_ca
    hgemm2<8><<<qgrid(MX, Dm), 256, QSMEM>>>(
        p_ln, p_w + OW_QCA, nullptr, nullptr, (float*)p_qca, MX, Dm, Dm, Dm, Dm);

    // 7) kv_ca = cond_h @ Wkv_ca
    hgemm2<8><<<qgrid(Bb*Cc, 2*Dm), 256, QSMEM>>>(
        p_w + OW_COND, p_w + OW_KVCA, nullptr, nullptr, (float*)p_kvca,
        Bb*Cc, 2*Dm, DC, DC, DC);

    // 8) fused cross-attention
    flash_kernel<<<dim3(1, Tt/FBQ, Bb*Hh), 256, FSMEM>>>(
        p_qca, p_kvca, p_kvca + Dm, p_attn,
        Tt, Cc, Dm, 2*Dm, Dm,
        TD, DH, KVb, DH, TD, DH, Hh, 0);

    // 9) x2 = x1 + ca_out @ Wproj_ca + b
    hgemm2<3><<<qgrid(MX, Dm), 256, QSMEM>>>(
        p_attn, p_w + OW_PCA, bproj_ca, p_x1, p_x2, MX, Dm, Dm, Dm, Dm);

    // 10) ln3 = LN(x2)
    ln_kernel<<<MX, 256>>>(p_x2, g3, b3, p_ln);

    // 11) ffh = gelu(ln3 @ Wff1 + bff1)
    hgemm2<13><<<qgrid(MX, DFF), 256, QSMEM>>>(
        p_ln, p_w + OW_FF1, bff1, nullptr, (float*)p_ff, MX, DFF, Dm, Dm, Dm);

    // 12) out = x2 + ffh @ Wff2 + bff2
    hgemm2<3><<<qgrid(MX, Dm), 256, QSMEM>>>(
        p_ff, p_w + OW_FF2, bff2, p_x2, out, MX, Dm, DFF, DFF, DFF);
}